// round 2
// baseline (speedup 1.0000x reference)
#include <cuda_runtime.h>
#include <cstdint>
#include <cstddef>

#define NLOC   4096
#define NALL   6144
#define NDIM   128
#define EDIM   64
#define ADIM   32
#define NEDGE  262144
#define NANGLE 409600
#define INV_DYN_E 0.15625f            // 1/6.4 (exact)
#define SYM_SCALE 0.0520833333333f    // (1/6.4)/3

// ---------------- device scratch ----------------
__device__ float g_sym[(size_t)NLOC * 768];
__device__ float g_base[(size_t)NLOC * 192];
__device__ float g_reduced[(size_t)NEDGE * EDIM];
__device__ int   g_ecnt[NLOC];
__device__ int   g_eoff[NLOC + 1];
__device__ int   g_ecur[NLOC];
__device__ int   g_eids[NEDGE];

// ---------------- helpers ----------------
__device__ __forceinline__ float silu_f(float x) { return x / (1.0f + __expf(-x)); }

__device__ __forceinline__ unsigned long long pack2(float w) {
    unsigned long long r;
    unsigned int u = __float_as_uint(w);
    asm("mov.b64 %0, {%1,%1};" : "=l"(r) : "r"(u));
    return r;
}
__device__ __forceinline__ void ffma2(unsigned long long& d, unsigned long long a,
                                      unsigned long long b) {
    asm("fma.rn.f32x2 %0, %1, %2, %0;" : "+l"(d) : "l"(a), "l"(b));
}
__device__ __forceinline__ void unpack2(unsigned long long v, float& lo, float& hi) {
    unsigned int l, h;
    asm("mov.b64 {%0,%1}, %2;" : "=r"(l), "=r"(h) : "l"(v));
    lo = __uint_as_float(l);
    hi = __uint_as_float(h);
}

// ---------------- zero scratch ----------------
__global__ void k_zero() {
    size_t i0 = (size_t)blockIdx.x * blockDim.x + threadIdx.x;
    size_t stride = (size_t)gridDim.x * blockDim.x;
    float4* r = reinterpret_cast<float4*>(g_reduced);
    size_t n4 = (size_t)NEDGE * EDIM / 4;
    for (size_t i = i0; i < n4; i += stride) r[i] = make_float4(0.f, 0.f, 0.f, 0.f);
    if (i0 < NLOC) g_ecnt[i0] = 0;
}

// ---------------- CSR build over n2e ----------------
__global__ void k_count(const int* __restrict__ n2e) {
    int e = blockIdx.x * blockDim.x + threadIdx.x;
    if (e < NEDGE) atomicAdd(&g_ecnt[n2e[e]], 1);
}

__global__ void k_scan() {
    __shared__ int sh[1024];
    int t = threadIdx.x;
    int c[4];
#pragma unroll
    for (int i = 0; i < 4; i++) c[i] = g_ecnt[t * 4 + i];
    int tot = c[0] + c[1] + c[2] + c[3];
    sh[t] = tot;
    __syncthreads();
    for (int st = 1; st < 1024; st <<= 1) {
        int add = (t >= st) ? sh[t - st] : 0;
        __syncthreads();
        sh[t] += add;
        __syncthreads();
    }
    int run = sh[t] - tot;  // exclusive prefix
#pragma unroll
    for (int i = 0; i < 4; i++) {
        g_eoff[t * 4 + i] = run;
        g_ecur[t * 4 + i] = run;
        run += c[i];
    }
    if (t == 1023) g_eoff[NLOC] = run;
}

__global__ void k_scatter(const int* __restrict__ n2e) {
    int e = blockIdx.x * blockDim.x + threadIdx.x;
    if (e < NEDGE) {
        int n = n2e[e];
        int pos = atomicAdd(&g_ecur[n], 1);
        g_eids[pos] = e;
    }
}

// ---------------- node_self ----------------
__global__ void k_node_self(const float* __restrict__ node_ext,
                            const float* __restrict__ W, const float* __restrict__ b,
                            const float* __restrict__ n_res0, float* __restrict__ out_node) {
    extern __shared__ float sm[];
    float* Ws = sm;              // 128*128
    float* xs = sm + 128 * 128;  // 128
    int tid = threadIdx.x;
    for (int idx = tid; idx < 128 * 128; idx += 128) Ws[idx] = W[idx];
    __syncthreads();
    for (int n = blockIdx.x; n < NLOC; n += gridDim.x) {
        xs[tid] = node_ext[(size_t)n * NDIM + tid];
        __syncthreads();
        float acc = b[tid];
#pragma unroll 8
        for (int k = 0; k < 128; k++) acc += xs[k] * Ws[k * 128 + tid];
        float y = silu_f(acc);
        out_node[(size_t)n * NDIM + tid] = node_ext[(size_t)n * NDIM + tid] + n_res0[tid] * y;
        __syncthreads();
    }
}

// ---------------- sym op ----------------
__global__ void k_sym(const float* __restrict__ edge_ebd, const float* __restrict__ node_ext,
                      const float* __restrict__ h2, const float* __restrict__ sw,
                      const int* __restrict__ n_ext2e) {
    __shared__ float S0[192], S1[192], S2[192];
    __shared__ float symv[768];
    int n = blockIdx.x;
    int t = threadIdx.x;
    int beg = g_eoff[n], end = g_eoff[n + 1];
    float a0 = 0.f, a1 = 0.f, a2 = 0.f;
    for (int i = beg; i < end; i++) {
        int e = g_eids[i];
        float swv = sw[e];
        float h0 = h2[e * 3 + 0] * swv;
        float h1 = h2[e * 3 + 1] * swv;
        float hh = h2[e * 3 + 2] * swv;
        float val = (t < 64) ? edge_ebd[(size_t)e * EDIM + t]
                             : node_ext[(size_t)n_ext2e[e] * NDIM + (t - 64)];
        a0 += h0 * val;
        a1 += h1 * val;
        a2 += hh * val;
    }
    S0[t] = a0; S1[t] = a1; S2[t] = a2;
    __syncthreads();
    if (t < 64) {
#pragma unroll
        for (int a = 0; a < 4; a++)
            symv[a * 64 + t] = SYM_SCALE * (S0[a] * S0[t] + S1[a] * S1[t] + S2[a] * S2[t]);
    } else {
        int dn = t - 64;
#pragma unroll
        for (int a = 0; a < 4; a++)
            symv[256 + a * 128 + dn] =
                SYM_SCALE * (S0[64 + a] * S0[t] + S1[64 + a] * S1[t] + S2[64 + a] * S2[t]);
    }
    __syncthreads();
    for (int idx = t; idx < 768; idx += 192) g_sym[(size_t)n * 768 + idx] = symv[idx];
}

// ---------------- node_sym GEMM: (4096x768)@(768x128) ----------------
__global__ __launch_bounds__(256) void k_symmm(const float* __restrict__ W,
                                               const float* __restrict__ b,
                                               const float* __restrict__ n_res1,
                                               float* __restrict__ out_node) {
    __shared__ float Wt[32 * 128];
    __shared__ float At[32 * 72];
    int tid = threadIdx.x;
    int jt = tid & 31, mt = tid >> 5;
    int n0 = blockIdx.x * 64;
    float acc[8][4];
#pragma unroll
    for (int i = 0; i < 8; i++)
#pragma unroll
        for (int q = 0; q < 4; q++) acc[i][q] = 0.f;
    for (int kt = 0; kt < 768; kt += 32) {
        for (int idx = tid; idx < 32 * 128; idx += 256)
            Wt[idx] = W[(size_t)(kt + idx / 128) * 128 + (idx % 128)];
        for (int idx = tid; idx < 32 * 64; idx += 256) {
            int m = idx / 32, k = idx % 32;
            At[k * 72 + m] = g_sym[(size_t)(n0 + m) * 768 + kt + k];
        }
        __syncthreads();
#pragma unroll 4
        for (int k = 0; k < 32; k++) {
            float4 A0 = *reinterpret_cast<const float4*>(&At[k * 72 + mt * 8]);
            float4 A1 = *reinterpret_cast<const float4*>(&At[k * 72 + mt * 8 + 4]);
            float am[8] = {A0.x, A0.y, A0.z, A0.w, A1.x, A1.y, A1.z, A1.w};
            float4 wv = *reinterpret_cast<const float4*>(&Wt[k * 128 + jt * 4]);
            float wq[4] = {wv.x, wv.y, wv.z, wv.w};
#pragma unroll
            for (int i = 0; i < 8; i++)
#pragma unroll
                for (int q = 0; q < 4; q++) acc[i][q] += am[i] * wq[q];
        }
        __syncthreads();
    }
#pragma unroll
    for (int i = 0; i < 8; i++) {
        int n = n0 + mt * 8 + i;
#pragma unroll
        for (int q = 0; q < 4; q++) {
            int j = jt * 4 + q;
            float y = silu_f(acc[i][q] + b[j]);
            out_node[(size_t)n * 128 + j] += n_res1[j] * y;
        }
    }
}

// ---------------- base precompute ----------------
__global__ __launch_bounds__(256) void k_base(const float* __restrict__ node_ext,
                                              const float* __restrict__ W_ne,
                                              const float* __restrict__ W_es,
                                              const float* __restrict__ b_ne,
                                              const float* __restrict__ b_es) {
    __shared__ float Wt[32 * 192];
    __shared__ float At[32 * 72];
    int tid = threadIdx.x;
    int jt = tid & 31, mt = tid >> 5;
    int n0 = blockIdx.x * 64;
    float acc[8][6];
#pragma unroll
    for (int i = 0; i < 8; i++)
#pragma unroll
        for (int c = 0; c < 6; c++) acc[i][c] = 0.f;
    for (int kt = 0; kt < 128; kt += 32) {
        for (int idx = tid; idx < 32 * 192; idx += 256) {
            int k = idx / 192, j = idx % 192;
            int row = kt + k;
            Wt[idx] = (j < 128) ? W_ne[(size_t)row * 128 + j] : W_es[(size_t)row * 64 + (j - 128)];
        }
        for (int idx = tid; idx < 32 * 64; idx += 256) {
            int m = idx / 32, k = idx % 32;
            At[k * 72 + m] = node_ext[(size_t)(n0 + m) * NDIM + kt + k];
        }
        __syncthreads();
#pragma unroll 2
        for (int k = 0; k < 32; k++) {
            float4 A0 = *reinterpret_cast<const float4*>(&At[k * 72 + mt * 8]);
            float4 A1 = *reinterpret_cast<const float4*>(&At[k * 72 + mt * 8 + 4]);
            float am[8] = {A0.x, A0.y, A0.z, A0.w, A1.x, A1.y, A1.z, A1.w};
#pragma unroll
            for (int c = 0; c < 6; c++) {
                float w = Wt[k * 192 + jt + 32 * c];
#pragma unroll
                for (int i = 0; i < 8; i++) acc[i][c] += am[i] * w;
            }
        }
        __syncthreads();
    }
#pragma unroll
    for (int i = 0; i < 8; i++) {
        int n = n0 + mt * 8 + i;
#pragma unroll
        for (int c = 0; c < 6; c++) {
            int j = jt + 32 * c;
            float bb = (j < 128) ? b_ne[j] : b_es[j - 128];
            g_base[(size_t)n * 192 + j] = acc[i][c] + bb;
        }
    }
}

// ---------------- main edge GEMM (f32x2 packed) ----------------
__global__ __launch_bounds__(256) void k_edge(
    const float* __restrict__ node_ext, const float* __restrict__ edge_ebd,
    const float* __restrict__ sw, const int* __restrict__ n_ext2e,
    const float* __restrict__ W_ne, const float* __restrict__ W_es,
    const float* __restrict__ n_res2, const float* __restrict__ e_res0,
    float* __restrict__ out_node, float* __restrict__ out_edge) {
    extern __shared__ float smem[];
    float* Ws = smem;               // 192*192
    float* At = Ws + 192 * 192;     // 192*72
    float* base_s = At + 192 * 72;  // 192
    float* msg = base_s + 192;      // 128
    float* sws = msg + 128;         // 64
    int* eid = (int*)(sws + 64);    // 64
    int* nei = eid + 64;            // 64

    int tid = threadIdx.x;
    int jt = tid & 31, mt = tid >> 5;
    for (int idx = tid; idx < 192 * 192; idx += 256) {
        int k = idx / 192, j = idx % 192;
        Ws[idx] = (j < 128) ? W_ne[(size_t)(128 + k) * 128 + j]
                            : W_es[(size_t)(128 + k) * 64 + (j - 128)];
    }
    for (int nn = 0; nn < 4; nn++) {
        int node = blockIdx.x * 4 + nn;
        __syncthreads();
        for (int idx = tid; idx < 192; idx += 256)
            base_s[idx] = g_base[(size_t)node * 192 + idx];
        if (tid < 128) msg[tid] = 0.f;
        __syncthreads();
        int beg = g_eoff[node];
        int cnt = g_eoff[node + 1] - beg;
        for (int c0 = 0; c0 < cnt; c0 += 64) {
            int mcount = min(64, cnt - c0);
            if (tid < 64) {
                if (tid < mcount) {
                    int e = g_eids[beg + c0 + tid];
                    eid[tid] = e;
                    nei[tid] = n_ext2e[e];
                    sws[tid] = sw[e];
                } else {
                    eid[tid] = 0; nei[tid] = 0; sws[tid] = 0.f;
                }
            }
            __syncthreads();
            for (int idx = tid; idx < 64 * 192; idx += 256) {
                int m = idx / 192, kk = idx - m * 192;
                float v = 0.f;
                if (m < mcount)
                    v = (kk < 128) ? node_ext[(size_t)nei[m] * NDIM + kk]
                                   : edge_ebd[(size_t)eid[m] * EDIM + (kk - 128)];
                At[kk * 72 + m] = v;
            }
            __syncthreads();

            unsigned long long acc[4][6];
#pragma unroll
            for (int p = 0; p < 4; p++)
#pragma unroll
                for (int c = 0; c < 6; c++) acc[p][c] = 0ULL;

#pragma unroll 2
            for (int k = 0; k < 192; k++) {
                ulonglong2 A01 = *reinterpret_cast<const ulonglong2*>(&At[k * 72 + mt * 8]);
                ulonglong2 A23 = *reinterpret_cast<const ulonglong2*>(&At[k * 72 + mt * 8 + 4]);
                const float* wr = &Ws[k * 192 + jt];
#pragma unroll
                for (int c = 0; c < 6; c++) {
                    unsigned long long ww = pack2(wr[32 * c]);
                    ffma2(acc[0][c], A01.x, ww);
                    ffma2(acc[1][c], A01.y, ww);
                    ffma2(acc[2][c], A23.x, ww);
                    ffma2(acc[3][c], A23.y, ww);
                }
            }

            float msum[4] = {0.f, 0.f, 0.f, 0.f};
#pragma unroll
            for (int p = 0; p < 4; p++) {
                int r0 = mt * 8 + 2 * p;
                int r1 = r0 + 1;
#pragma unroll
                for (int c = 0; c < 6; c++) {
                    float lo, hi;
                    unpack2(acc[p][c], lo, hi);
                    int j = jt + 32 * c;
                    if (r0 < mcount) {
                        float y = silu_f(lo + base_s[j]);
                        if (j < 128) {
                            msum[c] += y * sws[r0];
                        } else {
                            int col = j - 128;
                            size_t off = (size_t)eid[r0] * EDIM + col;
                            out_edge[off] = edge_ebd[off] + e_res0[col] * y;
                        }
                    }
                    if (r1 < mcount) {
                        float y = silu_f(hi + base_s[j]);
                        if (j < 128) {
                            msum[c] += y * sws[r1];
                        } else {
                            int col = j - 128;
                            size_t off = (size_t)eid[r1] * EDIM + col;
                            out_edge[off] = edge_ebd[off] + e_res0[col] * y;
                        }
                    }
                }
            }
#pragma unroll
            for (int c = 0; c < 4; c++) atomicAdd(&msg[jt + 32 * c], msum[c]);
            __syncthreads();
        }
        if (tid < 128)
            out_node[(size_t)node * NDIM + tid] += n_res2[tid] * msg[tid] * INV_DYN_E;
    }
}

// ---------------- angle GEMM (f32x2 packed) ----------------
__global__ __launch_bounds__(256) void k_angle(
    const float* __restrict__ angle_ebd, const float* __restrict__ node_ext,
    const float* __restrict__ edge_ebd, const int* __restrict__ ai,
    const float* __restrict__ a_sw,
    const float* __restrict__ W_ea1, const float* __restrict__ b_ea1,
    const float* __restrict__ W_as, const float* __restrict__ b_as,
    const float* __restrict__ a_res0, float* __restrict__ out_angle) {
    extern __shared__ float smem[];
    float* Wa = smem;             // 288*96
    float* At = Wa + 288 * 96;    // 288*72
    int* na = (int*)(At + 288 * 72);  // 64
    int* ika = na + 64;               // 64
    int* ija = ika + 64;              // 64

    int tid = threadIdx.x;
    int jt = tid & 31, mt = tid >> 5;
    const int* n2a = ai;
    const int* eij = ai + NANGLE;
    const int* eik = ai + 2 * NANGLE;

    for (int idx = tid; idx < 288 * 96; idx += 256) {
        int k = idx / 96, j = idx % 96;
        Wa[idx] = (j < 64) ? W_ea1[(size_t)k * 64 + j] : W_as[(size_t)k * 32 + (j - 64)];
    }
    int a0 = blockIdx.x * 64;
    if (tid < 64) {
        na[tid] = n2a[a0 + tid];
        ika[tid] = eik[a0 + tid];
        ija[tid] = eij[a0 + tid];
    }
    __syncthreads();
    for (int idx = tid; idx < 64 * 288; idx += 256) {
        int m = idx / 288, k = idx - m * 288;
        int a = a0 + m;
        float v;
        if (k < 32) v = angle_ebd[(size_t)a * ADIM + k];
        else if (k < 160) v = node_ext[(size_t)na[m] * NDIM + (k - 32)];
        else if (k < 224) v = edge_ebd[(size_t)ika[m] * EDIM + (k - 160)];
        else v = edge_ebd[(size_t)ija[m] * EDIM + (k - 224)];
        At[k * 72 + m] = v;
    }
    __syncthreads();

    unsigned long long acc[4][3];
#pragma unroll
    for (int p = 0; p < 4; p++)
#pragma unroll
        for (int c = 0; c < 3; c++) acc[p][c] = 0ULL;

#pragma unroll 2
    for (int k = 0; k < 288; k++) {
        ulonglong2 A01 = *reinterpret_cast<const ulonglong2*>(&At[k * 72 + mt * 8]);
        ulonglong2 A23 = *reinterpret_cast<const ulonglong2*>(&At[k * 72 + mt * 8 + 4]);
        const float* wr = &Wa[k * 96 + jt];
#pragma unroll
        for (int c = 0; c < 3; c++) {
            unsigned long long ww = pack2(wr[32 * c]);
            ffma2(acc[0][c], A01.x, ww);
            ffma2(acc[1][c], A01.y, ww);
            ffma2(acc[2][c], A23.x, ww);
            ffma2(acc[3][c], A23.y, ww);
        }
    }

#pragma unroll
    for (int p = 0; p < 4; p++) {
        int r0 = mt * 8 + 2 * p;
        int r1 = r0 + 1;
        int a_r0 = a0 + r0, a_r1 = a0 + r1;
        float sw0 = a_sw[a_r0], sw1 = a_sw[a_r1];
#pragma unroll
        for (int c = 0; c < 3; c++) {
            float lo, hi;
            unpack2(acc[p][c], lo, hi);
            int j = jt + 32 * c;
            if (j < 64) {
                float y0 = silu_f(lo + b_ea1[j]);
                float y1 = silu_f(hi + b_ea1[j]);
                atomicAdd(&g_reduced[(size_t)ija[r0] * EDIM + j], y0 * sw0);
                atomicAdd(&g_reduced[(size_t)ija[r1] * EDIM + j], y1 * sw1);
            } else {
                int j2 = j - 64;  // == jt
                float y0 = silu_f(lo + b_as[j2]);
                float y1 = silu_f(hi + b_as[j2]);
                out_angle[(size_t)a_r0 * ADIM + j2] =
                    angle_ebd[(size_t)a_r0 * ADIM + j2] + a_res0[j2] * y0;
                out_angle[(size_t)a_r1 * ADIM + j2] =
                    angle_ebd[(size_t)a_r1 * ADIM + j2] + a_res0[j2] * y1;
            }
        }
    }
}

// ---------------- edge angle message GEMM 262144x64x64 ----------------
__global__ __launch_bounds__(256) void k_edge_msg(const float* __restrict__ W2,
                                                  const float* __restrict__ b2,
                                                  const float* __restrict__ e_res1,
                                                  float* __restrict__ out_edge) {
    __shared__ float Ws[64 * 64];
    __shared__ float At[64 * 68];
    int tid = threadIdx.x;
    int jt = tid & 31, mt = tid >> 5;
    int e0 = blockIdx.x * 64;
    for (int idx = tid; idx < 64 * 64; idx += 256) Ws[idx] = W2[idx];
    for (int idx = tid; idx < 64 * 64; idx += 256) {
        int m = idx >> 6, k = idx & 63;
        At[k * 68 + m] = g_reduced[(size_t)(e0 + m) * EDIM + k];
    }
    __syncthreads();
    float acc[8][2];
#pragma unroll
    for (int i = 0; i < 8; i++) { acc[i][0] = 0.f; acc[i][1] = 0.f; }
#pragma unroll 4
    for (int k = 0; k < 64; k++) {
        float4 A0 = *reinterpret_cast<const float4*>(&At[k * 68 + mt * 8]);
        float4 A1 = *reinterpret_cast<const float4*>(&At[k * 68 + mt * 8 + 4]);
        float am[8] = {A0.x, A0.y, A0.z, A0.w, A1.x, A1.y, A1.z, A1.w};
        float w0 = Ws[k * 64 + jt];
        float w1 = Ws[k * 64 + jt + 32];
#pragma unroll
        for (int i = 0; i < 8; i++) {
            acc[i][0] += am[i] * w0;
            acc[i][1] += am[i] * w1;
        }
    }
#pragma unroll
    for (int i = 0; i < 8; i++) {
        int e = e0 + mt * 8 + i;
#pragma unroll
        for (int q = 0; q < 2; q++) {
            int j = jt + 32 * q;
            float y = silu_f(acc[i][q] + b2[j]);
            out_edge[(size_t)e * EDIM + j] += e_res1[j] * y;
        }
    }
}

// ---------------- launch ----------------
extern "C" void kernel_launch(void* const* d_in, const int* in_sizes, int n_in,
                              void* d_out, int out_size) {
    const float* node_ext   = (const float*)d_in[0];
    const float* edge_ebd   = (const float*)d_in[1];
    const float* h2         = (const float*)d_in[2];
    const float* angle_ebd  = (const float*)d_in[3];
    const float* sw         = (const float*)d_in[6];
    const float* a_sw       = (const float*)d_in[9];
    const int*   edge_index = (const int*)d_in[10];
    const int*   angle_index= (const int*)d_in[11];
    const float* W_node_self = (const float*)d_in[12];
    const float* b_node_self = (const float*)d_in[13];
    const float* W_node_sym  = (const float*)d_in[14];
    const float* b_node_sym  = (const float*)d_in[15];
    const float* W_node_edge = (const float*)d_in[16];
    const float* b_node_edge = (const float*)d_in[17];
    const float* W_edge_self = (const float*)d_in[18];
    const float* b_edge_self = (const float*)d_in[19];
    const float* W_edge_angle1 = (const float*)d_in[20];
    const float* b_edge_angle1 = (const float*)d_in[21];
    const float* W_edge_angle2 = (const float*)d_in[22];
    const float* b_edge_angle2 = (const float*)d_in[23];
    const float* W_angle_self  = (const float*)d_in[24];
    const float* b_angle_self  = (const float*)d_in[25];
    const float* n_res0 = (const float*)d_in[26];
    const float* n_res1 = (const float*)d_in[27];
    const float* n_res2 = (const float*)d_in[28];
    const float* e_res0 = (const float*)d_in[29];
    const float* e_res1 = (const float*)d_in[30];
    const float* a_res0 = (const float*)d_in[31];

    float* out = (float*)d_out;
    float* out_node  = out;
    float* out_edge  = out + (size_t)NLOC * NDIM;
    float* out_angle = out_edge + (size_t)NEDGE * EDIM;

    const int* n2e = edge_index;              // row 0
    const int* n_ext2e = edge_index + NEDGE;  // row 1

    cudaFuncSetAttribute((const void*)k_node_self,
                         cudaFuncAttributeMaxDynamicSharedMemorySize, 66048);
    cudaFuncSetAttribute((const void*)k_edge,
                         cudaFuncAttributeMaxDynamicSharedMemorySize, 204800);
    cudaFuncSetAttribute((const void*)k_angle,
                         cudaFuncAttributeMaxDynamicSharedMemorySize, 194304);

    k_zero<<<4096, 256>>>();
    k_count<<<NEDGE / 256, 256>>>(n2e);
    k_scan<<<1, 1024>>>();
    k_scatter<<<NEDGE / 256, 256>>>(n2e);
    k_node_self<<<256, 128, 66048>>>(node_ext, W_node_self, b_node_self, n_res0, out_node);
    k_sym<<<NLOC, 192>>>(edge_ebd, node_ext, h2, sw, n_ext2e);
    k_symmm<<<NLOC / 64, 256>>>(W_node_sym, b_node_sym, n_res1, out_node);
    k_base<<<NLOC / 64, 256>>>(node_ext, W_node_edge, W_edge_self, b_node_edge, b_edge_self);
    k_edge<<<NLOC / 4, 256, 204800>>>(node_ext, edge_ebd, sw, n_ext2e,
                                      W_node_edge, W_edge_self, n_res2, e_res0,
                                      out_node, out_edge);
    k_angle<<<NANGLE / 64, 256, 194304>>>(angle_ebd, node_ext, edge_ebd, angle_index, a_sw,
                                          W_edge_angle1, b_edge_angle1,
                                          W_angle_self, b_angle_self, a_res0, out_angle);
    k_edge_msg<<<NEDGE / 64, 256>>>(W_edge_angle2, b_edge_angle2, e_res1, out_edge);
}

// round 3
// speedup vs baseline: 2.0716x; 2.0716x over previous
#include <cuda_runtime.h>
#include <cstdint>
#include <cstddef>

#define NLOC   4096
#define NALL   6144
#define NDIM   128
#define EDIM   64
#define ADIM   32
#define NEDGE  262144
#define NANGLE 409600
#define INV_DYN_E 0.15625f            // 1/6.4
#define SYM_SCALE 0.0520833333333f    // (1/6.4)/3

// ---------------- device scratch ----------------
__device__ float g_sym[(size_t)NLOC * 768];
__device__ float g_base[(size_t)NLOC * 192];
__device__ float g_reduced[(size_t)NEDGE * EDIM];
__device__ float g_msg[(size_t)NLOC * NDIM];
__device__ int   g_ecnt[NLOC];
__device__ int   g_eoff[NLOC + 1];
__device__ int   g_ecur[NLOC];
__device__ int   g_eids[NEDGE];
__device__ int   g_enode[NEDGE];

// ---------------- helpers ----------------
__device__ __forceinline__ float silu_f(float x) { return x / (1.0f + __expf(-x)); }

__device__ __forceinline__ unsigned long long pack2(float w) {
    unsigned long long r;
    unsigned int u = __float_as_uint(w);
    asm("mov.b64 %0, {%1,%1};" : "=l"(r) : "r"(u));
    return r;
}
__device__ __forceinline__ void ffma2(unsigned long long& d, unsigned long long a,
                                      unsigned long long b) {
    asm("fma.rn.f32x2 %0, %1, %2, %0;" : "+l"(d) : "l"(a), "l"(b));
}
__device__ __forceinline__ void unpack2(unsigned long long v, float& lo, float& hi) {
    unsigned int l, h;
    asm("mov.b64 {%0,%1}, %2;" : "=r"(l), "=r"(h) : "l"(v));
    lo = __uint_as_float(l);
    hi = __uint_as_float(h);
}

// ---------------- zero scratch ----------------
__global__ void k_zero() {
    size_t i0 = (size_t)blockIdx.x * blockDim.x + threadIdx.x;
    size_t stride = (size_t)gridDim.x * blockDim.x;
    float4* r = reinterpret_cast<float4*>(g_reduced);
    size_t n4 = (size_t)NEDGE * EDIM / 4;
    for (size_t i = i0; i < n4; i += stride) r[i] = make_float4(0.f, 0.f, 0.f, 0.f);
    float4* m = reinterpret_cast<float4*>(g_msg);
    size_t m4 = (size_t)NLOC * NDIM / 4;
    for (size_t i = i0; i < m4; i += stride) m[i] = make_float4(0.f, 0.f, 0.f, 0.f);
    if (i0 < NLOC) g_ecnt[i0] = 0;
}

// ---------------- CSR build ----------------
__global__ void k_count(const int* __restrict__ n2e) {
    int e = blockIdx.x * blockDim.x + threadIdx.x;
    if (e < NEDGE) atomicAdd(&g_ecnt[n2e[e]], 1);
}

__global__ void k_scan() {
    __shared__ int sh[1024];
    int t = threadIdx.x;
    int c[4];
#pragma unroll
    for (int i = 0; i < 4; i++) c[i] = g_ecnt[t * 4 + i];
    int tot = c[0] + c[1] + c[2] + c[3];
    sh[t] = tot;
    __syncthreads();
    for (int st = 1; st < 1024; st <<= 1) {
        int add = (t >= st) ? sh[t - st] : 0;
        __syncthreads();
        sh[t] += add;
        __syncthreads();
    }
    int run = sh[t] - tot;
#pragma unroll
    for (int i = 0; i < 4; i++) {
        g_eoff[t * 4 + i] = run;
        g_ecur[t * 4 + i] = run;
        run += c[i];
    }
    if (t == 1023) g_eoff[NLOC] = run;
}

__global__ void k_scatter(const int* __restrict__ n2e) {
    int e = blockIdx.x * blockDim.x + threadIdx.x;
    if (e < NEDGE) {
        int n = n2e[e];
        int pos = atomicAdd(&g_ecur[n], 1);
        g_eids[pos] = e;
        g_enode[pos] = n;
    }
}

// ---------------- node_self ----------------
__global__ void k_node_self(const float* __restrict__ node_ext,
                            const float* __restrict__ W, const float* __restrict__ b,
                            const float* __restrict__ n_res0, float* __restrict__ out_node) {
    extern __shared__ float sm[];
    float* Ws = sm;
    float* xs = sm + 128 * 128;
    int tid = threadIdx.x;
    for (int idx = tid; idx < 128 * 128; idx += 128) Ws[idx] = W[idx];
    __syncthreads();
    for (int n = blockIdx.x; n < NLOC; n += gridDim.x) {
        xs[tid] = node_ext[(size_t)n * NDIM + tid];
        __syncthreads();
        float acc = b[tid];
#pragma unroll 8
        for (int k = 0; k < 128; k++) acc += xs[k] * Ws[k * 128 + tid];
        float y = silu_f(acc);
        out_node[(size_t)n * NDIM + tid] = node_ext[(size_t)n * NDIM + tid] + n_res0[tid] * y;
        __syncthreads();
    }
}

// ---------------- sym op ----------------
__global__ void k_sym(const float* __restrict__ edge_ebd, const float* __restrict__ node_ext,
                      const float* __restrict__ h2, const float* __restrict__ sw,
                      const int* __restrict__ n_ext2e) {
    __shared__ float S0[192], S1[192], S2[192];
    __shared__ float symv[768];
    int n = blockIdx.x;
    int t = threadIdx.x;
    int beg = g_eoff[n], end = g_eoff[n + 1];
    float a0 = 0.f, a1 = 0.f, a2 = 0.f;
    for (int i = beg; i < end; i++) {
        int e = g_eids[i];
        float swv = sw[e];
        float h0 = h2[e * 3 + 0] * swv;
        float h1 = h2[e * 3 + 1] * swv;
        float hh = h2[e * 3 + 2] * swv;
        float val = (t < 64) ? edge_ebd[(size_t)e * EDIM + t]
                             : node_ext[(size_t)n_ext2e[e] * NDIM + (t - 64)];
        a0 += h0 * val;
        a1 += h1 * val;
        a2 += hh * val;
    }
    S0[t] = a0; S1[t] = a1; S2[t] = a2;
    __syncthreads();
    if (t < 64) {
#pragma unroll
        for (int a = 0; a < 4; a++)
            symv[a * 64 + t] = SYM_SCALE * (S0[a] * S0[t] + S1[a] * S1[t] + S2[a] * S2[t]);
    } else {
        int dn = t - 64;
#pragma unroll
        for (int a = 0; a < 4; a++)
            symv[256 + a * 128 + dn] =
                SYM_SCALE * (S0[64 + a] * S0[t] + S1[64 + a] * S1[t] + S2[64 + a] * S2[t]);
    }
    __syncthreads();
    for (int idx = t; idx < 768; idx += 192) g_sym[(size_t)n * 768 + idx] = symv[idx];
}

// ---------------- node_sym GEMM ----------------
__global__ __launch_bounds__(256) void k_symmm(const float* __restrict__ W,
                                               const float* __restrict__ b,
                                               const float* __restrict__ n_res1,
                                               float* __restrict__ out_node) {
    __shared__ float Wt[32 * 128];
    __shared__ float At[32 * 72];
    int tid = threadIdx.x;
    int jt = tid & 31, mt = tid >> 5;
    int n0 = blockIdx.x * 64;
    float acc[8][4];
#pragma unroll
    for (int i = 0; i < 8; i++)
#pragma unroll
        for (int q = 0; q < 4; q++) acc[i][q] = 0.f;
    for (int kt = 0; kt < 768; kt += 32) {
        for (int idx = tid; idx < 32 * 128; idx += 256)
            Wt[idx] = W[(size_t)(kt + idx / 128) * 128 + (idx % 128)];
        for (int idx = tid; idx < 32 * 64; idx += 256) {
            int m = idx / 32, k = idx % 32;
            At[k * 72 + m] = g_sym[(size_t)(n0 + m) * 768 + kt + k];
        }
        __syncthreads();
#pragma unroll 4
        for (int k = 0; k < 32; k++) {
            float4 A0 = *reinterpret_cast<const float4*>(&At[k * 72 + mt * 8]);
            float4 A1 = *reinterpret_cast<const float4*>(&At[k * 72 + mt * 8 + 4]);
            float am[8] = {A0.x, A0.y, A0.z, A0.w, A1.x, A1.y, A1.z, A1.w};
            float4 wv = *reinterpret_cast<const float4*>(&Wt[k * 128 + jt * 4]);
            float wq[4] = {wv.x, wv.y, wv.z, wv.w};
#pragma unroll
            for (int i = 0; i < 8; i++)
#pragma unroll
                for (int q = 0; q < 4; q++) acc[i][q] += am[i] * wq[q];
        }
        __syncthreads();
    }
#pragma unroll
    for (int i = 0; i < 8; i++) {
        int n = n0 + mt * 8 + i;
#pragma unroll
        for (int q = 0; q < 4; q++) {
            int j = jt * 4 + q;
            float y = silu_f(acc[i][q] + b[j]);
            out_node[(size_t)n * 128 + j] += n_res1[j] * y;
        }
    }
}

// ---------------- base precompute ----------------
__global__ __launch_bounds__(256) void k_base(const float* __restrict__ node_ext,
                                              const float* __restrict__ W_ne,
                                              const float* __restrict__ W_es,
                                              const float* __restrict__ b_ne,
                                              const float* __restrict__ b_es) {
    __shared__ float Wt[32 * 192];
    __shared__ float At[32 * 72];
    int tid = threadIdx.x;
    int jt = tid & 31, mt = tid >> 5;
    int n0 = blockIdx.x * 64;
    float acc[8][6];
#pragma unroll
    for (int i = 0; i < 8; i++)
#pragma unroll
        for (int c = 0; c < 6; c++) acc[i][c] = 0.f;
    for (int kt = 0; kt < 128; kt += 32) {
        for (int idx = tid; idx < 32 * 192; idx += 256) {
            int k = idx / 192, j = idx % 192;
            int row = kt + k;
            Wt[idx] = (j < 128) ? W_ne[(size_t)row * 128 + j] : W_es[(size_t)row * 64 + (j - 128)];
        }
        for (int idx = tid; idx < 32 * 64; idx += 256) {
            int m = idx / 32, k = idx % 32;
            At[k * 72 + m] = node_ext[(size_t)(n0 + m) * NDIM + kt + k];
        }
        __syncthreads();
#pragma unroll 2
        for (int k = 0; k < 32; k++) {
            float4 A0 = *reinterpret_cast<const float4*>(&At[k * 72 + mt * 8]);
            float4 A1 = *reinterpret_cast<const float4*>(&At[k * 72 + mt * 8 + 4]);
            float am[8] = {A0.x, A0.y, A0.z, A0.w, A1.x, A1.y, A1.z, A1.w};
#pragma unroll
            for (int c = 0; c < 6; c++) {
                float w = Wt[k * 192 + jt + 32 * c];
#pragma unroll
                for (int i = 0; i < 8; i++) acc[i][c] += am[i] * w;
            }
        }
        __syncthreads();
    }
#pragma unroll
    for (int i = 0; i < 8; i++) {
        int n = n0 + mt * 8 + i;
#pragma unroll
        for (int c = 0; c < 6; c++) {
            int j = jt + 32 * c;
            float bb = (j < 128) ? b_ne[j] : b_es[j - 128];
            g_base[(size_t)n * 192 + j] = acc[i][c] + bb;
        }
    }
}

// ---------------- main edge GEMM: full-64 CSR chunks, 512 threads, persistent ----------------
__global__ __launch_bounds__(512) void k_edge(
    const float* __restrict__ node_ext, const float* __restrict__ edge_ebd,
    const float* __restrict__ sw, const int* __restrict__ n_ext2e,
    const float* __restrict__ W_ne, const float* __restrict__ W_es,
    const float* __restrict__ e_res0, float* __restrict__ out_edge) {
    extern __shared__ float smem[];
    float* Ws = smem;                     // 192*192
    float* At = Ws + 192 * 192;           // 192*68
    int* eidv = (int*)(At + 192 * 68);    // 64
    int* nodev = eidv + 64;               // 64
    float* sws = (float*)(nodev + 64);    // 64

    int tid = threadIdx.x;
    int jt = tid & 31, mt = tid >> 5;   // mt 0..15, rows mt*4..+4
    int mfill = tid & 63;               // fill row
    int seg = tid >> 6;                 // 0..7, kk range seg*24..+24

    for (int idx = tid; idx < 192 * 192; idx += 512) {
        int k = idx / 192, j = idx % 192;
        Ws[idx] = (j < 128) ? W_ne[(size_t)(128 + k) * 128 + j]
                            : W_es[(size_t)(128 + k) * 64 + (j - 128)];
    }
    float er0 = e_res0[jt], er1 = e_res0[jt + 32];

    for (int ch = blockIdx.x; ch < NEDGE / 64; ch += gridDim.x) {
        int c0 = ch * 64;
        __syncthreads();
        if (tid < 64) {
            int e = g_eids[c0 + tid];
            eidv[tid] = e;
            nodev[tid] = g_enode[c0 + tid];
            sws[tid] = sw[e];
        }
        // fill At (row mfill, kk seg*24..+24); loads indices directly from global
        {
            int e = __ldg(&g_eids[c0 + mfill]);
            int nd = __ldg(&n_ext2e[e]);
            const float4* nrow = (const float4*)(node_ext + (size_t)nd * NDIM);
            const float4* erow = (const float4*)(edge_ebd + (size_t)e * EDIM);
#pragma unroll
            for (int q = 0; q < 6; q++) {
                int kk = seg * 24 + q * 4;
                float4 v = (kk < 128) ? nrow[kk >> 2] : erow[(kk - 128) >> 2];
                At[(kk + 0) * 68 + mfill] = v.x;
                At[(kk + 1) * 68 + mfill] = v.y;
                At[(kk + 2) * 68 + mfill] = v.z;
                At[(kk + 3) * 68 + mfill] = v.w;
            }
        }
        __syncthreads();

        unsigned long long acc[2][6];
#pragma unroll
        for (int p = 0; p < 2; p++)
#pragma unroll
            for (int c = 0; c < 6; c++) acc[p][c] = 0ULL;

#pragma unroll 2
        for (int k = 0; k < 192; k++) {
            ulonglong2 A = *reinterpret_cast<const ulonglong2*>(&At[k * 68 + mt * 4]);
            const float* wr = &Ws[k * 192 + jt];
#pragma unroll
            for (int c = 0; c < 6; c++) {
                unsigned long long ww = pack2(wr[32 * c]);
                ffma2(acc[0][c], A.x, ww);
                ffma2(acc[1][c], A.y, ww);
            }
        }

        int r0 = mt * 4;
        // edge outputs (cols 128..191)
#pragma unroll
        for (int c = 4; c < 6; c++) {
            int j = jt + 32 * c;
            int col = j - 128;
            float er = (c == 4) ? er0 : er1;
#pragma unroll
            for (int p = 0; p < 2; p++) {
                float lo, hi;
                unpack2(acc[p][c], lo, hi);
                int ra = r0 + 2 * p, rb = ra + 1;
                {
                    float bv = g_base[(size_t)nodev[ra] * 192 + j];
                    float y = silu_f(lo + bv);
                    size_t off = (size_t)eidv[ra] * EDIM + col;
                    out_edge[off] = edge_ebd[off] + er * y;
                }
                {
                    float bv = g_base[(size_t)nodev[rb] * 192 + j];
                    float y = silu_f(hi + bv);
                    size_t off = (size_t)eidv[rb] * EDIM + col;
                    out_edge[off] = edge_ebd[off] + er * y;
                }
            }
        }
        // node message (cols 0..127), segmented atomic flush by node
#pragma unroll
        for (int c = 0; c < 4; c++) {
            int j = jt + 32 * c;
            int cur = nodev[r0];
            float s = 0.f;
#pragma unroll
            for (int p = 0; p < 2; p++) {
                float lo, hi;
                unpack2(acc[p][c], lo, hi);
                float v[2] = {lo, hi};
#pragma unroll
                for (int h = 0; h < 2; h++) {
                    int r = r0 + 2 * p + h;
                    int nd = nodev[r];
                    float y = silu_f(v[h] + g_base[(size_t)nd * 192 + j]);
                    float contrib = y * sws[r];
                    if (nd != cur) {
                        atomicAdd(&g_msg[(size_t)cur * NDIM + j], s);
                        s = 0.f;
                        cur = nd;
                    }
                    s += contrib;
                }
            }
            atomicAdd(&g_msg[(size_t)cur * NDIM + j], s);
        }
    }
}

// ---------------- node finish: add edge message ----------------
__global__ void k_node_finish(const float* __restrict__ n_res2, float* __restrict__ out_node) {
    int i = blockIdx.x * blockDim.x + threadIdx.x;
    if (i < NLOC * NDIM) {
        int j = i & (NDIM - 1);
        out_node[i] += n_res2[j] * g_msg[i] * INV_DYN_E;
    }
}

// ---------------- angle GEMM: persistent, 512 threads ----------------
__global__ __launch_bounds__(512) void k_angle(
    const float* __restrict__ angle_ebd, const float* __restrict__ node_ext,
    const float* __restrict__ edge_ebd, const int* __restrict__ ai,
    const float* __restrict__ a_sw,
    const float* __restrict__ W_ea1, const float* __restrict__ b_ea1,
    const float* __restrict__ W_as, const float* __restrict__ b_as,
    const float* __restrict__ a_res0, float* __restrict__ out_angle) {
    extern __shared__ float smem[];
    float* Wa = smem;                    // 288*96
    float* At = Wa + 288 * 96;           // 288*68
    int* ijav = (int*)(At + 288 * 68);   // 64
    float* aswv = (float*)(ijav + 64);   // 64

    int tid = threadIdx.x;
    int jt = tid & 31, mt = tid >> 5;
    int mfill = tid & 63;
    int seg = tid >> 6;  // 0..7, kk seg*36..+36

    const int* n2a = ai;
    const int* eij = ai + NANGLE;
    const int* eik = ai + 2 * NANGLE;

    for (int idx = tid; idx < 288 * 96; idx += 512) {
        int k = idx / 96, j = idx % 96;
        Wa[idx] = (j < 64) ? W_ea1[(size_t)k * 64 + j] : W_as[(size_t)k * 32 + (j - 64)];
    }
    float be0 = b_ea1[jt], be1 = b_ea1[jt + 32];
    float ba = b_as[jt], ar = a_res0[jt];

    for (int t = blockIdx.x; t < NANGLE / 64; t += gridDim.x) {
        int a0 = t * 64;
        __syncthreads();
        if (tid < 64) {
            ijav[tid] = eij[a0 + tid];
            aswv[tid] = a_sw[a0 + tid];
        }
        {
            int m = mfill;
            int a = a0 + m;
            int nd = __ldg(&n2a[a]);
            int ek = __ldg(&eik[a]);
            int ej = __ldg(&eij[a]);
            const float4* arow = (const float4*)(angle_ebd + (size_t)a * ADIM);
            const float4* nrow = (const float4*)(node_ext + (size_t)nd * NDIM);
            const float4* krow = (const float4*)(edge_ebd + (size_t)ek * EDIM);
            const float4* jrow = (const float4*)(edge_ebd + (size_t)ej * EDIM);
#pragma unroll
            for (int q = 0; q < 9; q++) {
                int kk = seg * 36 + q * 4;
                float4 v;
                if (kk < 32) v = arow[kk >> 2];
                else if (kk < 160) v = nrow[(kk - 32) >> 2];
                else if (kk < 224) v = krow[(kk - 160) >> 2];
                else v = jrow[(kk - 224) >> 2];
                At[(kk + 0) * 68 + m] = v.x;
                At[(kk + 1) * 68 + m] = v.y;
                At[(kk + 2) * 68 + m] = v.z;
                At[(kk + 3) * 68 + m] = v.w;
            }
        }
        __syncthreads();

        unsigned long long acc[2][3];
#pragma unroll
        for (int p = 0; p < 2; p++)
#pragma unroll
            for (int c = 0; c < 3; c++) acc[p][c] = 0ULL;

#pragma unroll 2
        for (int k = 0; k < 288; k++) {
            ulonglong2 A = *reinterpret_cast<const ulonglong2*>(&At[k * 68 + mt * 4]);
            const float* wr = &Wa[k * 96 + jt];
#pragma unroll
            for (int c = 0; c < 3; c++) {
                unsigned long long ww = pack2(wr[32 * c]);
                ffma2(acc[0][c], A.x, ww);
                ffma2(acc[1][c], A.y, ww);
            }
        }

        int r0 = mt * 4;
#pragma unroll
        for (int p = 0; p < 2; p++) {
            int ra = r0 + 2 * p, rb = ra + 1;
            float sw0 = aswv[ra], sw1 = aswv[rb];
#pragma unroll
            for (int c = 0; c < 3; c++) {
                float lo, hi;
                unpack2(acc[p][c], lo, hi);
                if (c < 2) {
                    int j = jt + 32 * c;
                    float bb = (c == 0) ? be0 : be1;
                    float y0 = silu_f(lo + bb) * sw0;
                    float y1 = silu_f(hi + bb) * sw1;
                    atomicAdd(&g_reduced[(size_t)ijav[ra] * EDIM + j], y0);
                    atomicAdd(&g_reduced[(size_t)ijav[rb] * EDIM + j], y1);
                } else {
                    float y0 = silu_f(lo + ba);
                    float y1 = silu_f(hi + ba);
                    size_t o0 = (size_t)(a0 + ra) * ADIM + jt;
                    size_t o1 = (size_t)(a0 + rb) * ADIM + jt;
                    out_angle[o0] = angle_ebd[o0] + ar * y0;
                    out_angle[o1] = angle_ebd[o1] + ar * y1;
                }
            }
        }
    }
}

// ---------------- edge angle message GEMM ----------------
__global__ __launch_bounds__(256) void k_edge_msg(const float* __restrict__ W2,
                                                  const float* __restrict__ b2,
                                                  const float* __restrict__ e_res1,
                                                  float* __restrict__ out_edge) {
    __shared__ float Ws[64 * 64];
    __shared__ float At[64 * 68];
    int tid = threadIdx.x;
    int jt = tid & 31, mt = tid >> 5;
    int e0 = blockIdx.x * 64;
    for (int idx = tid; idx < 64 * 64; idx += 256) Ws[idx] = W2[idx];
    for (int idx = tid; idx < 64 * 64; idx += 256) {
        int m = idx >> 6, k = idx & 63;
        At[k * 68 + m] = g_reduced[(size_t)(e0 + m) * EDIM + k];
    }
    __syncthreads();
    float acc[8][2];
#pragma unroll
    for (int i = 0; i < 8; i++) { acc[i][0] = 0.f; acc[i][1] = 0.f; }
#pragma unroll 4
    for (int k = 0; k < 64; k++) {
        float4 A0 = *reinterpret_cast<const float4*>(&At[k * 68 + mt * 8]);
        float4 A1 = *reinterpret_cast<const float4*>(&At[k * 68 + mt * 8 + 4]);
        float am[8] = {A0.x, A0.y, A0.z, A0.w, A1.x, A1.y, A1.z, A1.w};
        float w0 = Ws[k * 64 + jt];
        float w1 = Ws[k * 64 + jt + 32];
#pragma unroll
        for (int i = 0; i < 8; i++) {
            acc[i][0] += am[i] * w0;
            acc[i][1] += am[i] * w1;
        }
    }
#pragma unroll
    for (int i = 0; i < 8; i++) {
        int e = e0 + mt * 8 + i;
#pragma unroll
        for (int q = 0; q < 2; q++) {
            int j = jt + 32 * q;
            float y = silu_f(acc[i][q] + b2[j]);
            out_edge[(size_t)e * EDIM + j] += e_res1[j] * y;
        }
    }
}

// ---------------- launch ----------------
extern "C" void kernel_launch(void* const* d_in, const int* in_sizes, int n_in,
                              void* d_out, int out_size) {
    const float* node_ext   = (const float*)d_in[0];
    const float* edge_ebd   = (const float*)d_in[1];
    const float* h2         = (const float*)d_in[2];
    const float* angle_ebd  = (const float*)d_in[3];
    const float* sw         = (const float*)d_in[6];
    const float* a_sw       = (const float*)d_in[9];
    const int*   edge_index = (const int*)d_in[10];
    const int*   angle_index= (const int*)d_in[11];
    const float* W_node_self = (const float*)d_in[12];
    const float* b_node_self = (const float*)d_in[13];
    const float* W_node_sym  = (const float*)d_in[14];
    const float* b_node_sym  = (const float*)d_in[15];
    const float* W_node_edge = (const float*)d_in[16];
    const float* b_node_edge = (const float*)d_in[17];
    const float* W_edge_self = (const float*)d_in[18];
    const float* b_edge_self = (const float*)d_in[19];
    const float* W_edge_angle1 = (const float*)d_in[20];
    const float* b_edge_angle1 = (const float*)d_in[21];
    const float* W_edge_angle2 = (const float*)d_in[22];
    const float* b_edge_angle2 = (const float*)d_in[23];
    const float* W_angle_self  = (const float*)d_in[24];
    const float* b_angle_self  = (const float*)d_in[25];
    const float* n_res0 = (const float*)d_in[26];
    const float* n_res1 = (const float*)d_in[27];
    const float* n_res2 = (const float*)d_in[28];
    const float* e_res0 = (const float*)d_in[29];
    const float* e_res1 = (const float*)d_in[30];
    const float* a_res0 = (const float*)d_in[31];

    float* out = (float*)d_out;
    float* out_node  = out;
    float* out_edge  = out + (size_t)NLOC * NDIM;
    float* out_angle = out_edge + (size_t)NEDGE * EDIM;

    const int* n2e = edge_index;
    const int* n_ext2e = edge_index + NEDGE;

    cudaFuncSetAttribute((const void*)k_node_self,
                         cudaFuncAttributeMaxDynamicSharedMemorySize, 66048);
    cudaFuncSetAttribute((const void*)k_edge,
                         cudaFuncAttributeMaxDynamicSharedMemorySize, 201728);
    cudaFuncSetAttribute((const void*)k_angle,
                         cudaFuncAttributeMaxDynamicSharedMemorySize, 190976);

    k_zero<<<4096, 256>>>();
    k_count<<<NEDGE / 256, 256>>>(n2e);
    k_scan<<<1, 1024>>>();
    k_scatter<<<NEDGE / 256, 256>>>(n2e);
    k_node_self<<<256, 128, 66048>>>(node_ext, W_node_self, b_node_self, n_res0, out_node);
    k_sym<<<NLOC, 192>>>(edge_ebd, node_ext, h2, sw, n_ext2e);
    k_symmm<<<NLOC / 64, 256>>>(W_node_sym, b_node_sym, n_res1, out_node);
    k_base<<<NLOC / 64, 256>>>(node_ext, W_node_edge, W_edge_self, b_node_edge, b_edge_self);
    k_edge<<<444, 512, 201728>>>(node_ext, edge_ebd, sw, n_ext2e,
                                 W_node_edge, W_edge_self, e_res0, out_edge);
    k_node_finish<<<NLOC * NDIM / 256, 256>>>(n_res2, out_node);
    k_angle<<<444, 512, 190976>>>(angle_ebd, node_ext, edge_ebd, angle_index, a_sw,
                                  W_edge_angle1, b_edge_angle1,
                                  W_angle_self, b_angle_self, a_res0, out_angle);
    k_edge_msg<<<NEDGE / 64, 256>>>(W_edge_angle2, b_edge_angle2, e_res1, out_edge);
}

// round 6
// speedup vs baseline: 2.6040x; 1.2570x over previous
#include <cuda_runtime.h>
#include <cstdint>
#include <cstddef>

#define NLOC   4096
#define NALL   6144
#define NDIM   128
#define EDIM   64
#define ADIM   32
#define NEDGE  262144
#define NANGLE 409600
#define INV_DYN_E 0.15625f            // 1/6.4
#define SYM_SCALE 0.0520833333333f    // (1/6.4)/3

// ---------------- device scratch ----------------
__device__ float g_sym[(size_t)NLOC * 768];
__device__ float g_base[(size_t)NLOC * 192];
__device__ float g_nbase[(size_t)NLOC * 96];
__device__ float g_reduced[(size_t)NEDGE * EDIM];
__device__ float g_msg[(size_t)NLOC * NDIM];
__device__ int   g_ecnt[NLOC];
__device__ int   g_eoff[NLOC + 1];
__device__ int   g_ecur[NLOC];
__device__ int   g_eids[NEDGE];
__device__ int   g_enode[NEDGE];

// ---------------- helpers ----------------
__device__ __forceinline__ float silu_f(float x) { return x / (1.0f + __expf(-x)); }

__device__ __forceinline__ unsigned long long pack2(float w) {
    unsigned long long r;
    unsigned int u = __float_as_uint(w);
    asm("mov.b64 %0, {%1,%1};" : "=l"(r) : "r"(u));
    return r;
}
__device__ __forceinline__ void ffma2(unsigned long long& d, unsigned long long a,
                                      unsigned long long b) {
    asm("fma.rn.f32x2 %0, %1, %2, %0;" : "+l"(d) : "l"(a), "l"(b));
}
__device__ __forceinline__ void unpack2(unsigned long long v, float& lo, float& hi) {
    unsigned int l, h;
    asm("mov.b64 {%0,%1}, %2;" : "=r"(l), "=r"(h) : "l"(v));
    lo = __uint_as_float(l);
    hi = __uint_as_float(h);
}

// ---------------- zero scratch ----------------
__global__ void k_zero() {
    size_t i0 = (size_t)blockIdx.x * blockDim.x + threadIdx.x;
    size_t stride = (size_t)gridDim.x * blockDim.x;
    float4* r = reinterpret_cast<float4*>(g_reduced);
    size_t n4 = (size_t)NEDGE * EDIM / 4;
    for (size_t i = i0; i < n4; i += stride) r[i] = make_float4(0.f, 0.f, 0.f, 0.f);
    float4* m = reinterpret_cast<float4*>(g_msg);
    size_t m4 = (size_t)NLOC * NDIM / 4;
    for (size_t i = i0; i < m4; i += stride) m[i] = make_float4(0.f, 0.f, 0.f, 0.f);
    if (i0 < NLOC) g_ecnt[i0] = 0;
}

// ---------------- CSR build ----------------
__global__ void k_count(const int* __restrict__ n2e) {
    int e = blockIdx.x * blockDim.x + threadIdx.x;
    if (e < NEDGE) atomicAdd(&g_ecnt[n2e[e]], 1);
}

__global__ void k_scan() {
    __shared__ int sh[1024];
    int t = threadIdx.x;
    int c[4];
#pragma unroll
    for (int i = 0; i < 4; i++) c[i] = g_ecnt[t * 4 + i];
    int tot = c[0] + c[1] + c[2] + c[3];
    sh[t] = tot;
    __syncthreads();
    for (int st = 1; st < 1024; st <<= 1) {
        int add = (t >= st) ? sh[t - st] : 0;
        __syncthreads();
        sh[t] += add;
        __syncthreads();
    }
    int run = sh[t] - tot;
#pragma unroll
    for (int i = 0; i < 4; i++) {
        g_eoff[t * 4 + i] = run;
        g_ecur[t * 4 + i] = run;
        run += c[i];
    }
    if (t == 1023) g_eoff[NLOC] = run;
}

__global__ void k_scatter(const int* __restrict__ n2e) {
    int e = blockIdx.x * blockDim.x + threadIdx.x;
    if (e < NEDGE) {
        int n = n2e[e];
        int pos = atomicAdd(&g_ecur[n], 1);
        g_eids[pos] = e;
        g_enode[pos] = n;
    }
}

// ---------------- node_self ----------------
__global__ void k_node_self(const float* __restrict__ node_ext,
                            const float* __restrict__ W, const float* __restrict__ b,
                            const float* __restrict__ n_res0, float* __restrict__ out_node) {
    extern __shared__ float sm[];
    float* Ws = sm;
    float* xs = sm + 128 * 128;
    int tid = threadIdx.x;
    for (int idx = tid; idx < 128 * 128; idx += 128) Ws[idx] = W[idx];
    __syncthreads();
    for (int n = blockIdx.x; n < NLOC; n += gridDim.x) {
        xs[tid] = node_ext[(size_t)n * NDIM + tid];
        __syncthreads();
        float acc = b[tid];
#pragma unroll 8
        for (int k = 0; k < 128; k++) acc += xs[k] * Ws[k * 128 + tid];
        float y = silu_f(acc);
        out_node[(size_t)n * NDIM + tid] = node_ext[(size_t)n * NDIM + tid] + n_res0[tid] * y;
        __syncthreads();
    }
}

// ---------------- sym op ----------------
__global__ void k_sym(const float* __restrict__ edge_ebd, const float* __restrict__ node_ext,
                      const float* __restrict__ h2, const float* __restrict__ sw,
                      const int* __restrict__ n_ext2e) {
    __shared__ float S0[192], S1[192], S2[192];
    __shared__ float symv[768];
    int n = blockIdx.x;
    int t = threadIdx.x;
    int beg = g_eoff[n], end = g_eoff[n + 1];
    float a0 = 0.f, a1 = 0.f, a2 = 0.f;
    for (int i = beg; i < end; i++) {
        int e = g_eids[i];
        float swv = sw[e];
        float h0 = h2[e * 3 + 0] * swv;
        float h1 = h2[e * 3 + 1] * swv;
        float hh = h2[e * 3 + 2] * swv;
        float val = (t < 64) ? edge_ebd[(size_t)e * EDIM + t]
                             : node_ext[(size_t)n_ext2e[e] * NDIM + (t - 64)];
        a0 += h0 * val;
        a1 += h1 * val;
        a2 += hh * val;
    }
    S0[t] = a0; S1[t] = a1; S2[t] = a2;
    __syncthreads();
    if (t < 64) {
#pragma unroll
        for (int a = 0; a < 4; a++)
            symv[a * 64 + t] = SYM_SCALE * (S0[a] * S0[t] + S1[a] * S1[t] + S2[a] * S2[t]);
    } else {
        int dn = t - 64;
#pragma unroll
        for (int a = 0; a < 4; a++)
            symv[256 + a * 128 + dn] =
                SYM_SCALE * (S0[64 + a] * S0[t] + S1[64 + a] * S1[t] + S2[64 + a] * S2[t]);
    }
    __syncthreads();
    for (int idx = t; idx < 768; idx += 192) g_sym[(size_t)n * 768 + idx] = symv[idx];
}

// ---------------- node_sym GEMM ----------------
__global__ __launch_bounds__(256) void k_symmm(const float* __restrict__ W,
                                               const float* __restrict__ b,
                                               const float* __restrict__ n_res1,
                                               float* __restrict__ out_node) {
    __shared__ float Wt[32 * 128];
    __shared__ float At[32 * 72];
    int tid = threadIdx.x;
    int jt = tid & 31, mt = tid >> 5;
    int n0 = blockIdx.x * 64;
    float acc[8][4];
#pragma unroll
    for (int i = 0; i < 8; i++)
#pragma unroll
        for (int q = 0; q < 4; q++) acc[i][q] = 0.f;
    for (int kt = 0; kt < 768; kt += 32) {
        for (int idx = tid; idx < 32 * 128; idx += 256)
            Wt[idx] = W[(size_t)(kt + idx / 128) * 128 + (idx % 128)];
        for (int idx = tid; idx < 32 * 64; idx += 256) {
            int m = idx / 32, k = idx % 32;
            At[k * 72 + m] = g_sym[(size_t)(n0 + m) * 768 + kt + k];
        }
        __syncthreads();
#pragma unroll 4
        for (int k = 0; k < 32; k++) {
            float4 A0 = *reinterpret_cast<const float4*>(&At[k * 72 + mt * 8]);
            float4 A1 = *reinterpret_cast<const float4*>(&At[k * 72 + mt * 8 + 4]);
            float am[8] = {A0.x, A0.y, A0.z, A0.w, A1.x, A1.y, A1.z, A1.w};
            float4 wv = *reinterpret_cast<const float4*>(&Wt[k * 128 + jt * 4]);
            float wq[4] = {wv.x, wv.y, wv.z, wv.w};
#pragma unroll
            for (int i = 0; i < 8; i++)
#pragma unroll
                for (int q = 0; q < 4; q++) acc[i][q] += am[i] * wq[q];
        }
        __syncthreads();
    }
#pragma unroll
    for (int i = 0; i < 8; i++) {
        int n = n0 + mt * 8 + i;
#pragma unroll
        for (int q = 0; q < 4; q++) {
            int j = jt * 4 + q;
            float y = silu_f(acc[i][q] + b[j]);
            out_node[(size_t)n * 128 + j] += n_res1[j] * y;
        }
    }
}

// ---------------- base precompute (edge kernel, 192 cols) ----------------
__global__ __launch_bounds__(256) void k_base(const float* __restrict__ node_ext,
                                              const float* __restrict__ W_ne,
                                              const float* __restrict__ W_es,
                                              const float* __restrict__ b_ne,
                                              const float* __restrict__ b_es) {
    __shared__ float Wt[32 * 192];
    __shared__ float At[32 * 72];
    int tid = threadIdx.x;
    int jt = tid & 31, mt = tid >> 5;
    int n0 = blockIdx.x * 64;
    float acc[8][6];
#pragma unroll
    for (int i = 0; i < 8; i++)
#pragma unroll
        for (int c = 0; c < 6; c++) acc[i][c] = 0.f;
    for (int kt = 0; kt < 128; kt += 32) {
        for (int idx = tid; idx < 32 * 192; idx += 256) {
            int k = idx / 192, j = idx % 192;
            int row = kt + k;
            Wt[idx] = (j < 128) ? W_ne[(size_t)row * 128 + j] : W_es[(size_t)row * 64 + (j - 128)];
        }
        for (int idx = tid; idx < 32 * 64; idx += 256) {
            int m = idx / 32, k = idx % 32;
            At[k * 72 + m] = node_ext[(size_t)(n0 + m) * NDIM + kt + k];
        }
        __syncthreads();
#pragma unroll 2
        for (int k = 0; k < 32; k++) {
            float4 A0 = *reinterpret_cast<const float4*>(&At[k * 72 + mt * 8]);
            float4 A1 = *reinterpret_cast<const float4*>(&At[k * 72 + mt * 8 + 4]);
            float am[8] = {A0.x, A0.y, A0.z, A0.w, A1.x, A1.y, A1.z, A1.w};
#pragma unroll
            for (int c = 0; c < 6; c++) {
                float w = Wt[k * 192 + jt + 32 * c];
#pragma unroll
                for (int i = 0; i < 8; i++) acc[i][c] += am[i] * w;
            }
        }
        __syncthreads();
    }
#pragma unroll
    for (int i = 0; i < 8; i++) {
        int n = n0 + mt * 8 + i;
#pragma unroll
        for (int c = 0; c < 6; c++) {
            int j = jt + 32 * c;
            float bb = (j < 128) ? b_ne[j] : b_es[j - 128];
            g_base[(size_t)n * 192 + j] = acc[i][c] + bb;
        }
    }
}

// ---------------- nbase precompute (angle kernel, 96 cols) ----------------
// g_nbase[n][j] = bias_j + sum_k node[n][k] * W(32+k, j)  (W = [W_ea1 | W_as])
__global__ __launch_bounds__(256) void k_nbase(const float* __restrict__ node_ext,
                                               const float* __restrict__ W_ea1,
                                               const float* __restrict__ W_as,
                                               const float* __restrict__ b_ea1,
                                               const float* __restrict__ b_as) {
    __shared__ float Wt[32 * 96];
    __shared__ float At[32 * 72];
    int tid = threadIdx.x;
    int jt = tid & 31, mt = tid >> 5;
    int n0 = blockIdx.x * 64;
    float acc[8][3];
#pragma unroll
    for (int i = 0; i < 8; i++)
#pragma unroll
        for (int c = 0; c < 3; c++) acc[i][c] = 0.f;
    for (int kt = 0; kt < 128; kt += 32) {
        for (int idx = tid; idx < 32 * 96; idx += 256) {
            int k = idx / 96, j = idx % 96;
            int row = 32 + kt + k;
            Wt[idx] = (j < 64) ? W_ea1[(size_t)row * 64 + j] : W_as[(size_t)row * 32 + (j - 64)];
        }
        for (int idx = tid; idx < 32 * 64; idx += 256) {
            int m = idx / 32, k = idx % 32;
            At[k * 72 + m] = node_ext[(size_t)(n0 + m) * NDIM + kt + k];
        }
        __syncthreads();
#pragma unroll 2
        for (int k = 0; k < 32; k++) {
            float4 A0 = *reinterpret_cast<const float4*>(&At[k * 72 + mt * 8]);
            float4 A1 = *reinterpret_cast<const float4*>(&At[k * 72 + mt * 8 + 4]);
            float am[8] = {A0.x, A0.y, A0.z, A0.w, A1.x, A1.y, A1.z, A1.w};
#pragma unroll
            for (int c = 0; c < 3; c++) {
                float w = Wt[k * 96 + jt + 32 * c];
#pragma unroll
                for (int i = 0; i < 8; i++) acc[i][c] += am[i] * w;
            }
        }
        __syncthreads();
    }
#pragma unroll
    for (int i = 0; i < 8; i++) {
        int n = n0 + mt * 8 + i;
#pragma unroll
        for (int c = 0; c < 3; c++) {
            int j = jt + 32 * c;
            float bb = (j < 64) ? b_ea1[j] : b_as[j - 64];
            g_nbase[(size_t)n * 96 + j] = acc[i][c] + bb;
        }
    }
}

// ---------------- main edge GEMM (f32x2, persistent, 512 threads) ----------------
__global__ __launch_bounds__(512) void k_edge(
    const float* __restrict__ node_ext, const float* __restrict__ edge_ebd,
    const float* __restrict__ sw, const int* __restrict__ n_ext2e,
    const float* __restrict__ W_ne, const float* __restrict__ W_es,
    const float* __restrict__ e_res0, float* __restrict__ out_edge) {
    extern __shared__ float smem[];
    float* Ws = smem;                     // 192*192
    float* At = Ws + 192 * 192;           // 192*68
    int* eidv = (int*)(At + 192 * 68);    // 64
    int* nodev = eidv + 64;               // 64
    float* sws = (float*)(nodev + 64);    // 64

    int tid = threadIdx.x;
    int jt = tid & 31, mt = tid >> 5;
    int mfill = tid & 63;
    int seg = tid >> 6;

    for (int idx = tid; idx < 192 * 192; idx += 512) {
        int k = idx / 192, j = idx % 192;
        Ws[idx] = (j < 128) ? W_ne[(size_t)(128 + k) * 128 + j]
                            : W_es[(size_t)(128 + k) * 64 + (j - 128)];
    }
    float er0 = e_res0[jt], er1 = e_res0[jt + 32];

    for (int ch = blockIdx.x; ch < NEDGE / 64; ch += gridDim.x) {
        int c0 = ch * 64;
        __syncthreads();
        if (tid < 64) {
            int e = g_eids[c0 + tid];
            eidv[tid] = e;
            nodev[tid] = g_enode[c0 + tid];
            sws[tid] = sw[e];
        }
        {
            int e = __ldg(&g_eids[c0 + mfill]);
            int nd = __ldg(&n_ext2e[e]);
            const float4* nrow = (const float4*)(node_ext + (size_t)nd * NDIM);
            const float4* erow = (const float4*)(edge_ebd + (size_t)e * EDIM);
#pragma unroll
            for (int q = 0; q < 6; q++) {
                int kk = seg * 24 + q * 4;
                float4 v = (kk < 128) ? nrow[kk >> 2] : erow[(kk - 128) >> 2];
                At[(kk + 0) * 68 + mfill] = v.x;
                At[(kk + 1) * 68 + mfill] = v.y;
                At[(kk + 2) * 68 + mfill] = v.z;
                At[(kk + 3) * 68 + mfill] = v.w;
            }
        }
        __syncthreads();

        unsigned long long acc[2][6];
#pragma unroll
        for (int p = 0; p < 2; p++)
#pragma unroll
            for (int c = 0; c < 6; c++) acc[p][c] = 0ULL;

#pragma unroll 2
        for (int k = 0; k < 192; k++) {
            ulonglong2 A = *reinterpret_cast<const ulonglong2*>(&At[k * 68 + mt * 4]);
            const float* wr = &Ws[k * 192 + jt];
#pragma unroll
            for (int c = 0; c < 6; c++) {
                unsigned long long ww = pack2(wr[32 * c]);
                ffma2(acc[0][c], A.x, ww);
                ffma2(acc[1][c], A.y, ww);
            }
        }

        int r0 = mt * 4;
#pragma unroll
        for (int c = 4; c < 6; c++) {
            int j = jt + 32 * c;
            int col = j - 128;
            float er = (c == 4) ? er0 : er1;
#pragma unroll
            for (int p = 0; p < 2; p++) {
                float lo, hi;
                unpack2(acc[p][c], lo, hi);
                int ra = r0 + 2 * p, rb = ra + 1;
                {
                    float bv = g_base[(size_t)nodev[ra] * 192 + j];
                    float y = silu_f(lo + bv);
                    size_t off = (size_t)eidv[ra] * EDIM + col;
                    out_edge[off] = edge_ebd[off] + er * y;
                }
                {
                    float bv = g_base[(size_t)nodev[rb] * 192 + j];
                    float y = silu_f(hi + bv);
                    size_t off = (size_t)eidv[rb] * EDIM + col;
                    out_edge[off] = edge_ebd[off] + er * y;
                }
            }
        }
#pragma unroll
        for (int c = 0; c < 4; c++) {
            int j = jt + 32 * c;
            int cur = nodev[r0];
            float s = 0.f;
#pragma unroll
            for (int p = 0; p < 2; p++) {
                float lo, hi;
                unpack2(acc[p][c], lo, hi);
                float v[2] = {lo, hi};
#pragma unroll
                for (int h = 0; h < 2; h++) {
                    int r = r0 + 2 * p + h;
                    int nd = nodev[r];
                    float y = silu_f(v[h] + g_base[(size_t)nd * 192 + j]);
                    float contrib = y * sws[r];
                    if (nd != cur) {
                        atomicAdd(&g_msg[(size_t)cur * NDIM + j], s);
                        s = 0.f;
                        cur = nd;
                    }
                    s += contrib;
                }
            }
            atomicAdd(&g_msg[(size_t)cur * NDIM + j], s);
        }
    }
}

__global__ void k_node_finish(const float* __restrict__ n_res2, float* __restrict__ out_node) {
    int i = blockIdx.x * blockDim.x + threadIdx.x;
    if (i < NLOC * NDIM) {
        int j = i & (NDIM - 1);
        out_node[i] += n_res2[j] * g_msg[i] * INV_DYN_E;
    }
}

// ---------------- angle GEMM: K=160 via g_nbase, persistent, 512 threads ----------------
// A = [angle(32) | edge_ik(64) | edge_ij(64)], W rows {0..31,160..223,224..287}, N=96.
__global__ __launch_bounds__(512, 2) void k_angle(
    const float* __restrict__ angle_ebd, const float* __restrict__ edge_ebd,
    const int* __restrict__ ai, const float* __restrict__ a_sw,
    const float* __restrict__ W_ea1, const float* __restrict__ W_as,
    const float* __restrict__ a_res0, float* __restrict__ out_angle) {
    extern __shared__ float smem[];
    float* Wa = smem;                    // 160*96 = 61440 B
    float* At = Wa + 160 * 96;           // 160*68 = 43520 B
    int* nav = (int*)(At + 160 * 68);    // 64
    int* ijav = nav + 64;                // 64
    float* aswv = (float*)(ijav + 64);   // 64

    int tid = threadIdx.x;
    int jt = tid & 31, mt = tid >> 5;
    int mfill = tid & 63;
    int seg = tid >> 6;  // 0..7, cols seg*20..+20

    const int* n2a = ai;
    const int* eij = ai + NANGLE;
    const int* eik = ai + 2 * NANGLE;

    for (int idx = tid; idx < 160 * 96; idx += 512) {
        int k = idx / 96, j = idx % 96;
        int srck = (k < 32) ? k : ((k < 96) ? 160 + (k - 32) : 224 + (k - 96));
        Wa[idx] = (j < 64) ? W_ea1[(size_t)srck * 64 + j] : W_as[(size_t)srck * 32 + (j - 64)];
    }
    float ar = a_res0[jt];

    for (int t = blockIdx.x; t < NANGLE / 64; t += gridDim.x) {
        int a0 = t * 64;
        __syncthreads();
        if (tid < 64) {
            nav[tid] = n2a[a0 + tid];
            ijav[tid] = eij[a0 + tid];
            aswv[tid] = a_sw[a0 + tid];
        }
        {
            int a = a0 + mfill;
            int ek = __ldg(&eik[a]);
            int ej = __ldg(&eij[a]);
            const float4* arow = (const float4*)(angle_ebd + (size_t)a * ADIM);
            const float4* krow = (const float4*)(edge_ebd + (size_t)ek * EDIM);
            const float4* jrow = (const float4*)(edge_ebd + (size_t)ej * EDIM);
#pragma unroll
            for (int q = 0; q < 5; q++) {
                int kk = seg * 20 + q * 4;
                float4 v = (kk < 32) ? arow[kk >> 2]
                         : (kk < 96) ? krow[(kk - 32) >> 2]
                                     : jrow[(kk - 96) >> 2];
                At[(kk + 0) * 68 + mfill] = v.x;
                At[(kk + 1) * 68 + mfill] = v.y;
                At[(kk + 2) * 68 + mfill] = v.z;
                At[(kk + 3) * 68 + mfill] = v.w;
            }
        }
        __syncthreads();

        unsigned long long acc[2][3];
#pragma unroll
        for (int p = 0; p < 2; p++)
#pragma unroll
            for (int c = 0; c < 3; c++) acc[p][c] = 0ULL;

#pragma unroll 4
        for (int k = 0; k < 160; k++) {
            ulonglong2 A = *reinterpret_cast<const ulonglong2*>(&At[k * 68 + mt * 4]);
            const float* wr = &Wa[k * 96 + jt];
#pragma unroll
            for (int c = 0; c < 3; c++) {
                unsigned long long ww = pack2(wr[32 * c]);
                ffma2(acc[0][c], A.x, ww);
                ffma2(acc[1][c], A.y, ww);
            }
        }

        int r0 = mt * 4;
#pragma unroll
        for (int p = 0; p < 2; p++) {
            int ra = r0 + 2 * p, rb = ra + 1;
            int na_a = nav[ra], na_b = nav[rb];
            float sw0 = aswv[ra], sw1 = aswv[rb];
#pragma unroll
            for (int c = 0; c < 3; c++) {
                float lo, hi;
                unpack2(acc[p][c], lo, hi);
                int j = jt + 32 * c;
                float nb0 = g_nbase[(size_t)na_a * 96 + j];
                float nb1 = g_nbase[(size_t)na_b * 96 + j];
                if (c < 2) {
                    float y0 = silu_f(lo + nb0) * sw0;
                    float y1 = silu_f(hi + nb1) * sw1;
                    atomicAdd(&g_reduced[(size_t)ijav[ra] * EDIM + j], y0);
                    atomicAdd(&g_reduced[(size_t)ijav[rb] * EDIM + j], y1);
                } else {
                    float y0 = silu_f(lo + nb0);
                    float y1 = silu_f(hi + nb1);
                    size_t o0 = (size_t)(a0 + ra) * ADIM + jt;
                    size_t o1 = (size_t)(a0 + rb) * ADIM + jt;
                    out_angle[o0] = angle_ebd[o0] + ar * y0;
                    out_angle[o1] = angle_ebd[o1] + ar * y1;
                }
            }
        }
    }
}

// ---------------- edge angle message GEMM (f32x2) ----------------
__global__ __launch_bounds__(256) void k_edge_msg(const float* __restrict__ W2,
                                                  const float* __restrict__ b2,
                                                  const float* __restrict__ e_res1,
                                                  float* __restrict__ out_edge) {
    __shared__ float Ws[64 * 64];
    __shared__ float At[64 * 68];
    int tid = threadIdx.x;
    int jt = tid & 31, mt = tid >> 5;
    int e0 = blockIdx.x * 64;
    for (int idx = tid; idx < 64 * 64; idx += 256) Ws[idx] = W2[idx];
    for (int idx = tid; idx < 64 * 64; idx += 256) {
        int m = idx >> 6, k = idx & 63;
        At[k * 68 + m] = g_reduced[(size_t)(e0 + m) * EDIM + k];
    }
    __syncthreads();
    unsigned long long acc[4][2];
#pragma unroll
    for (int i = 0; i < 4; i++) { acc[i][0] = 0ULL; acc[i][1] = 0ULL; }
#pragma unroll 4
    for (int k = 0; k < 64; k++) {
        ulonglong2 A0 = *reinterpret_cast<const ulonglong2*>(&At[k * 68 + mt * 8]);
        ulonglong2 A1 = *reinterpret_cast<const ulonglong2*>(&At[k * 68 + mt * 8 + 4]);
        unsigned long long w0 = pack2(Ws[k * 64 + jt]);
        unsigned long long w1 = pack2(Ws[k * 64 + jt + 32]);
        ffma2(acc[0][0], A0.x, w0); ffma2(acc[0][1], A0.x, w1);
        ffma2(acc[1][0], A0.y, w0); ffma2(acc[1][1], A0.y, w1);
        ffma2(acc[2][0], A1.x, w0); ffma2(acc[2][1], A1.x, w1);
        ffma2(acc[3][0], A1.y, w0); ffma2(acc[3][1], A1.y, w1);
    }
    float bb0 = b2[jt], bb1 = b2[jt + 32];
    float er0 = e_res1[jt], er1 = e_res1[jt + 32];
#pragma unroll
    for (int i = 0; i < 4; i++) {
#pragma unroll
        for (int q = 0; q < 2; q++) {
            float lo, hi;
            unpack2(acc[i][q], lo, hi);
            int j = (q == 0) ? jt : jt + 32;
            float bb = (q == 0) ? bb0 : bb1;
            float er = (q == 0) ? er0 : er1;
            int ea = e0 + mt * 8 + 2 * i;
            int eb = ea + 1;
            out_edge[(size_t)ea * EDIM + j] += er * silu_f(lo + bb);
            out_edge[(size_t)eb * EDIM + j] += er * silu_f(hi + bb);
        }
    }
}

// ---------------- launch ----------------
extern "C" void kernel_launch(void* const* d_in, const int* in_sizes, int n_in,
                              void* d_out, int out_size) {
    const float* node_ext   = (const float*)d_in[0];
    const float* edge_ebd   = (const float*)d_in[1];
    const float* h2         = (const float*)d_in[2];
    const float* angle_ebd  = (const float*)d_in[3];
    const float* sw         = (const float*)d_in[6];
    const float* a_sw       = (const float*)d_in[9];
    const int*   edge_index = (const int*)d_in[10];
    const int*   angle_index= (const int*)d_in[11];
    const float* W_node_self = (const float*)d_in[12];
    const float* b_node_self = (const float*)d_in[13];
    const float* W_node_sym  = (const float*)d_in[14];
    const float* b_node_sym  = (const float*)d_in[15];
    const float* W_node_edge = (const float*)d_in[16];
    const float* b_node_edge = (const float*)d_in[17];
    const float* W_edge_self = (const float*)d_in[18];
    const float* b_edge_self = (const float*)d_in[19];
    const float* W_edge_angle1 = (const float*)d_in[20];
    const float* b_edge_angle1 = (const float*)d_in[21];
    const float* W_edge_angle2 = (const float*)d_in[22];
    const float* b_edge_angle2 = (const float*)d_in[23];
    const float* W_angle_self  = (const float*)d_in[24];
    const float* b_angle_self  = (const float*)d_in[25];
    const float* n_res0 = (const float*)d_in[26];
    const float* n_res1 = (const float*)d_in[27];
    const float* n_res2 = (const float*)d_in[28];
    const float* e_res0 = (const float*)d_in[29];
    const float* e_res1 = (const float*)d_in[30];
    const float* a_res0 = (const float*)d_in[31];

    float* out = (float*)d_out;
    float* out_node  = out;
    float* out_edge  = out + (size_t)NLOC * NDIM;
    float* out_angle = out_edge + (size_t)NEDGE * EDIM;

    const int* n2e = edge_index;
    const int* n_ext2e = edge_index + NEDGE;

    cudaFuncSetAttribute((const void*)k_node_self,
                         cudaFuncAttributeMaxDynamicSharedMemorySize, 66048);
    cudaFuncSetAttribute((const void*)k_edge,
                         cudaFuncAttributeMaxDynamicSharedMemorySize, 201728);
    cudaFuncSetAttribute((const void*)k_angle,
                         cudaFuncAttributeMaxDynamicSharedMemorySize, 105728);

    k_zero<<<4096, 256>>>();
    k_count<<<NEDGE / 256, 256>>>(n2e);
    k_scan<<<1, 1024>>>();
    k_scatter<<<NEDGE / 256, 256>>>(n2e);
    k_node_self<<<256, 128, 66048>>>(node_ext, W_node_self, b_node_self, n_res0, out_node);
    k_sym<<<NLOC, 192>>>(edge_ebd, node_ext, h2, sw, n_ext2e);
    k_symmm<<<NLOC / 64, 256>>>(W_node_sym, b_node_sym, n_res1, out_node);
    k_base<<<NLOC / 64, 256>>>(node_ext, W_node_edge, W_edge_self, b_node_edge, b_edge_self);
    k_nbase<<<NLOC / 64, 256>>>(node_ext, W_edge_angle1, W_angle_self,
                                b_edge_angle1, b_angle_self);
    k_edge<<<444, 512, 201728>>>(node_ext, edge_ebd, sw, n_ext2e,
                                 W_node_edge, W_edge_self, e_res0, out_edge);
    k_node_finish<<<NLOC * NDIM / 256, 256>>>(n_res2, out_node);
    k_angle<<<592, 512, 105728>>>(angle_ebd, edge_ebd, angle_index, a_sw,
                                  W_edge_angle1, W_angle_self, a_res0, out_angle);
    k_edge_msg<<<NEDGE / 64, 256>>>(W_edge_angle2, b_edge_angle2, e_res1, out_edge);
}

// round 7
// speedup vs baseline: 3.2630x; 1.2531x over previous
#include <cuda_runtime.h>
#include <cuda_bf16.h>
#include <cstdint>
#include <cstddef>

#define NLOC   4096
#define NALL   6144
#define NDIM   128
#define EDIM   64
#define ADIM   32
#define NEDGE  262144
#define NANGLE 409600
#define INV_DYN_E 0.15625f            // 1/6.4
#define SYM_SCALE 0.0520833333333f    // (1/6.4)/3

// ---------------- device scratch ----------------
__device__ float g_sym[(size_t)NLOC * 768];
__device__ float g_base[(size_t)NLOC * 192];
__device__ float g_nbase[(size_t)NLOC * 96];
__device__ float g_reduced[(size_t)NEDGE * EDIM];
__device__ float g_msg[(size_t)NLOC * NDIM];
__device__ int   g_ecnt[NLOC];
__device__ int   g_eoff[NLOC + 1];
__device__ int   g_ecur[NLOC];
__device__ int   g_eids[NEDGE];
__device__ int   g_enode[NEDGE];

// ---------------- helpers ----------------
__device__ __forceinline__ float silu_f(float x) { return x / (1.0f + __expf(-x)); }

__device__ __forceinline__ unsigned long long pack2(float w) {
    unsigned long long r;
    unsigned int u = __float_as_uint(w);
    asm("mov.b64 %0, {%1,%1};" : "=l"(r) : "r"(u));
    return r;
}
__device__ __forceinline__ void ffma2(unsigned long long& d, unsigned long long a,
                                      unsigned long long b) {
    asm("fma.rn.f32x2 %0, %1, %2, %0;" : "+l"(d) : "l"(a), "l"(b));
}
__device__ __forceinline__ void unpack2(unsigned long long v, float& lo, float& hi) {
    unsigned int l, h;
    asm("mov.b64 {%0,%1}, %2;" : "=r"(l), "=r"(h) : "l"(v));
    lo = __uint_as_float(l);
    hi = __uint_as_float(h);
}

__device__ __forceinline__ uint32_t smem_u32(const void* p) {
    uint32_t a;
    asm("{ .reg .u64 t; cvta.to.shared.u64 t, %1; cvt.u32.u64 %0, t; }" : "=r"(a) : "l"(p));
    return a;
}

// ldmatrix x4 (non-transposed)
__device__ __forceinline__ void ldsm4(uint32_t* r, uint32_t addr) {
    asm volatile("ldmatrix.sync.aligned.m8n8.x4.shared.b16 {%0,%1,%2,%3}, [%4];"
                 : "=r"(r[0]), "=r"(r[1]), "=r"(r[2]), "=r"(r[3]) : "r"(addr));
}

// mma m16n8k16 bf16 -> f32
__device__ __forceinline__ void mma_bf16(float* d, const uint32_t* a, const uint32_t* b) {
    asm volatile(
        "mma.sync.aligned.m16n8k16.row.col.f32.bf16.bf16.f32 "
        "{%0,%1,%2,%3}, {%4,%5,%6,%7}, {%8,%9}, {%0,%1,%2,%3};"
        : "+f"(d[0]), "+f"(d[1]), "+f"(d[2]), "+f"(d[3])
        : "r"(a[0]), "r"(a[1]), "r"(a[2]), "r"(a[3]), "r"(b[0]), "r"(b[1]));
}

__device__ __forceinline__ uint32_t bfp(float a, float b) {
    __nv_bfloat162 t = __floats2bfloat162_rn(a, b);
    return *reinterpret_cast<uint32_t*>(&t);
}

// ---------------- zero scratch ----------------
__global__ void k_zero() {
    size_t i0 = (size_t)blockIdx.x * blockDim.x + threadIdx.x;
    size_t stride = (size_t)gridDim.x * blockDim.x;
    float4* r = reinterpret_cast<float4*>(g_reduced);
    size_t n4 = (size_t)NEDGE * EDIM / 4;
    for (size_t i = i0; i < n4; i += stride) r[i] = make_float4(0.f, 0.f, 0.f, 0.f);
    float4* m = reinterpret_cast<float4*>(g_msg);
    size_t m4 = (size_t)NLOC * NDIM / 4;
    for (size_t i = i0; i < m4; i += stride) m[i] = make_float4(0.f, 0.f, 0.f, 0.f);
    if (i0 < NLOC) g_ecnt[i0] = 0;
}

// ---------------- CSR build ----------------
__global__ void k_count(const int* __restrict__ n2e) {
    int e = blockIdx.x * blockDim.x + threadIdx.x;
    if (e < NEDGE) atomicAdd(&g_ecnt[n2e[e]], 1);
}

__global__ void k_scan() {
    __shared__ int sh[1024];
    int t = threadIdx.x;
    int c[4];
#pragma unroll
    for (int i = 0; i < 4; i++) c[i] = g_ecnt[t * 4 + i];
    int tot = c[0] + c[1] + c[2] + c[3];
    sh[t] = tot;
    __syncthreads();
    for (int st = 1; st < 1024; st <<= 1) {
        int add = (t >= st) ? sh[t - st] : 0;
        __syncthreads();
        sh[t] += add;
        __syncthreads();
    }
    int run = sh[t] - tot;
#pragma unroll
    for (int i = 0; i < 4; i++) {
        g_eoff[t * 4 + i] = run;
        g_ecur[t * 4 + i] = run;
        run += c[i];
    }
    if (t == 1023) g_eoff[NLOC] = run;
}

__global__ void k_scatter(const int* __restrict__ n2e) {
    int e = blockIdx.x * blockDim.x + threadIdx.x;
    if (e < NEDGE) {
        int n = n2e[e];
        int pos = atomicAdd(&g_ecur[n], 1);
        g_eids[pos] = e;
        g_enode[pos] = n;
    }
}

// ---------------- sym op ----------------
__global__ void k_sym(const float* __restrict__ edge_ebd, const float* __restrict__ node_ext,
                      const float* __restrict__ h2, const float* __restrict__ sw,
                      const int* __restrict__ n_ext2e) {
    __shared__ float S0[192], S1[192], S2[192];
    __shared__ float symv[768];
    int n = blockIdx.x;
    int t = threadIdx.x;
    int beg = g_eoff[n], end = g_eoff[n + 1];
    float a0 = 0.f, a1 = 0.f, a2 = 0.f;
    for (int i = beg; i < end; i++) {
        int e = g_eids[i];
        float swv = sw[e];
        float h0 = h2[e * 3 + 0] * swv;
        float h1 = h2[e * 3 + 1] * swv;
        float hh = h2[e * 3 + 2] * swv;
        float val = (t < 64) ? edge_ebd[(size_t)e * EDIM + t]
                             : node_ext[(size_t)n_ext2e[e] * NDIM + (t - 64)];
        a0 += h0 * val;
        a1 += h1 * val;
        a2 += hh * val;
    }
    S0[t] = a0; S1[t] = a1; S2[t] = a2;
    __syncthreads();
    if (t < 64) {
#pragma unroll
        for (int a = 0; a < 4; a++)
            symv[a * 64 + t] = SYM_SCALE * (S0[a] * S0[t] + S1[a] * S1[t] + S2[a] * S2[t]);
    } else {
        int dn = t - 64;
#pragma unroll
        for (int a = 0; a < 4; a++)
            symv[256 + a * 128 + dn] =
                SYM_SCALE * (S0[64 + a] * S0[t] + S1[64 + a] * S1[t] + S2[64 + a] * S2[t]);
    }
    __syncthreads();
    for (int idx = t; idx < 768; idx += 192) g_sym[(size_t)n * 768 + idx] = symv[idx];
}

// ---------------- node_sym GEMM fused with node_self ----------------
__global__ __launch_bounds__(256) void k_symmm(
    const float* __restrict__ W_sym, const float* __restrict__ b_sym,
    const float* __restrict__ n_res1,
    const float* __restrict__ W_self, const float* __restrict__ b_self,
    const float* __restrict__ n_res0,
    const float* __restrict__ node_ext, float* __restrict__ out_node) {
    __shared__ float Wt[32 * 128];
    __shared__ float At[32 * 72];
    int tid = threadIdx.x;
    int jt = tid & 31, mt = tid >> 5;
    int n0 = blockIdx.x * 64;
    float acc0[8][4], acc1[8][4];
#pragma unroll
    for (int i = 0; i < 8; i++)
#pragma unroll
        for (int q = 0; q < 4; q++) { acc0[i][q] = 0.f; acc1[i][q] = 0.f; }

    // sym part: K = 768
    for (int kt = 0; kt < 768; kt += 32) {
        for (int idx = tid; idx < 32 * 128; idx += 256)
            Wt[idx] = W_sym[(size_t)(kt + idx / 128) * 128 + (idx % 128)];
        for (int idx = tid; idx < 32 * 64; idx += 256) {
            int m = idx / 32, k = idx % 32;
            At[k * 72 + m] = g_sym[(size_t)(n0 + m) * 768 + kt + k];
        }
        __syncthreads();
#pragma unroll 4
        for (int k = 0; k < 32; k++) {
            float4 A0 = *reinterpret_cast<const float4*>(&At[k * 72 + mt * 8]);
            float4 A1 = *reinterpret_cast<const float4*>(&At[k * 72 + mt * 8 + 4]);
            float am[8] = {A0.x, A0.y, A0.z, A0.w, A1.x, A1.y, A1.z, A1.w};
            float4 wv = *reinterpret_cast<const float4*>(&Wt[k * 128 + jt * 4]);
            float wq[4] = {wv.x, wv.y, wv.z, wv.w};
#pragma unroll
            for (int i = 0; i < 8; i++)
#pragma unroll
                for (int q = 0; q < 4; q++) acc0[i][q] += am[i] * wq[q];
        }
        __syncthreads();
    }
    // self part: K = 128
    for (int kt = 0; kt < 128; kt += 32) {
        for (int idx = tid; idx < 32 * 128; idx += 256)
            Wt[idx] = W_self[(size_t)(kt + idx / 128) * 128 + (idx % 128)];
        for (int idx = tid; idx < 32 * 64; idx += 256) {
            int m = idx / 32, k = idx % 32;
            At[k * 72 + m] = node_ext[(size_t)(n0 + m) * NDIM + kt + k];
        }
        __syncthreads();
#pragma unroll 4
        for (int k = 0; k < 32; k++) {
            float4 A0 = *reinterpret_cast<const float4*>(&At[k * 72 + mt * 8]);
            float4 A1 = *reinterpret_cast<const float4*>(&At[k * 72 + mt * 8 + 4]);
            float am[8] = {A0.x, A0.y, A0.z, A0.w, A1.x, A1.y, A1.z, A1.w};
            float4 wv = *reinterpret_cast<const float4*>(&Wt[k * 128 + jt * 4]);
            float wq[4] = {wv.x, wv.y, wv.z, wv.w};
#pragma unroll
            for (int i = 0; i < 8; i++)
#pragma unroll
                for (int q = 0; q < 4; q++) acc1[i][q] += am[i] * wq[q];
        }
        __syncthreads();
    }
#pragma unroll
    for (int i = 0; i < 8; i++) {
        int n = n0 + mt * 8 + i;
#pragma unroll
        for (int q = 0; q < 4; q++) {
            int j = jt * 4 + q;
            float y1 = silu_f(acc0[i][q] + b_sym[j]);
            float y0 = silu_f(acc1[i][q] + b_self[j]);
            out_node[(size_t)n * 128 + j] =
                node_ext[(size_t)n * NDIM + j] + n_res0[j] * y0 + n_res1[j] * y1;
        }
    }
}

// ---------------- base precompute (edge kernel, 192 cols) ----------------
__global__ __launch_bounds__(256) void k_base(const float* __restrict__ node_ext,
                                              const float* __restrict__ W_ne,
                                              const float* __restrict__ W_es,
                                              const float* __restrict__ b_ne,
                                              const float* __restrict__ b_es) {
    __shared__ float Wt[32 * 192];
    __shared__ float At[32 * 72];
    int tid = threadIdx.x;
    int jt = tid & 31, mt = tid >> 5;
    int n0 = blockIdx.x * 64;
    float acc[8][6];
#pragma unroll
    for (int i = 0; i < 8; i++)
#pragma unroll
        for (int c = 0; c < 6; c++) acc[i][c] = 0.f;
    for (int kt = 0; kt < 128; kt += 32) {
        for (int idx = tid; idx < 32 * 192; idx += 256) {
            int k = idx / 192, j = idx % 192;
            int row = kt + k;
            Wt[idx] = (j < 128) ? W_ne[(size_t)row * 128 + j] : W_es[(size_t)row * 64 + (j - 128)];
        }
        for (int idx = tid; idx < 32 * 64; idx += 256) {
            int m = idx / 32, k = idx % 32;
            At[k * 72 + m] = node_ext[(size_t)(n0 + m) * NDIM + kt + k];
        }
        __syncthreads();
#pragma unroll 2
        for (int k = 0; k < 32; k++) {
            float4 A0 = *reinterpret_cast<const float4*>(&At[k * 72 + mt * 8]);
            float4 A1 = *reinterpret_cast<const float4*>(&At[k * 72 + mt * 8 + 4]);
            float am[8] = {A0.x, A0.y, A0.z, A0.w, A1.x, A1.y, A1.z, A1.w};
#pragma unroll
            for (int c = 0; c < 6; c++) {
                float w = Wt[k * 192 + jt + 32 * c];
#pragma unroll
                for (int i = 0; i < 8; i++) acc[i][c] += am[i] * w;
            }
        }
        __syncthreads();
    }
#pragma unroll
    for (int i = 0; i < 8; i++) {
        int n = n0 + mt * 8 + i;
#pragma unroll
        for (int c = 0; c < 6; c++) {
            int j = jt + 32 * c;
            float bb = (j < 128) ? b_ne[j] : b_es[j - 128];
            g_base[(size_t)n * 192 + j] = acc[i][c] + bb;
        }
    }
}

// ---------------- nbase precompute (angle kernel, 96 cols) ----------------
__global__ __launch_bounds__(256) void k_nbase(const float* __restrict__ node_ext,
                                               const float* __restrict__ W_ea1,
                                               const float* __restrict__ W_as,
                                               const float* __restrict__ b_ea1,
                                               const float* __restrict__ b_as) {
    __shared__ float Wt[32 * 96];
    __shared__ float At[32 * 72];
    int tid = threadIdx.x;
    int jt = tid & 31, mt = tid >> 5;
    int n0 = blockIdx.x * 64;
    float acc[8][3];
#pragma unroll
    for (int i = 0; i < 8; i++)
#pragma unroll
        for (int c = 0; c < 3; c++) acc[i][c] = 0.f;
    for (int kt = 0; kt < 128; kt += 32) {
        for (int idx = tid; idx < 32 * 96; idx += 256) {
            int k = idx / 96, j = idx % 96;
            int row = 32 + kt + k;
            Wt[idx] = (j < 64) ? W_ea1[(size_t)row * 64 + j] : W_as[(size_t)row * 32 + (j - 64)];
        }
        for (int idx = tid; idx < 32 * 64; idx += 256) {
            int m = idx / 32, k = idx % 32;
            At[k * 72 + m] = node_ext[(size_t)(n0 + m) * NDIM + kt + k];
        }
        __syncthreads();
#pragma unroll 2
        for (int k = 0; k < 32; k++) {
            float4 A0 = *reinterpret_cast<const float4*>(&At[k * 72 + mt * 8]);
            float4 A1 = *reinterpret_cast<const float4*>(&At[k * 72 + mt * 8 + 4]);
            float am[8] = {A0.x, A0.y, A0.z, A0.w, A1.x, A1.y, A1.z, A1.w};
#pragma unroll
            for (int c = 0; c < 3; c++) {
                float w = Wt[k * 96 + jt + 32 * c];
#pragma unroll
                for (int i = 0; i < 8; i++) acc[i][c] += am[i] * w;
            }
        }
        __syncthreads();
    }
#pragma unroll
    for (int i = 0; i < 8; i++) {
        int n = n0 + mt * 8 + i;
#pragma unroll
        for (int c = 0; c < 3; c++) {
            int j = jt + 32 * c;
            float bb = (j < 64) ? b_ea1[j] : b_as[j - 64];
            g_nbase[(size_t)n * 96 + j] = acc[i][c] + bb;
        }
    }
}

// ================= edge GEMM via mma.sync bf16 3-term split =================
// M=64 (chunk of CSR-ordered edges), N=192, K=192. Persistent, 512 threads.
// smem layout (halves stride 200 => ldmatrix bank-conflict-free):
//   Wh[192n][200k] bf16, Wl same; Ah[64m][200k], Al same; idx arrays.
#define ET_WH 0
#define ET_WL 76800
#define ET_AH 153600
#define ET_AL 179200
#define ET_IDX 204800
#define ET_SMEM 205568

__global__ __launch_bounds__(512, 1) void k_edge_tc(
    const float* __restrict__ node_ext, const float* __restrict__ edge_ebd,
    const float* __restrict__ sw, const int* __restrict__ n_ext2e,
    const float* __restrict__ W_ne, const float* __restrict__ W_es,
    const float* __restrict__ e_res0, float* __restrict__ out_edge) {
    extern __shared__ char smc[];
    uint32_t sb = smem_u32(smc);
    int tid = threadIdx.x;
    int wid = tid >> 5;
    int lane = tid & 31;
    int wm = wid >> 2;   // 0..3 : rows wm*16
    int wn = wid & 3;    // 0..3 : cols wn*48

    int* eidv = (int*)(smc + ET_IDX);
    int* nodev = eidv + 64;
    float* sws = (float*)(nodev + 64);

    // ---- load weights (rows 128..319 of [W_ne|W_es]) as bf16 hi/lo, layout [n][k] ----
    for (int idx = tid; idx < 192 * 192; idx += 512) {
        int k = idx / 192, j = idx % 192;
        float w = (j < 128) ? W_ne[(size_t)(128 + k) * 128 + j]
                            : W_es[(size_t)(128 + k) * 64 + (j - 128)];
        __nv_bfloat16 h = __float2bfloat16(w);
        float l = w - __bfloat162float(h);
        *reinterpret_cast<__nv_bfloat16*>(smc + ET_WH + (j * 200 + k) * 2) = h;
        *reinterpret_cast<__nv_bfloat16*>(smc + ET_WL + (j * 200 + k) * 2) = __float2bfloat16(l);
    }

    // ldmatrix source addresses
    uint32_t aRow = wm * 16 + (lane & 15);
    uint32_t aColH = (lane >> 4);  // 0/1 -> k-half offset 8
    uint32_t aAddrH = sb + ET_AH + (aRow * 200 + aColH * 8) * 2;
    uint32_t aAddrL = sb + ET_AL + (aRow * 200 + aColH * 8) * 2;
    int nrow = wn * 48 + (lane & 7) + ((lane & 16) ? 8 : 0);
    int khalf = (lane & 8) ? 8 : 0;
    uint32_t bAddrH = sb + ET_WH + (nrow * 200 + khalf) * 2;
    uint32_t bAddrL = sb + ET_WL + (nrow * 200 + khalf) * 2;

    int mfill = tid & 63;   // fill row
    int seg = tid >> 6;     // 0..7 -> k range seg*24..+24

    for (int ch = blockIdx.x; ch < NEDGE / 64; ch += gridDim.x) {
        int c0 = ch * 64;
        __syncthreads();
        if (tid < 64) {
            int e = g_eids[c0 + tid];
            eidv[tid] = e;
            nodev[tid] = g_enode[c0 + tid];
            sws[tid] = sw[e];
        }
        // ---- fill A (bf16 hi/lo): row mfill, cols seg*24..+24 ----
        {
            int e = __ldg(&g_eids[c0 + mfill]);
            int nd = __ldg(&n_ext2e[e]);
            const float4* nrowp = (const float4*)(node_ext + (size_t)nd * NDIM);
            const float4* erowp = (const float4*)(edge_ebd + (size_t)e * EDIM);
            uint32_t rowoff = (uint32_t)mfill * 200;
#pragma unroll
            for (int q = 0; q < 6; q++) {
                int kk = seg * 24 + q * 4;
                float4 v = (kk < 128) ? nrowp[kk >> 2] : erowp[(kk - 128) >> 2];
                __nv_bfloat16 h0 = __float2bfloat16(v.x);
                __nv_bfloat16 h1 = __float2bfloat16(v.y);
                __nv_bfloat16 h2 = __float2bfloat16(v.z);
                __nv_bfloat16 h3 = __float2bfloat16(v.w);
                uint32_t hi01, hi23;
                { __nv_bfloat162 t; t.x = h0; t.y = h1; hi01 = *reinterpret_cast<uint32_t*>(&t); }
                { __nv_bfloat162 t; t.x = h2; t.y = h3; hi23 = *reinterpret_cast<uint32_t*>(&t); }
                uint32_t lo01 = bfp(v.x - __bfloat162float(h0), v.y - __bfloat162float(h1));
                uint32_t lo23 = bfp(v.z - __bfloat162float(h2), v.w - __bfloat162float(h3));
                uint32_t boff = (rowoff + kk) * 2;
                *reinterpret_cast<uint32_t*>(smc + ET_AH + boff) = hi01;
                *reinterpret_cast<uint32_t*>(smc + ET_AH + boff + 4) = hi23;
                *reinterpret_cast<uint32_t*>(smc + ET_AL + boff) = lo01;
                *reinterpret_cast<uint32_t*>(smc + ET_AL + boff + 4) = lo23;
            }
        }
        __syncthreads();

        // ---- mainloop: 12 ksteps, 3-term bf16 split ----
        float d[6][4];
#pragma unroll
        for (int nt = 0; nt < 6; nt++)
#pragma unroll
            for (int q = 0; q < 4; q++) d[nt][q] = 0.f;

#pragma unroll
        for (int s = 0; s < 12; s++) {
            uint32_t ah[4], al[4];
            ldsm4(ah, aAddrH + s * 32);
            ldsm4(al, aAddrL + s * 32);
#pragma unroll
            for (int pr = 0; pr < 3; pr++) {
                uint32_t bh[4], bl[4];
                ldsm4(bh, bAddrH + pr * 16 * 400 + s * 32);
                ldsm4(bl, bAddrL + pr * 16 * 400 + s * 32);
                mma_bf16(d[pr * 2], ah, bh);
                mma_bf16(d[pr * 2], ah, bl);
                mma_bf16(d[pr * 2], al, bh);
                mma_bf16(d[pr * 2 + 1], ah, bh + 2);
                mma_bf16(d[pr * 2 + 1], ah, bl + 2);
                mma_bf16(d[pr * 2 + 1], al, bh + 2);
            }
        }

        // ---- epilogue ----
        int g = lane >> 2, qt = lane & 3;
        int r0 = wm * 16 + g, r1 = r0 + 8;
        int nd0 = nodev[r0], nd1 = nodev[r1];
        float sw0 = sws[r0], sw1 = sws[r1];
        int ee0 = eidv[r0], ee1 = eidv[r1];
        bool samend = (nd0 == nd1);
#pragma unroll
        for (int nt = 0; nt < 6; nt++) {
            int j0 = wn * 48 + nt * 8 + qt * 2;
            float2 b0v = *(const float2*)(g_base + (size_t)nd0 * 192 + j0);
            float2 b1v = *(const float2*)(g_base + (size_t)nd1 * 192 + j0);
            float y00 = silu_f(d[nt][0] + b0v.x);
            float y01 = silu_f(d[nt][1] + b0v.y);
            float y10 = silu_f(d[nt][2] + b1v.x);
            float y11 = silu_f(d[nt][3] + b1v.y);
            if (j0 < 128) {
                float v00 = y00 * sw0, v01 = y01 * sw0;
                float v10 = y10 * sw1, v11 = y11 * sw1;
                if (samend) {
                    atomicAdd(&g_msg[(size_t)nd0 * NDIM + j0], v00 + v10);
                    atomicAdd(&g_msg[(size_t)nd0 * NDIM + j0 + 1], v01 + v11);
                } else {
                    atomicAdd(&g_msg[(size_t)nd0 * NDIM + j0], v00);
                    atomicAdd(&g_msg[(size_t)nd0 * NDIM + j0 + 1], v01);
                    atomicAdd(&g_msg[(size_t)nd1 * NDIM + j0], v10);
                    atomicAdd(&g_msg[(size_t)nd1 * NDIM + j0 + 1], v11);
                }
            } else {
                int col = j0 - 128;
                float2 er = *(const float2*)(e_res0 + col);
                size_t o0 = (size_t)ee0 * EDIM + col;
                size_t o1 = (size_t)ee1 * EDIM + col;
                float2 eb0 = *(const float2*)(edge_ebd + o0);
                float2 eb1 = *(const float2*)(edge_ebd + o1);
                *(float2*)(out_edge + o0) = make_float2(eb0.x + er.x * y00, eb0.y + er.y * y01);
                *(float2*)(out_edge + o1) = make_float2(eb1.x + er.x * y10, eb1.y + er.y * y11);
            }
        }
    }
}

__global__ void k_node_finish(const float* __restrict__ n_res2, float* __restrict__ out_node) {
    int i = blockIdx.x * blockDim.x + threadIdx.x;
    if (i < NLOC * NDIM) {
        int j = i & (NDIM - 1);
        out_node[i] += n_res2[j] * g_msg[i] * INV_DYN_E;
    }
}

// ---------------- angle GEMM: K=160 via g_nbase, f32x2, persistent ----------------
__global__ __launch_bounds__(512, 2) void k_angle(
    const float* __restrict__ angle_ebd, const float* __restrict__ edge_ebd,
    const int* __restrict__ ai, const float* __restrict__ a_sw,
    const float* __restrict__ W_ea1, const float* __restrict__ W_as,
    const float* __restrict__ a_res0, float* __restrict__ out_angle) {
    extern __shared__ float smem[];
    float* Wa = smem;                    // 160*96
    float* At = Wa + 160 * 96;           // 160*68
    int* nav = (int*)(At + 160 * 68);
    int* ijav = nav + 64;
    float* aswv = (float*)(ijav + 64);

    int tid = threadIdx.x;
    int jt = tid & 31, mt = tid >> 5;
    int mfill = tid & 63;
    int seg = tid >> 6;

    const int* n2a = ai;
    const int* eij = ai + NANGLE;
    const int* eik = ai + 2 * NANGLE;

    for (int idx = tid; idx < 160 * 96; idx += 512) {
        int k = idx / 96, j = idx % 96;
        int srck = (k < 32) ? k : ((k < 96) ? 160 + (k - 32) : 224 + (k - 96));
        Wa[idx] = (j < 64) ? W_ea1[(size_t)srck * 64 + j] : W_as[(size_t)srck * 32 + (j - 64)];
    }
    float ar = a_res0[jt];

    for (int t = blockIdx.x; t < NANGLE / 64; t += gridDim.x) {
        int a0 = t * 64;
        __syncthreads();
        if (tid < 64) {
            nav[tid] = n2a[a0 + tid];
            ijav[tid] = eij[a0 + tid];
            aswv[tid] = a_sw[a0 + tid];
        }
        {
            int a = a0 + mfill;
            int ek = __ldg(&eik[a]);
            int ej = __ldg(&eij[a]);
            const float4* arow = (const float4*)(angle_ebd + (size_t)a * ADIM);
            const float4* krow = (const float4*)(edge_ebd + (size_t)ek * EDIM);
            const float4* jrow = (const float4*)(edge_ebd + (size_t)ej * EDIM);
#pragma unroll
            for (int q = 0; q < 5; q++) {
                int kk = seg * 20 + q * 4;
                float4 v = (kk < 32) ? arow[kk >> 2]
                         : (kk < 96) ? krow[(kk - 32) >> 2]
                                     : jrow[(kk - 96) >> 2];
                At[(kk + 0) * 68 + mfill] = v.x;
                At[(kk + 1) * 68 + mfill] = v.y;
                At[(kk + 2) * 68 + mfill] = v.z;
                At[(kk + 3) * 68 + mfill] = v.w;
            }
        }
        __syncthreads();

        unsigned long long acc[2][3];
#pragma unroll
        for (int p = 0; p < 2; p++)
#pragma unroll
            for (int c = 0; c < 3; c++) acc[p][c] = 0ULL;

#pragma unroll 4
        for (int k = 0; k < 160; k++) {
            ulonglong2 A = *reinterpret_cast<const ulonglong2*>(&At[k * 68 + mt * 4]);
            const float* wr = &Wa[k * 96 + jt];
#pragma unroll
            for (int c = 0; c < 3; c++) {
                unsigned long long ww = pack2(wr[32 * c]);
                ffma2(acc[0][c], A.x, ww);
                ffma2(acc[1][c], A.y, ww);
            }
        }

        int r0 = mt * 4;
#pragma unroll
        for (int p = 0; p < 2; p++) {
            int ra = r0 + 2 * p, rb = ra + 1;
            int na_a = nav[ra], na_b = nav[rb];
            float sw0 = aswv[ra], sw1 = aswv[rb];
#pragma unroll
            for (int c = 0; c < 3; c++) {
                float lo, hi;
                unpack2(acc[p][c], lo, hi);
                int j = jt + 32 * c;
                float nb0 = g_nbase[(size_t)na_a * 96 + j];
                float nb1 = g_nbase[(size_t)na_b * 96 + j];
                if (c < 2) {
                    float y0 = silu_f(lo + nb0) * sw0;
                    float y1 = silu_f(hi + nb1) * sw1;
                    atomicAdd(&g_reduced[(size_t)ijav[ra] * EDIM + j], y0);
                    atomicAdd(&g_reduced[(size_t)ijav[rb] * EDIM + j], y1);
                } else {
                    float y0 = silu_f(lo + nb0);
                    float y1 = silu_f(hi + nb1);
                    size_t o0 = (size_t)(a0 + ra) * ADIM + jt;
                    size_t o1 = (size_t)(a0 + rb) * ADIM + jt;
                    // angle residual read from smem tile (cols 0..31 of At)
                    out_angle[o0] = At[jt * 68 + ra] + ar * y0;
                    out_angle[o1] = At[jt * 68 + rb] + ar * y1;
                }
            }
        }
    }
}

// ---------------- edge angle message GEMM (f32x2) ----------------
__global__ __launch_bounds__(256) void k_edge_msg(const float* __restrict__ W2,
                                                  const float* __restrict__ b2,
                                                  const float* __restrict__ e_res1,
                                                  float* __restrict__ out_edge) {
    __shared__ float Ws[64 * 64];
    __shared__ float At[64 * 68];
    int tid = threadIdx.x;
    int jt = tid & 31, mt = tid >> 5;
    int e0 = blockIdx.x * 64;
    for (int idx = tid; idx < 64 * 64; idx += 256) Ws[idx] = W2[idx];
    for (int idx = tid; idx < 64 * 64; idx += 256) {
        int m = idx >> 6, k = idx & 63;
        At[k * 68 + m] = g_reduced[(size_t)(e0 + m) * EDIM + k];
    }
    __syncthreads();
    unsigned long long acc[4][2];
#pragma unroll
    for (int i = 0; i < 4; i++) { acc[i][0] = 0ULL; acc[i][1] = 0ULL; }
#pragma unroll 4
    for (int k = 0; k < 64; k++) {
        ulonglong2 A0 = *reinterpret_cast<const ulonglong2*>(&At[k * 68 + mt * 8]);
        ulonglong2 A1 = *reinterpret_cast<const ulonglong2*>(&At[k * 68 + mt * 8 + 4]);
        unsigned long long w0 = pack2(Ws[k * 64 + jt]);
        unsigned long long w1 = pack2(Ws[k * 64 + jt + 32]);
        ffma2(acc[0][0], A0.x, w0); ffma2(acc[0][1], A0.x, w1);
        ffma2(acc[1][0], A0.y, w0); ffma2(acc[1][1], A0.y, w1);
        ffma2(acc[2][0], A1.x, w0); ffma2(acc[2][1], A1.x, w1);
        ffma2(acc[3][0], A1.y, w0); ffma2(acc[3][1], A1.y, w1);
    }
    float bb0 = b2[jt], bb1 = b2[jt + 32];
    float er0 = e_res1[jt], er1 = e_res1[jt + 32];
#pragma unroll
    for (int i = 0; i < 4; i++) {
#pragma unroll
        for (int q = 0; q < 2; q++) {
            float lo, hi;
            unpack2(acc[i][q], lo, hi);
            int j = (q == 0) ? jt : jt + 32;
            float bb = (q == 0) ? bb0 : bb1;
            float er = (q == 0) ? er0 : er1;
            int ea = e0 + mt * 8 + 2 * i;
            int eb = ea + 1;
            out_edge[(size_t)ea * EDIM + j] += er * silu_f(lo + bb);
            out_edge[(size_t)eb * EDIM + j] += er * silu_f(hi + bb);
        }
    }
}

// ---------------- launch ----------------
extern "C" void kernel_launch(void* const* d_in, const int* in_sizes, int n_in,
                              void* d_out, int out_size) {
    const float* node_ext   = (const float*)d_in[0];
    const float* edge_ebd   = (const float*)d_in[1];
    const float* h2         = (const float*)d_in[2];
    const float* angle_ebd  = (const float*)d_in[3];
    const float* sw         = (const float*)d_in[6];
    const float* a_sw       = (const float*)d_in[9];
    const int*   edge_index = (const int*)d_in[10];
    const int*   angle_index= (const int*)d_in[11];
    const float* W_node_self = (const float*)d_in[12];
    const float* b_node_self = (const float*)d_in[13];
    const float* W_node_sym  = (const float*)d_in[14];
    const float* b_node_sym  = (const float*)d_in[15];
    const float* W_node_edge = (const float*)d_in[16];
    const float* b_node_edge = (const float*)d_in[17];
    const float* W_edge_self = (const float*)d_in[18];
    const float* b_edge_self = (const float*)d_in[19];
    const float* W_edge_angle1 = (const float*)d_in[20];
    const float* b_edge_angle1 = (const float*)d_in[21];
    const float* W_edge_angle2 = (const float*)d_in[22];
    const float* b_edge_angle2 = (const float*)d_in[23];
    const float* W_angle_self  = (const float*)d_in[24];
    const float* b_angle_self  = (const float*)d_in[25];
    const float* n_res0 = (const float*)d_in[26];
    const float* n_res1 = (const float*)d_in[27];
    const float* n_res2 = (const float*)d_in[28];
    const float* e_res0 = (const float*)d_in[29];
    const float* e_res1 = (const float*)d_in[30];
    const float* a_res0 = (const float*)d_in[31];

    float* out = (float*)d_out;
    float* out_node  = out;
    float* out_edge  = out + (size_t)NLOC * NDIM;
    float* out_angle = out_edge + (size_t)NEDGE * EDIM;

    const int* n2e = edge_index;
    const int* n_ext2e = edge_index + NEDGE;

    cudaFuncSetAttribute((const void*)k_edge_tc,
                         cudaFuncAttributeMaxDynamicSharedMemorySize, ET_SMEM);
    cudaFuncSetAttribute((const void*)k_angle,
                         cudaFuncAttributeMaxDynamicSharedMemorySize, 105728);

    k_zero<<<4096, 256>>>();
    k_count<<<NEDGE / 256, 256>>>(n2e);
    k_scan<<<1, 1024>>>();
    k_scatter<<<NEDGE / 256, 256>>>(n2e);
    k_sym<<<NLOC, 192>>>(edge_ebd, node_ext, h2, sw, n_ext2e);
    k_symmm<<<NLOC / 64, 256>>>(W_node_sym, b_node_sym, n_res1,
                                W_node_self, b_node_self, n_res0, node_ext, out_node);
    k_base<<<NLOC / 64, 256>>>(node_ext, W_node_edge, W_edge_self, b_node_edge, b_edge_self);
    k_nbase<<<NLOC / 64, 256>>>(node_ext, W_edge_angle1, W_angle_self,
                                b_edge_angle1, b_angle_self);
    k_edge_tc<<<148, 512, ET_SMEM>>>(node_ext, edge_ebd, sw, n_ext2e,
                                     W_node_edge, W_edge_self, e_res0, out_edge);
    k_node_finish<<<NLOC * NDIM / 256, 256>>>(n_res2, out_node);
    k_angle<<<592, 512, 105728>>>(angle_ebd, edge_ebd, angle_index, a_sw,
                                  W_edge_angle1, W_angle_self, a_res0, out_angle);
    k_edge_msg<<<NEDGE / 64, 256>>>(W_edge_angle2, b_edge_angle2, e_res1, out_edge);
}

// round 8
// speedup vs baseline: 3.3028x; 1.0122x over previous
#include <cuda_runtime.h>
#include <cuda_bf16.h>
#include <cstdint>
#include <cstddef>

#define NLOC   4096
#define NALL   6144
#define NDIM   128
#define EDIM   64
#define ADIM   32
#define NEDGE  262144
#define NANGLE 409600
#define INV_DYN_E 0.15625f            // 1/6.4
#define SYM_SCALE 0.0520833333333f    // (1/6.4)/3

// ---------------- device scratch ----------------
__device__ float g_sym[(size_t)NLOC * 768];
__device__ float g_base[(size_t)NLOC * 192];
__device__ float g_nbase[(size_t)NLOC * 96];
__device__ float g_reduced[(size_t)NEDGE * EDIM];
__device__ float g_msg[(size_t)NLOC * NDIM];
__device__ int   g_ecnt[NLOC];
__device__ int   g_eoff[NLOC + 1];
__device__ int   g_ecur[NLOC];
__device__ int   g_eids[NEDGE];
__device__ int   g_enode[NEDGE];

// ---------------- helpers ----------------
__device__ __forceinline__ float silu_f(float x) { return x / (1.0f + __expf(-x)); }

__device__ __forceinline__ unsigned long long pack2(float w) {
    unsigned long long r;
    unsigned int u = __float_as_uint(w);
    asm("mov.b64 %0, {%1,%1};" : "=l"(r) : "r"(u));
    return r;
}
__device__ __forceinline__ void ffma2(unsigned long long& d, unsigned long long a,
                                      unsigned long long b) {
    asm("fma.rn.f32x2 %0, %1, %2, %0;" : "+l"(d) : "l"(a), "l"(b));
}
__device__ __forceinline__ void unpack2(unsigned long long v, float& lo, float& hi) {
    unsigned int l, h;
    asm("mov.b64 {%0,%1}, %2;" : "=r"(l), "=r"(h) : "l"(v));
    lo = __uint_as_float(l);
    hi = __uint_as_float(h);
}

__device__ __forceinline__ uint32_t smem_u32(const void* p) {
    uint32_t a;
    asm("{ .reg .u64 t; cvta.to.shared.u64 t, %1; cvt.u32.u64 %0, t; }" : "=r"(a) : "l"(p));
    return a;
}

// ldmatrix x4 (non-transposed)
__device__ __forceinline__ void ldsm4(uint32_t* r, uint32_t addr) {
    asm volatile("ldmatrix.sync.aligned.m8n8.x4.shared.b16 {%0,%1,%2,%3}, [%4];"
                 : "=r"(r[0]), "=r"(r[1]), "=r"(r[2]), "=r"(r[3]) : "r"(addr));
}

// mma m16n8k16 bf16 -> f32
__device__ __forceinline__ void mma_bf16(float* d, const uint32_t* a, const uint32_t* b) {
    asm volatile(
        "mma.sync.aligned.m16n8k16.row.col.f32.bf16.bf16.f32 "
        "{%0,%1,%2,%3}, {%4,%5,%6,%7}, {%8,%9}, {%0,%1,%2,%3};"
        : "+f"(d[0]), "+f"(d[1]), "+f"(d[2]), "+f"(d[3])
        : "r"(a[0]), "r"(a[1]), "r"(a[2]), "r"(a[3]), "r"(b[0]), "r"(b[1]));
}

__device__ __forceinline__ uint32_t bfp(float a, float b) {
    __nv_bfloat162 t = __floats2bfloat162_rn(a, b);
    return *reinterpret_cast<uint32_t*>(&t);
}

// ---------------- zero scratch ----------------
__global__ void k_zero() {
    size_t i0 = (size_t)blockIdx.x * blockDim.x + threadIdx.x;
    size_t stride = (size_t)gridDim.x * blockDim.x;
    float4* r = reinterpret_cast<float4*>(g_reduced);
    size_t n4 = (size_t)NEDGE * EDIM / 4;
    for (size_t i = i0; i < n4; i += stride) r[i] = make_float4(0.f, 0.f, 0.f, 0.f);
    float4* m = reinterpret_cast<float4*>(g_msg);
    size_t m4 = (size_t)NLOC * NDIM / 4;
    for (size_t i = i0; i < m4; i += stride) m[i] = make_float4(0.f, 0.f, 0.f, 0.f);
    if (i0 < NLOC) g_ecnt[i0] = 0;
}

// ---------------- CSR build ----------------
__global__ void k_count(const int* __restrict__ n2e) {
    int e = blockIdx.x * blockDim.x + threadIdx.x;
    if (e < NEDGE) atomicAdd(&g_ecnt[n2e[e]], 1);
}

__global__ void k_scan() {
    __shared__ int sh[1024];
    int t = threadIdx.x;
    int c[4];
#pragma unroll
    for (int i = 0; i < 4; i++) c[i] = g_ecnt[t * 4 + i];
    int tot = c[0] + c[1] + c[2] + c[3];
    sh[t] = tot;
    __syncthreads();
    for (int st = 1; st < 1024; st <<= 1) {
        int add = (t >= st) ? sh[t - st] : 0;
        __syncthreads();
        sh[t] += add;
        __syncthreads();
    }
    int run = sh[t] - tot;
#pragma unroll
    for (int i = 0; i < 4; i++) {
        g_eoff[t * 4 + i] = run;
        g_ecur[t * 4 + i] = run;
        run += c[i];
    }
    if (t == 1023) g_eoff[NLOC] = run;
}

__global__ void k_scatter(const int* __restrict__ n2e) {
    int e = blockIdx.x * blockDim.x + threadIdx.x;
    if (e < NEDGE) {
        int n = n2e[e];
        int pos = atomicAdd(&g_ecur[n], 1);
        g_eids[pos] = e;
        g_enode[pos] = n;
    }
}

// ---------------- sym op ----------------
__global__ void k_sym(const float* __restrict__ edge_ebd, const float* __restrict__ node_ext,
                      const float* __restrict__ h2, const float* __restrict__ sw,
                      const int* __restrict__ n_ext2e) {
    __shared__ float S0[192], S1[192], S2[192];
    __shared__ float symv[768];
    int n = blockIdx.x;
    int t = threadIdx.x;
    int beg = g_eoff[n], end = g_eoff[n + 1];
    float a0 = 0.f, a1 = 0.f, a2 = 0.f;
    for (int i = beg; i < end; i++) {
        int e = g_eids[i];
        float swv = sw[e];
        float h0 = h2[e * 3 + 0] * swv;
        float h1 = h2[e * 3 + 1] * swv;
        float hh = h2[e * 3 + 2] * swv;
        float val = (t < 64) ? edge_ebd[(size_t)e * EDIM + t]
                             : node_ext[(size_t)n_ext2e[e] * NDIM + (t - 64)];
        a0 += h0 * val;
        a1 += h1 * val;
        a2 += hh * val;
    }
    S0[t] = a0; S1[t] = a1; S2[t] = a2;
    __syncthreads();
    if (t < 64) {
#pragma unroll
        for (int a = 0; a < 4; a++)
            symv[a * 64 + t] = SYM_SCALE * (S0[a] * S0[t] + S1[a] * S1[t] + S2[a] * S2[t]);
    } else {
        int dn = t - 64;
#pragma unroll
        for (int a = 0; a < 4; a++)
            symv[256 + a * 128 + dn] =
                SYM_SCALE * (S0[64 + a] * S0[t] + S1[64 + a] * S1[t] + S2[64 + a] * S2[t]);
    }
    __syncthreads();
    for (int idx = t; idx < 768; idx += 192) g_sym[(size_t)n * 768 + idx] = symv[idx];
}

// ---------------- node_sym GEMM fused with node_self ----------------
__global__ __launch_bounds__(256) void k_symmm(
    const float* __restrict__ W_sym, const float* __restrict__ b_sym,
    const float* __restrict__ n_res1,
    const float* __restrict__ W_self, const float* __restrict__ b_self,
    const float* __restrict__ n_res0,
    const float* __restrict__ node_ext, float* __restrict__ out_node) {
    __shared__ float Wt[32 * 128];
    __shared__ float At[32 * 72];
    int tid = threadIdx.x;
    int jt = tid & 31, mt = tid >> 5;
    int n0 = blockIdx.x * 64;
    float acc0[8][4], acc1[8][4];
#pragma unroll
    for (int i = 0; i < 8; i++)
#pragma unroll
        for (int q = 0; q < 4; q++) { acc0[i][q] = 0.f; acc1[i][q] = 0.f; }

    // sym part: K = 768
    for (int kt = 0; kt < 768; kt += 32) {
        for (int idx = tid; idx < 32 * 128; idx += 256)
            Wt[idx] = W_sym[(size_t)(kt + idx / 128) * 128 + (idx % 128)];
        for (int idx = tid; idx < 32 * 64; idx += 256) {
            int m = idx / 32, k = idx % 32;
            At[k * 72 + m] = g_sym[(size_t)(n0 + m) * 768 + kt + k];
        }
        __syncthreads();
#pragma unroll 4
        for (int k = 0; k < 32; k++) {
            float4 A0 = *reinterpret_cast<const float4*>(&At[k * 72 + mt * 8]);
            float4 A1 = *reinterpret_cast<const float4*>(&At[k * 72 + mt * 8 + 4]);
            float am[8] = {A0.x, A0.y, A0.z, A0.w, A1.x, A1.y, A1.z, A1.w};
            float4 wv = *reinterpret_cast<const float4*>(&Wt[k * 128 + jt * 4]);
            float wq[4] = {wv.x, wv.y, wv.z, wv.w};
#pragma unroll
            for (int i = 0; i < 8; i++)
#pragma unroll
                for (int q = 0; q < 4; q++) acc0[i][q] += am[i] * wq[q];
        }
        __syncthreads();
    }
    // self part: K = 128
    for (int kt = 0; kt < 128; kt += 32) {
        for (int idx = tid; idx < 32 * 128; idx += 256)
            Wt[idx] = W_self[(size_t)(kt + idx / 128) * 128 + (idx % 128)];
        for (int idx = tid; idx < 32 * 64; idx += 256) {
            int m = idx / 32, k = idx % 32;
            At[k * 72 + m] = node_ext[(size_t)(n0 + m) * NDIM + kt + k];
        }
        __syncthreads();
#pragma unroll 4
        for (int k = 0; k < 32; k++) {
            float4 A0 = *reinterpret_cast<const float4*>(&At[k * 72 + mt * 8]);
            float4 A1 = *reinterpret_cast<const float4*>(&At[k * 72 + mt * 8 + 4]);
            float am[8] = {A0.x, A0.y, A0.z, A0.w, A1.x, A1.y, A1.z, A1.w};
            float4 wv = *reinterpret_cast<const float4*>(&Wt[k * 128 + jt * 4]);
            float wq[4] = {wv.x, wv.y, wv.z, wv.w};
#pragma unroll
            for (int i = 0; i < 8; i++)
#pragma unroll
                for (int q = 0; q < 4; q++) acc1[i][q] += am[i] * wq[q];
        }
        __syncthreads();
    }
#pragma unroll
    for (int i = 0; i < 8; i++) {
        int n = n0 + mt * 8 + i;
#pragma unroll
        for (int q = 0; q < 4; q++) {
            int j = jt * 4 + q;
            float y1 = silu_f(acc0[i][q] + b_sym[j]);
            float y0 = silu_f(acc1[i][q] + b_self[j]);
            out_node[(size_t)n * 128 + j] =
                node_ext[(size_t)n * NDIM + j] + n_res0[j] * y0 + n_res1[j] * y1;
        }
    }
}

// ---------------- base precompute (edge kernel, 192 cols) ----------------
__global__ __launch_bounds__(256) void k_base(const float* __restrict__ node_ext,
                                              const float* __restrict__ W_ne,
                                              const float* __restrict__ W_es,
                                              const float* __restrict__ b_ne,
                                              const float* __restrict__ b_es) {
    __shared__ float Wt[32 * 192];
    __shared__ float At[32 * 72];
    int tid = threadIdx.x;
    int jt = tid & 31, mt = tid >> 5;
    int n0 = blockIdx.x * 64;
    float acc[8][6];
#pragma unroll
    for (int i = 0; i < 8; i++)
#pragma unroll
        for (int c = 0; c < 6; c++) acc[i][c] = 0.f;
    for (int kt = 0; kt < 128; kt += 32) {
        for (int idx = tid; idx < 32 * 192; idx += 256) {
            int k = idx / 192, j = idx % 192;
            int row = kt + k;
            Wt[idx] = (j < 128) ? W_ne[(size_t)row * 128 + j] : W_es[(size_t)row * 64 + (j - 128)];
        }
        for (int idx = tid; idx < 32 * 64; idx += 256) {
            int m = idx / 32, k = idx % 32;
            At[k * 72 + m] = node_ext[(size_t)(n0 + m) * NDIM + kt + k];
        }
        __syncthreads();
#pragma unroll 2
        for (int k = 0; k < 32; k++) {
            float4 A0 = *reinterpret_cast<const float4*>(&At[k * 72 + mt * 8]);
            float4 A1 = *reinterpret_cast<const float4*>(&At[k * 72 + mt * 8 + 4]);
            float am[8] = {A0.x, A0.y, A0.z, A0.w, A1.x, A1.y, A1.z, A1.w};
#pragma unroll
            for (int c = 0; c < 6; c++) {
                float w = Wt[k * 192 + jt + 32 * c];
#pragma unroll
                for (int i = 0; i < 8; i++) acc[i][c] += am[i] * w;
            }
        }
        __syncthreads();
    }
#pragma unroll
    for (int i = 0; i < 8; i++) {
        int n = n0 + mt * 8 + i;
#pragma unroll
        for (int c = 0; c < 6; c++) {
            int j = jt + 32 * c;
            float bb = (j < 128) ? b_ne[j] : b_es[j - 128];
            g_base[(size_t)n * 192 + j] = acc[i][c] + bb;
        }
    }
}

// ---------------- nbase precompute (angle kernel, 96 cols) ----------------
__global__ __launch_bounds__(256) void k_nbase(const float* __restrict__ node_ext,
                                               const float* __restrict__ W_ea1,
                                               const float* __restrict__ W_as,
                                               const float* __restrict__ b_ea1,
                                               const float* __restrict__ b_as) {
    __shared__ float Wt[32 * 96];
    __shared__ float At[32 * 72];
    int tid = threadIdx.x;
    int jt = tid & 31, mt = tid >> 5;
    int n0 = blockIdx.x * 64;
    float acc[8][3];
#pragma unroll
    for (int i = 0; i < 8; i++)
#pragma unroll
        for (int c = 0; c < 3; c++) acc[i][c] = 0.f;
    for (int kt = 0; kt < 128; kt += 32) {
        for (int idx = tid; idx < 32 * 96; idx += 256) {
            int k = idx / 96, j = idx % 96;
            int row = 32 + kt + k;
            Wt[idx] = (j < 64) ? W_ea1[(size_t)row * 64 + j] : W_as[(size_t)row * 32 + (j - 64)];
        }
        for (int idx = tid; idx < 32 * 64; idx += 256) {
            int m = idx / 32, k = idx % 32;
            At[k * 72 + m] = node_ext[(size_t)(n0 + m) * NDIM + kt + k];
        }
        __syncthreads();
#pragma unroll 2
        for (int k = 0; k < 32; k++) {
            float4 A0 = *reinterpret_cast<const float4*>(&At[k * 72 + mt * 8]);
            float4 A1 = *reinterpret_cast<const float4*>(&At[k * 72 + mt * 8 + 4]);
            float am[8] = {A0.x, A0.y, A0.z, A0.w, A1.x, A1.y, A1.z, A1.w};
#pragma unroll
            for (int c = 0; c < 3; c++) {
                float w = Wt[k * 96 + jt + 32 * c];
#pragma unroll
                for (int i = 0; i < 8; i++) acc[i][c] += am[i] * w;
            }
        }
        __syncthreads();
    }
#pragma unroll
    for (int i = 0; i < 8; i++) {
        int n = n0 + mt * 8 + i;
#pragma unroll
        for (int c = 0; c < 3; c++) {
            int j = jt + 32 * c;
            float bb = (j < 64) ? b_ea1[j] : b_as[j - 64];
            g_nbase[(size_t)n * 96 + j] = acc[i][c] + bb;
        }
    }
}

// ================= edge GEMM via mma.sync bf16 3-term split =================
// M=64 (chunk of CSR-ordered edges), N=192, K=192. Persistent, 512 threads.
// smem layout (halves stride 200 => ldmatrix bank-conflict-free):
//   Wh[192n][200k] bf16, Wl same; Ah[64m][200k], Al same; idx arrays.
#define ET_WH 0
#define ET_WL 76800
#define ET_AH 153600
#define ET_AL 179200
#define ET_IDX 204800
#define ET_SMEM 205568

__global__ __launch_bounds__(512, 1) void k_edge_tc(
    const float* __restrict__ node_ext, const float* __restrict__ edge_ebd,
    const float* __restrict__ sw, const int* __restrict__ n_ext2e,
    const float* __restrict__ W_ne, const float* __restrict__ W_es,
    const float* __restrict__ e_res0, float* __restrict__ out_edge) {
    extern __shared__ char smc[];
    uint32_t sb = smem_u32(smc);
    int tid = threadIdx.x;
    int wid = tid >> 5;
    int lane = tid & 31;
    int wm = wid >> 2;   // 0..3 : rows wm*16
    int wn = wid & 3;    // 0..3 : cols wn*48

    int* eidv = (int*)(smc + ET_IDX);
    int* nodev = eidv + 64;
    float* sws = (float*)(nodev + 64);

    // ---- load weights (rows 128..319 of [W_ne|W_es]) as bf16 hi/lo, layout [n][k] ----
    for (int idx = tid; idx < 192 * 192; idx += 512) {
        int k = idx / 192, j = idx % 192;
        float w = (j < 128) ? W_ne[(size_t)(128 + k) * 128 + j]
                            : W_es[(size_t)(128 + k) * 64 + (j - 128)];
        __nv_bfloat16 h = __float2bfloat16(w);
        float l = w - __bfloat162float(h);
        *reinterpret_cast<__nv_bfloat16*>(smc + ET_WH + (j * 200 + k) * 2) = h;
        *reinterpret_cast<__nv_bfloat16*>(smc + ET_WL + (j * 200 + k) * 2) = __float2bfloat16(l);
    }

    // ldmatrix source addresses
    uint32_t aRow = wm * 16 + (lane & 15);
    uint32_t aColH = (lane >> 4);  // 0/1 -> k-half offset 8
    uint32_t aAddrH = sb + ET_AH + (aRow * 200 + aColH * 8) * 2;
    uint32_t aAddrL = sb + ET_AL + (aRow * 200 + aColH * 8) * 2;
    int nrow = wn * 48 + (lane & 7) + ((lane & 16) ? 8 : 0);
    int khalf = (lane & 8) ? 8 : 0;
    uint32_t bAddrH = sb + ET_WH + (nrow * 200 + khalf) * 2;
    uint32_t bAddrL = sb + ET_WL + (nrow * 200 + khalf) * 2;

    int mfill = tid & 63;   // fill row
    int seg = tid >> 6;     // 0..7 -> k range seg*24..+24

    for (int ch = blockIdx.x; ch < NEDGE / 64; ch += gridDim.x) {
        int c0 = ch * 64;
        __syncthreads();
        if (tid < 64) {
            int e = g_eids[c0 + tid];
            eidv[tid] = e;
            nodev[tid] = g_enode[c0 + tid];
            sws[tid] = sw[e];
        }
        // ---- fill A (bf16 hi/lo): row mfill, cols seg*24..+24 ----
        {
            int e = __ldg(&g_eids[c0 + mfill]);
            int nd = __ldg(&n_ext2e[e]);
            const float4* nrowp = (const float4*)(node_ext + (size_t)nd * NDIM);
            const float4* erowp = (const float4*)(edge_ebd + (size_t)e * EDIM);
            uint32_t rowoff = (uint32_t)mfill * 200;
#pragma unroll
            for (int q = 0; q < 6; q++) {
                int kk = seg * 24 + q * 4;
                float4 v = (kk < 128) ? nrowp[kk >> 2] : erowp[(kk - 128) >> 2];
                __nv_bfloat16 h0 = __float2bfloat16(v.x);
                __nv_bfloat16 h1 = __float2bfloat16(v.y);
                __nv_bfloat16 h2 = __float2bfloat16(v.z);
                __nv_bfloat16 h3 = __float2bfloat16(v.w);
                uint32_t hi01, hi23;
                { __nv_bfloat162 t; t.x = h0; t.y = h1; hi01 = *reinterpret_cast<uint32_t*>(&t); }
                { __nv_bfloat162 t; t.x = h2; t.y = h3; hi23 = *reinterpret_cast<uint32_t*>(&t); }
                uint32_t lo01 = bfp(v.x - __bfloat162float(h0), v.y - __bfloat162float(h1));
                uint32_t lo23 = bfp(v.z - __bfloat162float(h2), v.w - __bfloat162float(h3));
                uint32_t boff = (rowoff + kk) * 2;
                *reinterpret_cast<uint32_t*>(smc + ET_AH + boff) = hi01;
                *reinterpret_cast<uint32_t*>(smc + ET_AH + boff + 4) = hi23;
                *reinterpret_cast<uint32_t*>(smc + ET_AL + boff) = lo01;
                *reinterpret_cast<uint32_t*>(smc + ET_AL + boff + 4) = lo23;
            }
        }
        __syncthreads();

        // ---- mainloop: 12 ksteps, 3-term bf16 split ----
        float d[6][4];
#pragma unroll
        for (int nt = 0; nt < 6; nt++)
#pragma unroll
            for (int q = 0; q < 4; q++) d[nt][q] = 0.f;

#pragma unroll
        for (int s = 0; s < 12; s++) {
            uint32_t ah[4], al[4];
            ldsm4(ah, aAddrH + s * 32);
            ldsm4(al, aAddrL + s * 32);
#pragma unroll
            for (int pr = 0; pr < 3; pr++) {
                uint32_t bh[4], bl[4];
                ldsm4(bh, bAddrH + pr * 16 * 400 + s * 32);
                ldsm4(bl, bAddrL + pr * 16 * 400 + s * 32);
                mma_bf16(d[pr * 2], ah, bh);
                mma_bf16(d[pr * 2], ah, bl);
                mma_bf16(d[pr * 2], al, bh);
                mma_bf16(d[pr * 2 + 1], ah, bh + 2);
                mma_bf16(d[pr * 2 + 1], ah, bl + 2);
                mma_bf16(d[pr * 2 + 1], al, bh + 2);
            }
        }

        // ---- epilogue ----
        int g = lane >> 2, qt = lane & 3;
        int r0 = wm * 16 + g, r1 = r0 + 8;
        int nd0 = nodev[r0], nd1 = nodev[r1];
        float sw0 = sws[r0], sw1 = sws[r1];
        int ee0 = eidv[r0], ee1 = eidv[r1];
        bool samend = (nd0 == nd1);
#pragma unroll
        for (int nt = 0; nt < 6; nt++) {
            int j0 = wn * 48 + nt * 8 + qt * 2;
            float2 b0v = *(const float2*)(g_base + (size_t)nd0 * 192 + j0);
            float2 b1v = *(const float2*)(g_base + (size_t)nd1 * 192 + j0);
            float y00 = silu_f(d[nt][0] + b0v.x);
            float y01 = silu_f(d[nt][1] + b0v.y);
            float y10 = silu_f(d[nt][2] + b1v.x);
            float y11 = silu_f(d[nt][3] + b1v.y);
            if (j0 < 128) {
                float v00 = y00 * sw0, v01 = y01 * sw0;
                float v10 = y10 * sw1, v11 = y11 * sw1;
                if (samend) {
                    atomicAdd(&g_msg[(size_t)nd0 * NDIM + j0], v00 + v10);
                    atomicAdd(&g_msg[(size_t)nd0 * NDIM + j0 + 1], v01 + v11);
                } else {
                    atomicAdd(&g_msg[(size_t)nd0 * NDIM + j0], v00);
                    atomicAdd(&g_msg[(size_t)nd0 * NDIM + j0 + 1], v01);
                    atomicAdd(&g_msg[(size_t)nd1 * NDIM + j0], v10);
                    atomicAdd(&g_msg[(size_t)nd1 * NDIM + j0 + 1], v11);
                }
            } else {
                int col = j0 - 128;
                float2 er = *(const float2*)(e_res0 + col);
                size_t o0 = (size_t)ee0 * EDIM + col;
                size_t o1 = (size_t)ee1 * EDIM + col;
                float2 eb0 = *(const float2*)(edge_ebd + o0);
                float2 eb1 = *(const float2*)(edge_ebd + o1);
                *(float2*)(out_edge + o0) = make_float2(eb0.x + er.x * y00, eb0.y + er.y * y01);
                *(float2*)(out_edge + o1) = make_float2(eb1.x + er.x * y10, eb1.y + er.y * y11);
            }
        }
    }
}

__global__ void k_node_finish(const float* __restrict__ n_res2, float* __restrict__ out_node) {
    int i = blockIdx.x * blockDim.x + threadIdx.x;
    if (i < NLOC * NDIM) {
        int j = i & (NDIM - 1);
        out_node[i] += n_res2[j] * g_msg[i] * INV_DYN_E;
    }
}

// ---------------- angle GEMM: K=160 via g_nbase, f32x2, persistent ----------------
__global__ __launch_bounds__(512, 2) void k_angle(
    const float* __restrict__ angle_ebd, const float* __restrict__ edge_ebd,
    const int* __restrict__ ai, const float* __restrict__ a_sw,
    const float* __restrict__ W_ea1, const float* __restrict__ W_as,
    const float* __restrict__ a_res0, float* __restrict__ out_angle) {
    extern __shared__ float smem[];
    float* Wa = smem;                    // 160*96
    float* At = Wa + 160 * 96;           // 160*68
    int* nav = (int*)(At + 160 * 68);
    int* ijav = nav + 64;
    float* aswv = (float*)(ijav + 64);

    int tid = threadIdx.x;
    int jt = tid & 31, mt = tid >> 5;
    int mfill = tid & 63;
    int seg = tid >> 6;

    const int* n2a = ai;
    const int* eij = ai + NANGLE;
    const int* eik = ai + 2 * NANGLE;

    for (int idx = tid; idx < 160 * 96; idx += 512) {
        int k = idx / 96, j = idx % 96;
        int srck = (k < 32) ? k : ((k < 96) ? 160 + (k - 32) : 224 + (k - 96));
        Wa[idx] = (j < 64) ? W_ea1[(size_t)srck * 64 + j] : W_as[(size_t)srck * 32 + (j - 64)];
    }
    float ar = a_res0[jt];

    for (int t = blockIdx.x; t < NANGLE / 64; t += gridDim.x) {
        int a0 = t * 64;
        __syncthreads();
        if (tid < 64) {
            nav[tid] = n2a[a0 + tid];
            ijav[tid] = eij[a0 + tid];
            aswv[tid] = a_sw[a0 + tid];
        }
        {
            int a = a0 + mfill;
            int ek = __ldg(&eik[a]);
            int ej = __ldg(&eij[a]);
            const float4* arow = (const float4*)(angle_ebd + (size_t)a * ADIM);
            const float4* krow = (const float4*)(edge_ebd + (size_t)ek * EDIM);
            const float4* jrow = (const float4*)(edge_ebd + (size_t)ej * EDIM);
#pragma unroll
            for (int q = 0; q < 5; q++) {
                int kk = seg * 20 + q * 4;
                float4 v = (kk < 32) ? arow[kk >> 2]
                         : (kk < 96) ? krow[(kk - 32) >> 2]
                                     : jrow[(kk - 96) >> 2];
                At[(kk + 0) * 68 + mfill] = v.x;
                At[(kk + 1) * 68 + mfill] = v.y;
                At[(kk + 2) * 68 + mfill] = v.z;
                At[(kk + 3) * 68 + mfill] = v.w;
            }
        }
        __syncthreads();

        unsigned long long acc[2][3];
#pragma unroll
        for (int p = 0; p < 2; p++)
#pragma unroll
            for (int c = 0; c < 3; c++) acc[p][c] = 0ULL;

#pragma unroll 4
        for (int k = 0; k < 160; k++) {
            ulonglong2 A = *reinterpret_cast<const ulonglong2*>(&At[k * 68 + mt * 4]);
            const float* wr = &Wa[k * 96 + jt];
#pragma unroll
            for (int c = 0; c < 3; c++) {
                unsigned long long ww = pack2(wr[32 * c]);
                ffma2(acc[0][c], A.x, ww);
                ffma2(acc[1][c], A.y, ww);
            }
        }

        int r0 = mt * 4;
#pragma unroll
        for (int p = 0; p < 2; p++) {
            int ra = r0 + 2 * p, rb = ra + 1;
            int na_a = nav[ra], na_b = nav[rb];
            float sw0 = aswv[ra], sw1 = aswv[rb];
#pragma unroll
            for (int c = 0; c < 3; c++) {
                float lo, hi;
                unpack2(acc[p][c], lo, hi);
                int j = jt + 32 * c;
                float nb0 = g_nbase[(size_t)na_a * 96 + j];
                float nb1 = g_nbase[(size_t)na_b * 96 + j];
                if (c < 2) {
                    float y0 = silu_f(lo + nb0) * sw0;
                    float y1 = silu_f(hi + nb1) * sw1;
                    atomicAdd(&g_reduced[(size_t)ijav[ra] * EDIM + j], y0);
                    atomicAdd(&g_reduced[(size_t)ijav[rb] * EDIM + j], y1);
                } else {
                    float y0 = silu_f(lo + nb0);
                    float y1 = silu_f(hi + nb1);
                    size_t o0 = (size_t)(a0 + ra) * ADIM + jt;
                    size_t o1 = (size_t)(a0 + rb) * ADIM + jt;
                    // angle residual read from smem tile (cols 0..31 of At)
                    out_angle[o0] = At[jt * 68 + ra] + ar * y0;
                    out_angle[o1] = At[jt * 68 + rb] + ar * y1;
                }
            }
        }
    }
}

// ---------------- edge angle message GEMM (f32x2) ----------------
__global__ __launch_bounds__(256) void k_edge_msg(const float* __restrict__ W2,
                                                  const float* __restrict__ b2,
                                                  const float* __restrict__ e_res1,
                                                  float* __restrict__ out_edge) {
    __shared__ float Ws[64 * 64];
    __shared__ float At[64 * 68];
    int tid = threadIdx.x;
    int jt = tid & 31, mt = tid >> 5;
    int e0 = blockIdx.x * 64;
    for (int idx = tid; idx < 64 * 64; idx += 256) Ws[idx] = W2[idx];
    for (int idx = tid; idx < 64 * 64; idx += 256) {
        int m = idx >> 6, k = idx & 63;
        At[k * 68 + m] = g_reduced[(size_t)(e0 + m) * EDIM + k];
    }
    __syncthreads();
    unsigned long long acc[4][2];
#pragma unroll
    for (int i = 0; i < 4; i++) { acc[i][0] = 0ULL; acc[i][1] = 0ULL; }
#pragma unroll 4
    for (int k = 0; k < 64; k++) {
        ulonglong2 A0 = *reinterpret_cast<const ulonglong2*>(&At[k * 68 + mt * 8]);
        ulonglong2 A1 = *reinterpret_cast<const ulonglong2*>(&At[k * 68 + mt * 8 + 4]);
        unsigned long long w0 = pack2(Ws[k * 64 + jt]);
        unsigned long long w1 = pack2(Ws[k * 64 + jt + 32]);
        ffma2(acc[0][0], A0.x, w0); ffma2(acc[0][1], A0.x, w1);
        ffma2(acc[1][0], A0.y, w0); ffma2(acc[1][1], A0.y, w1);
        ffma2(acc[2][0], A1.x, w0); ffma2(acc[2][1], A1.x, w1);
        ffma2(acc[3][0], A1.y, w0); ffma2(acc[3][1], A1.y, w1);
    }
    float bb0 = b2[jt], bb1 = b2[jt + 32];
    float er0 = e_res1[jt], er1 = e_res1[jt + 32];
#pragma unroll
    for (int i = 0; i < 4; i++) {
#pragma unroll
        for (int q = 0; q < 2; q++) {
            float lo, hi;
            unpack2(acc[i][q], lo, hi);
            int j = (q == 0) ? jt : jt + 32;
            float bb = (q == 0) ? bb0 : bb1;
            float er = (q == 0) ? er0 : er1;
            int ea = e0 + mt * 8 + 2 * i;
            int eb = ea + 1;
            out_edge[(size_t)ea * EDIM + j] += er * silu_f(lo + bb);
            out_edge[(size_t)eb * EDIM + j] += er * silu_f(hi + bb);
        }
    }
}

// ---------------- launch ----------------
extern "C" void kernel_launch(void* const* d_in, const int* in_sizes, int n_in,
                              void* d_out, int out_size) {
    const float* node_ext   = (const float*)d_in[0];
    const float* edge_ebd   = (const float*)d_in[1];
    const float* h2         = (const float*)d_in[2];
    const float* angle_ebd  = (const float*)d_in[3];
    const float* sw         = (const float*)d_in[6];
    const float* a_sw       = (const float*)d_in[9];
    const int*   edge_index = (const int*)d_in[10];
    const int*   angle_index= (const int*)d_in[11];
    const float* W_node_self = (const float*)d_in[12];
    const float* b_node_self = (const float*)d_in[13];
    const float* W_node_sym  = (const float*)d_in[14];
    const float* b_node_sym  = (const float*)d_in[15];
    const float* W_node_edge = (const float*)d_in[16];
    const float* b_node_edge = (const float*)d_in[17];
    const float* W_edge_self = (const float*)d_in[18];
    const float* b_edge_self = (const float*)d_in[19];
    const float* W_edge_angle1 = (const float*)d_in[20];
    const float* b_edge_angle1 = (const float*)d_in[21];
    const float* W_edge_angle2 = (const float*)d_in[22];
    const float* b_edge_angle2 = (const float*)d_in[23];
    const float* W_angle_self  = (const float*)d_in[24];
    const float* b_angle_self  = (const float*)d_in[25];
    const float* n_res0 = (const float*)d_in[26];
    const float* n_res1 = (const float*)d_in[27];
    const float* n_res2 = (const float*)d_in[28];
    const float* e_res0 = (const float*)d_in[29];
    const float* e_res1 = (const float*)d_in[30];
    const float* a_res0 = (const float*)d_in[31];

    float* out = (float*)d_out;
    float* out_node  = out;
    float* out_edge  = out + (size_t)NLOC * NDIM;
    float* out_angle = out_edge + (size_t)NEDGE * EDIM;

    const int* n2e = edge_index;
    const int* n_ext2e = edge_index + NEDGE;

    cudaFuncSetAttribute((const void*)k_edge_tc,
                         cudaFuncAttributeMaxDynamicSharedMemorySize, ET_SMEM);
    cudaFuncSetAttribute((const void*)k_angle,
                         cudaFuncAttributeMaxDynamicSharedMemorySize, 105728);

    k_zero<<<4096, 256>>>();
    k_count<<<NEDGE / 256, 256>>>(n2e);
    k_scan<<<1, 1024>>>();
    k_scatter<<<NEDGE / 256, 256>>>(n2e);
    k_sym<<<NLOC, 192>>>(edge_ebd, node_ext, h2, sw, n_ext2e);
    k_symmm<<<NLOC / 64, 256>>>(W_node_sym, b_node_sym, n_res1,
                                W_node_self, b_node_self, n_res0, node_ext, out_node);
    k_base<<<NLOC / 64, 256>>>(node_ext, W_node_edge, W_edge_self, b_node_edge, b_edge_self);
    k_nbase<<<NLOC / 64, 256>>>(node_ext, W_edge_angle1, W_angle_self,
                                b_edge_angle1, b_angle_self);
    k_edge_tc<<<148, 512, ET_SMEM>>>(node_ext, edge_ebd, sw, n_ext2e,
                                     W_node_edge, W_edge_self, e_res0, out_edge);
    k_node_finish<<<NLOC * NDIM / 256, 256>>>(n_res2, out_node);
    k_angle<<<592, 512, 105728>>>(angle_ebd, edge_ebd, angle_index, a_sw,
                                  W_edge_angle1, W_angle_self, a_res0, out_angle);
    k_edge_msg<<<NEDGE / 64, 256>>>(W_edge_angle2, b_edge_angle2, e_res1, out_edge);
}

// round 9
// speedup vs baseline: 3.7455x; 1.1340x over previous
#include <cuda_runtime.h>
#include <cuda_bf16.h>
#include <cstdint>
#include <cstddef>

#define NLOC   4096
#define NALL   6144
#define NDIM   128
#define EDIM   64
#define ADIM   32
#define NEDGE  262144
#define NANGLE 409600
#define INV_DYN_E 0.15625f            // 1/6.4
#define SYM_SCALE 0.0520833333333f    // (1/6.4)/3

// ---------------- device scratch ----------------
__device__ float g_sym[(size_t)NLOC * 768];
__device__ float g_base[(size_t)NLOC * 192];
__device__ float g_nbase[(size_t)NLOC * 96];
__device__ float g_reduced[(size_t)NEDGE * EDIM];
__device__ float g_msg[(size_t)NLOC * NDIM];
__device__ int   g_ecnt[NLOC];
__device__ int   g_eoff[NLOC + 1];
__device__ int   g_ecur[NLOC];
__device__ int   g_eids[NEDGE];
__device__ int   g_enode[NEDGE];

// ---------------- helpers ----------------
__device__ __forceinline__ float silu_f(float x) { return x / (1.0f + __expf(-x)); }

__device__ __forceinline__ unsigned long long pack2(float w) {
    unsigned long long r;
    unsigned int u = __float_as_uint(w);
    asm("mov.b64 %0, {%1,%1};" : "=l"(r) : "r"(u));
    return r;
}
__device__ __forceinline__ void ffma2(unsigned long long& d, unsigned long long a,
                                      unsigned long long b) {
    asm("fma.rn.f32x2 %0, %1, %2, %0;" : "+l"(d) : "l"(a), "l"(b));
}
__device__ __forceinline__ void unpack2(unsigned long long v, float& lo, float& hi) {
    unsigned int l, h;
    asm("mov.b64 {%0,%1}, %2;" : "=r"(l), "=r"(h) : "l"(v));
    lo = __uint_as_float(l);
    hi = __uint_as_float(h);
}

__device__ __forceinline__ uint32_t smem_u32(const void* p) {
    uint32_t a;
    asm("{ .reg .u64 t; cvta.to.shared.u64 t, %1; cvt.u32.u64 %0, t; }" : "=r"(a) : "l"(p));
    return a;
}

__device__ __forceinline__ void ldsm4(uint32_t* r, uint32_t addr) {
    asm volatile("ldmatrix.sync.aligned.m8n8.x4.shared.b16 {%0,%1,%2,%3}, [%4];"
                 : "=r"(r[0]), "=r"(r[1]), "=r"(r[2]), "=r"(r[3]) : "r"(addr));
}
__device__ __forceinline__ void ldsm2(uint32_t* r, uint32_t addr) {
    asm volatile("ldmatrix.sync.aligned.m8n8.x2.shared.b16 {%0,%1}, [%2];"
                 : "=r"(r[0]), "=r"(r[1]) : "r"(addr));
}

__device__ __forceinline__ void mma_bf16(float* d, const uint32_t* a, const uint32_t* b) {
    asm volatile(
        "mma.sync.aligned.m16n8k16.row.col.f32.bf16.bf16.f32 "
        "{%0,%1,%2,%3}, {%4,%5,%6,%7}, {%8,%9}, {%0,%1,%2,%3};"
        : "+f"(d[0]), "+f"(d[1]), "+f"(d[2]), "+f"(d[3])
        : "r"(a[0]), "r"(a[1]), "r"(a[2]), "r"(a[3]), "r"(b[0]), "r"(b[1]));
}

__device__ __forceinline__ uint32_t bfp(float a, float b) {
    __nv_bfloat162 t = __floats2bfloat162_rn(a, b);
    return *reinterpret_cast<uint32_t*>(&t);
}

// ---------------- zero scratch ----------------
__global__ void k_zero() {
    size_t i0 = (size_t)blockIdx.x * blockDim.x + threadIdx.x;
    size_t stride = (size_t)gridDim.x * blockDim.x;
    float4* r = reinterpret_cast<float4*>(g_reduced);
    size_t n4 = (size_t)NEDGE * EDIM / 4;
    for (size_t i = i0; i < n4; i += stride) r[i] = make_float4(0.f, 0.f, 0.f, 0.f);
    float4* m = reinterpret_cast<float4*>(g_msg);
    size_t m4 = (size_t)NLOC * NDIM / 4;
    for (size_t i = i0; i < m4; i += stride) m[i] = make_float4(0.f, 0.f, 0.f, 0.f);
    if (i0 < NLOC) g_ecnt[i0] = 0;
}

// ---------------- CSR build ----------------
__global__ void k_count(const int* __restrict__ n2e) {
    int e = blockIdx.x * blockDim.x + threadIdx.x;
    if (e < NEDGE) atomicAdd(&g_ecnt[n2e[e]], 1);
}

__global__ void k_scan() {
    __shared__ int sh[1024];
    int t = threadIdx.x;
    int c[4];
#pragma unroll
    for (int i = 0; i < 4; i++) c[i] = g_ecnt[t * 4 + i];
    int tot = c[0] + c[1] + c[2] + c[3];
    sh[t] = tot;
    __syncthreads();
    for (int st = 1; st < 1024; st <<= 1) {
        int add = (t >= st) ? sh[t - st] : 0;
        __syncthreads();
        sh[t] += add;
        __syncthreads();
    }
    int run = sh[t] - tot;
#pragma unroll
    for (int i = 0; i < 4; i++) {
        g_eoff[t * 4 + i] = run;
        g_ecur[t * 4 + i] = run;
        run += c[i];
    }
    if (t == 1023) g_eoff[NLOC] = run;
}

__global__ void k_scatter(const int* __restrict__ n2e) {
    int e = blockIdx.x * blockDim.x + threadIdx.x;
    if (e < NEDGE) {
        int n = n2e[e];
        int pos = atomicAdd(&g_ecur[n], 1);
        g_eids[pos] = e;
        g_enode[pos] = n;
    }
}

// ---------------- sym op ----------------
__global__ void k_sym(const float* __restrict__ edge_ebd, const float* __restrict__ node_ext,
                      const float* __restrict__ h2, const float* __restrict__ sw,
                      const int* __restrict__ n_ext2e) {
    __shared__ float S0[192], S1[192], S2[192];
    __shared__ float symv[768];
    int n = blockIdx.x;
    int t = threadIdx.x;
    int beg = g_eoff[n], end = g_eoff[n + 1];
    float a0 = 0.f, a1 = 0.f, a2 = 0.f;
    for (int i = beg; i < end; i++) {
        int e = g_eids[i];
        float swv = sw[e];
        float h0 = h2[e * 3 + 0] * swv;
        float h1 = h2[e * 3 + 1] * swv;
        float hh = h2[e * 3 + 2] * swv;
        float val = (t < 64) ? edge_ebd[(size_t)e * EDIM + t]
                             : node_ext[(size_t)n_ext2e[e] * NDIM + (t - 64)];
        a0 += h0 * val;
        a1 += h1 * val;
        a2 += hh * val;
    }
    S0[t] = a0; S1[t] = a1; S2[t] = a2;
    __syncthreads();
    if (t < 64) {
#pragma unroll
        for (int a = 0; a < 4; a++)
            symv[a * 64 + t] = SYM_SCALE * (S0[a] * S0[t] + S1[a] * S1[t] + S2[a] * S2[t]);
    } else {
        int dn = t - 64;
#pragma unroll
        for (int a = 0; a < 4; a++)
            symv[256 + a * 128 + dn] =
                SYM_SCALE * (S0[64 + a] * S0[t] + S1[64 + a] * S1[t] + S2[64 + a] * S2[t]);
    }
    __syncthreads();
    for (int idx = t; idx < 768; idx += 192) g_sym[(size_t)n * 768 + idx] = symv[idx];
}

// ---------------- node_sym GEMM fused with node_self ----------------
__global__ __launch_bounds__(256) void k_symmm(
    const float* __restrict__ W_sym, const float* __restrict__ b_sym,
    const float* __restrict__ n_res1,
    const float* __restrict__ W_self, const float* __restrict__ b_self,
    const float* __restrict__ n_res0,
    const float* __restrict__ node_ext, float* __restrict__ out_node) {
    __shared__ float Wt[32 * 128];
    __shared__ float At[32 * 72];
    int tid = threadIdx.x;
    int jt = tid & 31, mt = tid >> 5;
    int n0 = blockIdx.x * 64;
    float acc0[8][4], acc1[8][4];
#pragma unroll
    for (int i = 0; i < 8; i++)
#pragma unroll
        for (int q = 0; q < 4; q++) { acc0[i][q] = 0.f; acc1[i][q] = 0.f; }

    for (int kt = 0; kt < 768; kt += 32) {
        for (int idx = tid; idx < 32 * 128; idx += 256)
            Wt[idx] = W_sym[(size_t)(kt + idx / 128) * 128 + (idx % 128)];
        for (int idx = tid; idx < 32 * 64; idx += 256) {
            int m = idx / 32, k = idx % 32;
            At[k * 72 + m] = g_sym[(size_t)(n0 + m) * 768 + kt + k];
        }
        __syncthreads();
#pragma unroll 4
        for (int k = 0; k < 32; k++) {
            float4 A0 = *reinterpret_cast<const float4*>(&At[k * 72 + mt * 8]);
            float4 A1 = *reinterpret_cast<const float4*>(&At[k * 72 + mt * 8 + 4]);
            float am[8] = {A0.x, A0.y, A0.z, A0.w, A1.x, A1.y, A1.z, A1.w};
            float4 wv = *reinterpret_cast<const float4*>(&Wt[k * 128 + jt * 4]);
            float wq[4] = {wv.x, wv.y, wv.z, wv.w};
#pragma unroll
            for (int i = 0; i < 8; i++)
#pragma unroll
                for (int q = 0; q < 4; q++) acc0[i][q] += am[i] * wq[q];
        }
        __syncthreads();
    }
    for (int kt = 0; kt < 128; kt += 32) {
        for (int idx = tid; idx < 32 * 128; idx += 256)
            Wt[idx] = W_self[(size_t)(kt + idx / 128) * 128 + (idx % 128)];
        for (int idx = tid; idx < 32 * 64; idx += 256) {
            int m = idx / 32, k = idx % 32;
            At[k * 72 + m] = node_ext[(size_t)(n0 + m) * NDIM + kt + k];
        }
        __syncthreads();
#pragma unroll 4
        for (int k = 0; k < 32; k++) {
            float4 A0 = *reinterpret_cast<const float4*>(&At[k * 72 + mt * 8]);
            float4 A1 = *reinterpret_cast<const float4*>(&At[k * 72 + mt * 8 + 4]);
            float am[8] = {A0.x, A0.y, A0.z, A0.w, A1.x, A1.y, A1.z, A1.w};
            float4 wv = *reinterpret_cast<const float4*>(&Wt[k * 128 + jt * 4]);
            float wq[4] = {wv.x, wv.y, wv.z, wv.w};
#pragma unroll
            for (int i = 0; i < 8; i++)
#pragma unroll
                for (int q = 0; q < 4; q++) acc1[i][q] += am[i] * wq[q];
        }
        __syncthreads();
    }
#pragma unroll
    for (int i = 0; i < 8; i++) {
        int n = n0 + mt * 8 + i;
#pragma unroll
        for (int q = 0; q < 4; q++) {
            int j = jt * 4 + q;
            float y1 = silu_f(acc0[i][q] + b_sym[j]);
            float y0 = silu_f(acc1[i][q] + b_self[j]);
            out_node[(size_t)n * 128 + j] =
                node_ext[(size_t)n * NDIM + j] + n_res0[j] * y0 + n_res1[j] * y1;
        }
    }
}

// ---------------- base precompute (edge kernel, 192 cols) ----------------
__global__ __launch_bounds__(256) void k_base(const float* __restrict__ node_ext,
                                              const float* __restrict__ W_ne,
                                              const float* __restrict__ W_es,
                                              const float* __restrict__ b_ne,
                                              const float* __restrict__ b_es) {
    __shared__ float Wt[32 * 192];
    __shared__ float At[32 * 72];
    int tid = threadIdx.x;
    int jt = tid & 31, mt = tid >> 5;
    int n0 = blockIdx.x * 64;
    float acc[8][6];
#pragma unroll
    for (int i = 0; i < 8; i++)
#pragma unroll
        for (int c = 0; c < 6; c++) acc[i][c] = 0.f;
    for (int kt = 0; kt < 128; kt += 32) {
        for (int idx = tid; idx < 32 * 192; idx += 256) {
            int k = idx / 192, j = idx % 192;
            int row = kt + k;
            Wt[idx] = (j < 128) ? W_ne[(size_t)row * 128 + j] : W_es[(size_t)row * 64 + (j - 128)];
        }
        for (int idx = tid; idx < 32 * 64; idx += 256) {
            int m = idx / 32, k = idx % 32;
            At[k * 72 + m] = node_ext[(size_t)(n0 + m) * NDIM + kt + k];
        }
        __syncthreads();
#pragma unroll 2
        for (int k = 0; k < 32; k++) {
            float4 A0 = *reinterpret_cast<const float4*>(&At[k * 72 + mt * 8]);
            float4 A1 = *reinterpret_cast<const float4*>(&At[k * 72 + mt * 8 + 4]);
            float am[8] = {A0.x, A0.y, A0.z, A0.w, A1.x, A1.y, A1.z, A1.w};
#pragma unroll
            for (int c = 0; c < 6; c++) {
                float w = Wt[k * 192 + jt + 32 * c];
#pragma unroll
                for (int i = 0; i < 8; i++) acc[i][c] += am[i] * w;
            }
        }
        __syncthreads();
    }
#pragma unroll
    for (int i = 0; i < 8; i++) {
        int n = n0 + mt * 8 + i;
#pragma unroll
        for (int c = 0; c < 6; c++) {
            int j = jt + 32 * c;
            float bb = (j < 128) ? b_ne[j] : b_es[j - 128];
            g_base[(size_t)n * 192 + j] = acc[i][c] + bb;
        }
    }
}

// ---------------- nbase precompute (angle kernel, 96 cols) ----------------
__global__ __launch_bounds__(256) void k_nbase(const float* __restrict__ node_ext,
                                               const float* __restrict__ W_ea1,
                                               const float* __restrict__ W_as,
                                               const float* __restrict__ b_ea1,
                                               const float* __restrict__ b_as) {
    __shared__ float Wt[32 * 96];
    __shared__ float At[32 * 72];
    int tid = threadIdx.x;
    int jt = tid & 31, mt = tid >> 5;
    int n0 = blockIdx.x * 64;
    float acc[8][3];
#pragma unroll
    for (int i = 0; i < 8; i++)
#pragma unroll
        for (int c = 0; c < 3; c++) acc[i][c] = 0.f;
    for (int kt = 0; kt < 128; kt += 32) {
        for (int idx = tid; idx < 32 * 96; idx += 256) {
            int k = idx / 96, j = idx % 96;
            int row = 32 + kt + k;
            Wt[idx] = (j < 64) ? W_ea1[(size_t)row * 64 + j] : W_as[(size_t)row * 32 + (j - 64)];
        }
        for (int idx = tid; idx < 32 * 64; idx += 256) {
            int m = idx / 32, k = idx % 32;
            At[k * 72 + m] = node_ext[(size_t)(n0 + m) * NDIM + kt + k];
        }
        __syncthreads();
#pragma unroll 2
        for (int k = 0; k < 32; k++) {
            float4 A0 = *reinterpret_cast<const float4*>(&At[k * 72 + mt * 8]);
            float4 A1 = *reinterpret_cast<const float4*>(&At[k * 72 + mt * 8 + 4]);
            float am[8] = {A0.x, A0.y, A0.z, A0.w, A1.x, A1.y, A1.z, A1.w};
#pragma unroll
            for (int c = 0; c < 3; c++) {
                float w = Wt[k * 96 + jt + 32 * c];
#pragma unroll
                for (int i = 0; i < 8; i++) acc[i][c] += am[i] * w;
            }
        }
        __syncthreads();
    }
#pragma unroll
    for (int i = 0; i < 8; i++) {
        int n = n0 + mt * 8 + i;
#pragma unroll
        for (int c = 0; c < 3; c++) {
            int j = jt + 32 * c;
            float bb = (j < 64) ? b_ea1[j] : b_as[j - 64];
            g_nbase[(size_t)n * 96 + j] = acc[i][c] + bb;
        }
    }
}

// ================= edge GEMM via mma.sync bf16 3-term split =================
#define ET_WH 0
#define ET_WL 76800
#define ET_AH 153600
#define ET_AL 179200
#define ET_IDX 204800
#define ET_SMEM 205568

__global__ __launch_bounds__(512, 1) void k_edge_tc(
    const float* __restrict__ node_ext, const float* __restrict__ edge_ebd,
    const float* __restrict__ sw, const int* __restrict__ n_ext2e,
    const float* __restrict__ W_ne, const float* __restrict__ W_es,
    const float* __restrict__ e_res0, float* __restrict__ out_edge) {
    extern __shared__ char smc[];
    uint32_t sb = smem_u32(smc);
    int tid = threadIdx.x;
    int wid = tid >> 5;
    int lane = tid & 31;
    int wm = wid >> 2;
    int wn = wid & 3;

    int* eidv = (int*)(smc + ET_IDX);
    int* nodev = eidv + 64;
    float* sws = (float*)(nodev + 64);

    for (int idx = tid; idx < 192 * 192; idx += 512) {
        int k = idx / 192, j = idx % 192;
        float w = (j < 128) ? W_ne[(size_t)(128 + k) * 128 + j]
                            : W_es[(size_t)(128 + k) * 64 + (j - 128)];
        __nv_bfloat16 h = __float2bfloat16(w);
        float l = w - __bfloat162float(h);
        *reinterpret_cast<__nv_bfloat16*>(smc + ET_WH + (j * 200 + k) * 2) = h;
        *reinterpret_cast<__nv_bfloat16*>(smc + ET_WL + (j * 200 + k) * 2) = __float2bfloat16(l);
    }

    uint32_t aRow = wm * 16 + (lane & 15);
    uint32_t aColH = (lane >> 4);
    uint32_t aAddrH = sb + ET_AH + (aRow * 200 + aColH * 8) * 2;
    uint32_t aAddrL = sb + ET_AL + (aRow * 200 + aColH * 8) * 2;
    int nrow = wn * 48 + (lane & 7) + ((lane & 16) ? 8 : 0);
    int khalf = (lane & 8) ? 8 : 0;
    uint32_t bAddrH = sb + ET_WH + (nrow * 200 + khalf) * 2;
    uint32_t bAddrL = sb + ET_WL + (nrow * 200 + khalf) * 2;

    int mfill = tid & 63;
    int seg = tid >> 6;

    for (int ch = blockIdx.x; ch < NEDGE / 64; ch += gridDim.x) {
        int c0 = ch * 64;
        __syncthreads();
        if (tid < 64) {
            int e = g_eids[c0 + tid];
            eidv[tid] = e;
            nodev[tid] = g_enode[c0 + tid];
            sws[tid] = sw[e];
        }
        {
            int e = __ldg(&g_eids[c0 + mfill]);
            int nd = __ldg(&n_ext2e[e]);
            const float4* nrowp = (const float4*)(node_ext + (size_t)nd * NDIM);
            const float4* erowp = (const float4*)(edge_ebd + (size_t)e * EDIM);
            uint32_t rowoff = (uint32_t)mfill * 200;
#pragma unroll
            for (int q = 0; q < 6; q++) {
                int kk = seg * 24 + q * 4;
                float4 v = (kk < 128) ? nrowp[kk >> 2] : erowp[(kk - 128) >> 2];
                __nv_bfloat16 h0 = __float2bfloat16(v.x);
                __nv_bfloat16 h1 = __float2bfloat16(v.y);
                __nv_bfloat16 h2 = __float2bfloat16(v.z);
                __nv_bfloat16 h3 = __float2bfloat16(v.w);
                uint32_t hi01, hi23;
                { __nv_bfloat162 t; t.x = h0; t.y = h1; hi01 = *reinterpret_cast<uint32_t*>(&t); }
                { __nv_bfloat162 t; t.x = h2; t.y = h3; hi23 = *reinterpret_cast<uint32_t*>(&t); }
                uint32_t lo01 = bfp(v.x - __bfloat162float(h0), v.y - __bfloat162float(h1));
                uint32_t lo23 = bfp(v.z - __bfloat162float(h2), v.w - __bfloat162float(h3));
                uint32_t boff = (rowoff + kk) * 2;
                *reinterpret_cast<uint32_t*>(smc + ET_AH + boff) = hi01;
                *reinterpret_cast<uint32_t*>(smc + ET_AH + boff + 4) = hi23;
                *reinterpret_cast<uint32_t*>(smc + ET_AL + boff) = lo01;
                *reinterpret_cast<uint32_t*>(smc + ET_AL + boff + 4) = lo23;
            }
        }
        __syncthreads();

        float d[6][4];
#pragma unroll
        for (int nt = 0; nt < 6; nt++)
#pragma unroll
            for (int q = 0; q < 4; q++) d[nt][q] = 0.f;

#pragma unroll
        for (int s = 0; s < 12; s++) {
            uint32_t ah[4], al[4];
            ldsm4(ah, aAddrH + s * 32);
            ldsm4(al, aAddrL + s * 32);
#pragma unroll
            for (int pr = 0; pr < 3; pr++) {
                uint32_t bh[4], bl[4];
                ldsm4(bh, bAddrH + pr * 16 * 400 + s * 32);
                ldsm4(bl, bAddrL + pr * 16 * 400 + s * 32);
                mma_bf16(d[pr * 2], ah, bh);
                mma_bf16(d[pr * 2], ah, bl);
                mma_bf16(d[pr * 2], al, bh);
                mma_bf16(d[pr * 2 + 1], ah, bh + 2);
                mma_bf16(d[pr * 2 + 1], ah, bl + 2);
                mma_bf16(d[pr * 2 + 1], al, bh + 2);
            }
        }

        int g = lane >> 2, qt = lane & 3;
        int r0 = wm * 16 + g, r1 = r0 + 8;
        int nd0 = nodev[r0], nd1 = nodev[r1];
        float sw0 = sws[r0], sw1 = sws[r1];
        int ee0 = eidv[r0], ee1 = eidv[r1];
        bool samend = (nd0 == nd1);
#pragma unroll
        for (int nt = 0; nt < 6; nt++) {
            int j0 = wn * 48 + nt * 8 + qt * 2;
            float2 b0v = *(const float2*)(g_base + (size_t)nd0 * 192 + j0);
            float2 b1v = *(const float2*)(g_base + (size_t)nd1 * 192 + j0);
            float y00 = silu_f(d[nt][0] + b0v.x);
            float y01 = silu_f(d[nt][1] + b0v.y);
            float y10 = silu_f(d[nt][2] + b1v.x);
            float y11 = silu_f(d[nt][3] + b1v.y);
            if (j0 < 128) {
                float v00 = y00 * sw0, v01 = y01 * sw0;
                float v10 = y10 * sw1, v11 = y11 * sw1;
                if (samend) {
                    atomicAdd(&g_msg[(size_t)nd0 * NDIM + j0], v00 + v10);
                    atomicAdd(&g_msg[(size_t)nd0 * NDIM + j0 + 1], v01 + v11);
                } else {
                    atomicAdd(&g_msg[(size_t)nd0 * NDIM + j0], v00);
                    atomicAdd(&g_msg[(size_t)nd0 * NDIM + j0 + 1], v01);
                    atomicAdd(&g_msg[(size_t)nd1 * NDIM + j0], v10);
                    atomicAdd(&g_msg[(size_t)nd1 * NDIM + j0 + 1], v11);
                }
            } else {
                int col = j0 - 128;
                float2 er = *(const float2*)(e_res0 + col);
                size_t o0 = (size_t)ee0 * EDIM + col;
                size_t o1 = (size_t)ee1 * EDIM + col;
                float2 eb0 = *(const float2*)(edge_ebd + o0);
                float2 eb1 = *(const float2*)(edge_ebd + o1);
                *(float2*)(out_edge + o0) = make_float2(eb0.x + er.x * y00, eb0.y + er.y * y01);
                *(float2*)(out_edge + o1) = make_float2(eb1.x + er.x * y10, eb1.y + er.y * y11);
            }
        }
    }
}

__global__ void k_node_finish(const float* __restrict__ n_res2, float* __restrict__ out_node) {
    int i = blockIdx.x * blockDim.x + threadIdx.x;
    if (i < NLOC * NDIM) {
        int j = i & (NDIM - 1);
        out_node[i] += n_res2[j] * g_msg[i] * INV_DYN_E;
    }
}

// ================= angle GEMM via mma.sync bf16 3-term split =================
// M=64 angles/tile, K=160, N=96. Warp grid 4x4, warp = 16 rows x 24 cols.
// halves stride 168 (336B rows, 16B-aligned, conflict-free ldmatrix).
#define AT_WH 0
#define AT_WL 32256
#define AT_AH 64512
#define AT_AL 86016
#define AT_IDX 107520
#define AT_SMEM 108288

__global__ __launch_bounds__(512, 2) void k_angle_tc(
    const float* __restrict__ angle_ebd, const float* __restrict__ edge_ebd,
    const int* __restrict__ ai, const float* __restrict__ a_sw,
    const float* __restrict__ W_ea1, const float* __restrict__ W_as,
    const float* __restrict__ a_res0, float* __restrict__ out_angle) {
    extern __shared__ char smc[];
    uint32_t sb = smem_u32(smc);
    int tid = threadIdx.x;
    int wid = tid >> 5;
    int lane = tid & 31;
    int wm = wid >> 2;
    int wn = wid & 3;

    int* nav = (int*)(smc + AT_IDX);
    int* ijav = nav + 64;
    float* aswv = (float*)(ijav + 64);

    const int* n2a = ai;
    const int* eij = ai + NANGLE;
    const int* eik = ai + 2 * NANGLE;

    // weights bf16 hi/lo, [n=96][k=160] stride 168
    for (int idx = tid; idx < 96 * 160; idx += 512) {
        int j = idx / 160, k = idx % 160;
        int srck = (k < 32) ? k : ((k < 96) ? 160 + (k - 32) : 224 + (k - 96));
        float w = (j < 64) ? W_ea1[(size_t)srck * 64 + j] : W_as[(size_t)srck * 32 + (j - 64)];
        __nv_bfloat16 h = __float2bfloat16(w);
        float l = w - __bfloat162float(h);
        *reinterpret_cast<__nv_bfloat16*>(smc + AT_WH + (j * 168 + k) * 2) = h;
        *reinterpret_cast<__nv_bfloat16*>(smc + AT_WL + (j * 168 + k) * 2) = __float2bfloat16(l);
    }

    uint32_t aRow = wm * 16 + (lane & 15);
    uint32_t aColH = (lane >> 4);
    uint32_t aAddrH = sb + AT_AH + (aRow * 168 + aColH * 8) * 2;
    uint32_t aAddrL = sb + AT_AL + (aRow * 168 + aColH * 8) * 2;
    int nrow = wn * 24 + (lane & 7) + ((lane & 16) ? 8 : 0);
    int khalf = (lane & 8) ? 8 : 0;
    uint32_t bAddrH = sb + AT_WH + (nrow * 168 + khalf) * 2;
    uint32_t bAddrL = sb + AT_WL + (nrow * 168 + khalf) * 2;
    int nrow2 = wn * 24 + 16 + (lane & 7);
    int khalf2 = (lane & 8) ? 8 : 0;
    uint32_t b2AddrH = sb + AT_WH + (nrow2 * 168 + khalf2) * 2;
    uint32_t b2AddrL = sb + AT_WL + (nrow2 * 168 + khalf2) * 2;

    int mfill = tid & 63;
    int seg = tid >> 6;   // 0..7 -> k range seg*20..+20

    for (int t = blockIdx.x; t < NANGLE / 64; t += gridDim.x) {
        int a0 = t * 64;
        __syncthreads();
        if (tid < 64) {
            nav[tid] = n2a[a0 + tid];
            ijav[tid] = eij[a0 + tid];
            aswv[tid] = a_sw[a0 + tid];
        }
        {
            int a = a0 + mfill;
            int ek = __ldg(&eik[a]);
            int ej = __ldg(&eij[a]);
            const float4* arow = (const float4*)(angle_ebd + (size_t)a * ADIM);
            const float4* krow = (const float4*)(edge_ebd + (size_t)ek * EDIM);
            const float4* jrow = (const float4*)(edge_ebd + (size_t)ej * EDIM);
            uint32_t rowoff = (uint32_t)mfill * 168;
#pragma unroll
            for (int q = 0; q < 5; q++) {
                int kk = seg * 20 + q * 4;
                float4 v = (kk < 32) ? arow[kk >> 2]
                         : (kk < 96) ? krow[(kk - 32) >> 2]
                                     : jrow[(kk - 96) >> 2];
                __nv_bfloat16 h0 = __float2bfloat16(v.x);
                __nv_bfloat16 h1 = __float2bfloat16(v.y);
                __nv_bfloat16 h2 = __float2bfloat16(v.z);
                __nv_bfloat16 h3 = __float2bfloat16(v.w);
                uint32_t hi01, hi23;
                { __nv_bfloat162 tt; tt.x = h0; tt.y = h1; hi01 = *reinterpret_cast<uint32_t*>(&tt); }
                { __nv_bfloat162 tt; tt.x = h2; tt.y = h3; hi23 = *reinterpret_cast<uint32_t*>(&tt); }
                uint32_t lo01 = bfp(v.x - __bfloat162float(h0), v.y - __bfloat162float(h1));
                uint32_t lo23 = bfp(v.z - __bfloat162float(h2), v.w - __bfloat162float(h3));
                uint32_t boff = (rowoff + kk) * 2;
                *reinterpret_cast<uint32_t*>(smc + AT_AH + boff) = hi01;
                *reinterpret_cast<uint32_t*>(smc + AT_AH + boff + 4) = hi23;
                *reinterpret_cast<uint32_t*>(smc + AT_AL + boff) = lo01;
                *reinterpret_cast<uint32_t*>(smc + AT_AL + boff + 4) = lo23;
            }
        }
        __syncthreads();

        float d[3][4];
#pragma unroll
        for (int nt = 0; nt < 3; nt++)
#pragma unroll
            for (int q = 0; q < 4; q++) d[nt][q] = 0.f;

#pragma unroll
        for (int s = 0; s < 10; s++) {
            uint32_t ah[4], al[4];
            ldsm4(ah, aAddrH + s * 32);
            ldsm4(al, aAddrL + s * 32);
            uint32_t bh[4], bl[4], b2h[2], b2l[2];
            ldsm4(bh, bAddrH + s * 32);
            ldsm4(bl, bAddrL + s * 32);
            ldsm2(b2h, b2AddrH + s * 32);
            ldsm2(b2l, b2AddrL + s * 32);
            mma_bf16(d[0], ah, bh);
            mma_bf16(d[0], ah, bl);
            mma_bf16(d[0], al, bh);
            mma_bf16(d[1], ah, bh + 2);
            mma_bf16(d[1], ah, bl + 2);
            mma_bf16(d[1], al, bh + 2);
            mma_bf16(d[2], ah, b2h);
            mma_bf16(d[2], ah, b2l);
            mma_bf16(d[2], al, b2h);
        }

        int g = lane >> 2, qt = lane & 3;
        int r0 = wm * 16 + g, r1 = r0 + 8;
        int nd0 = nav[r0], nd1 = nav[r1];
        float sw0 = aswv[r0], sw1 = aswv[r1];
        int ij0 = ijav[r0], ij1 = ijav[r1];
#pragma unroll
        for (int nt = 0; nt < 3; nt++) {
            int j0 = wn * 24 + nt * 8 + qt * 2;
            float2 nb0 = *(const float2*)(g_nbase + (size_t)nd0 * 96 + j0);
            float2 nb1 = *(const float2*)(g_nbase + (size_t)nd1 * 96 + j0);
            float y00 = silu_f(d[nt][0] + nb0.x);
            float y01 = silu_f(d[nt][1] + nb0.y);
            float y10 = silu_f(d[nt][2] + nb1.x);
            float y11 = silu_f(d[nt][3] + nb1.y);
            if (j0 < 64) {
                atomicAdd(&g_reduced[(size_t)ij0 * EDIM + j0], y00 * sw0);
                atomicAdd(&g_reduced[(size_t)ij0 * EDIM + j0 + 1], y01 * sw0);
                atomicAdd(&g_reduced[(size_t)ij1 * EDIM + j0], y10 * sw1);
                atomicAdd(&g_reduced[(size_t)ij1 * EDIM + j0 + 1], y11 * sw1);
            } else {
                int col = j0 - 64;
                float2 arr = *(const float2*)(a_res0 + col);
                size_t o0 = (size_t)(a0 + r0) * ADIM + col;
                size_t o1 = (size_t)(a0 + r1) * ADIM + col;
                float2 ae0 = *(const float2*)(angle_ebd + o0);
                float2 ae1 = *(const float2*)(angle_ebd + o1);
                *(float2*)(out_angle + o0) = make_float2(ae0.x + arr.x * y00, ae0.y + arr.y * y01);
                *(float2*)(out_angle + o1) = make_float2(ae1.x + arr.x * y10, ae1.y + arr.y * y11);
            }
        }
    }
}

// ---------------- edge angle message GEMM (f32x2) ----------------
__global__ __launch_bounds__(256) void k_edge_msg(const float* __restrict__ W2,
                                                  const float* __restrict__ b2,
                                                  const float* __restrict__ e_res1,
                                                  float* __restrict__ out_edge) {
    __shared__ float Ws[64 * 64];
    __shared__ float At[64 * 68];
    int tid = threadIdx.x;
    int jt = tid & 31, mt = tid >> 5;
    int e0 = blockIdx.x * 64;
    for (int idx = tid; idx < 64 * 64; idx += 256) Ws[idx] = W2[idx];
    for (int idx = tid; idx < 64 * 64; idx += 256) {
        int m = idx >> 6, k = idx & 63;
        At[k * 68 + m] = g_reduced[(size_t)(e0 + m) * EDIM + k];
    }
    __syncthreads();
    unsigned long long acc[4][2];
#pragma unroll
    for (int i = 0; i < 4; i++) { acc[i][0] = 0ULL; acc[i][1] = 0ULL; }
#pragma unroll 4
    for (int k = 0; k < 64; k++) {
        ulonglong2 A0 = *reinterpret_cast<const ulonglong2*>(&At[k * 68 + mt * 8]);
        ulonglong2 A1 = *reinterpret_cast<const ulonglong2*>(&At[k * 68 + mt * 8 + 4]);
        unsigned long long w0 = pack2(Ws[k * 64 + jt]);
        unsigned long long w1 = pack2(Ws[k * 64 + jt + 32]);
        ffma2(acc[0][0], A0.x, w0); ffma2(acc[0][1], A0.x, w1);
        ffma2(acc[1][0], A0.y, w0); ffma2(acc[1][1], A0.y, w1);
        ffma2(acc[2][0], A1.x, w0); ffma2(acc[2][1], A1.x, w1);
        ffma2(acc[3][0], A1.y, w0); ffma2(acc[3][1], A1.y, w1);
    }
    float bb0 = b2[jt], bb1 = b2[jt + 32];
    float er0 = e_res1[jt], er1 = e_res1[jt + 32];
#pragma unroll
    for (int i = 0; i < 4; i++) {
#pragma unroll
        for (int q = 0; q < 2; q++) {
            float lo, hi;
            unpack2(acc[i][q], lo, hi);
            int j = (q == 0) ? jt : jt + 32;
            float bb = (q == 0) ? bb0 : bb1;
            float er = (q == 0) ? er0 : er1;
            int ea = e0 + mt * 8 + 2 * i;
            int eb = ea + 1;
            out_edge[(size_t)ea * EDIM + j] += er * silu_f(lo + bb);
            out_edge[(size_t)eb * EDIM + j] += er * silu_f(hi + bb);
        }
    }
}

// ---------------- launch ----------------
extern "C" void kernel_launch(void* const* d_in, const int* in_sizes, int n_in,
                              void* d_out, int out_size) {
    const float* node_ext   = (const float*)d_in[0];
    const float* edge_ebd   = (const float*)d_in[1];
    const float* h2         = (const float*)d_in[2];
    const float* angle_ebd  = (const float*)d_in[3];
    const float* sw         = (const float*)d_in[6];
    const float* a_sw       = (const float*)d_in[9];
    const int*   edge_index = (const int*)d_in[10];
    const int*   angle_index= (const int*)d_in[11];
    const float* W_node_self = (const float*)d_in[12];
    const float* b_node_self = (const float*)d_in[13];
    const float* W_node_sym  = (const float*)d_in[14];
    const float* b_node_sym  = (const float*)d_in[15];
    const float* W_node_edge = (const float*)d_in[16];
    const float* b_node_edge = (const float*)d_in[17];
    const float* W_edge_self = (const float*)d_in[18];
    const float* b_edge_self = (const float*)d_in[19];
    const float* W_edge_angle1 = (const float*)d_in[20];
    const float* b_edge_angle1 = (const float*)d_in[21];
    const float* W_edge_angle2 = (const float*)d_in[22];
    const float* b_edge_angle2 = (const float*)d_in[23];
    const float* W_angle_self  = (const float*)d_in[24];
    const float* b_angle_self  = (const float*)d_in[25];
    const float* n_res0 = (const float*)d_in[26];
    const float* n_res1 = (const float*)d_in[27];
    const float* n_res2 = (const float*)d_in[28];
    const float* e_res0 = (const float*)d_in[29];
    const float* e_res1 = (const float*)d_in[30];
    const float* a_res0 = (const float*)d_in[31];

    float* out = (float*)d_out;
    float* out_node  = out;
    float* out_edge  = out + (size_t)NLOC * NDIM;
    float* out_angle = out_edge + (size_t)NEDGE * EDIM;

    const int* n2e = edge_index;
    const int* n_ext2e = edge_index + NEDGE;

    cudaFuncSetAttribute((const void*)k_edge_tc,
                         cudaFuncAttributeMaxDynamicSharedMemorySize, ET_SMEM);
    cudaFuncSetAttribute((const void*)k_angle_tc,
                         cudaFuncAttributeMaxDynamicSharedMemorySize, AT_SMEM);

    k_zero<<<4096, 256>>>();
    k_count<<<NEDGE / 256, 256>>>(n2e);
    k_scan<<<1, 1024>>>();
    k_scatter<<<NEDGE / 256, 256>>>(n2e);
    k_sym<<<NLOC, 192>>>(edge_ebd, node_ext, h2, sw, n_ext2e);
    k_symmm<<<NLOC / 64, 256>>>(W_node_sym, b_node_sym, n_res1,
                                W_node_self, b_node_self, n_res0, node_ext, out_node);
    k_base<<<NLOC / 64, 256>>>(node_ext, W_node_edge, W_edge_self, b_node_edge, b_edge_self);
    k_nbase<<<NLOC / 64, 256>>>(node_ext, W_edge_angle1, W_angle_self,
                                b_edge_angle1, b_angle_self);
    k_edge_tc<<<148, 512, ET_SMEM>>>(node_ext, edge_ebd, sw, n_ext2e,
                                     W_node_edge, W_edge_self, e_res0, out_edge);
    k_node_finish<<<NLOC * NDIM / 256, 256>>>(n_res2, out_node);
    k_angle_tc<<<296, 512, AT_SMEM>>>(angle_ebd, edge_ebd, angle_index, a_sw,
                                      W_edge_angle1, W_angle_self, a_res0, out_angle);
    k_edge_msg<<<NEDGE / 64, 256>>>(W_edge_angle2, b_edge_angle2, e_res1, out_edge);
}

// round 11
// speedup vs baseline: 3.7456x; 1.0000x over previous
#include <cuda_runtime.h>
#include <cuda_bf16.h>
#include <cstdint>
#include <cstddef>

#define NLOC   4096
#define NALL   6144
#define NDIM   128
#define EDIM   64
#define ADIM   32
#define NEDGE  262144
#define NANGLE 409600
#define INV_DYN_E 0.15625f            // 1/6.4
#define SYM_SCALE 0.0520833333333f    // (1/6.4)/3

// ---------------- device scratch ----------------
__device__ float g_sym[(size_t)NLOC * 768];
__device__ float g_base[(size_t)NLOC * 192];
__device__ float g_nbase[(size_t)NLOC * 96];
__device__ float g_reduced[(size_t)NEDGE * EDIM];
__device__ float g_msg[(size_t)NLOC * NDIM];
__device__ int   g_ecnt[NLOC];
__device__ int   g_eoff[NLOC + 1];
__device__ int   g_ecur[NLOC];
__device__ int   g_eids[NEDGE];
__device__ int   g_enode[NEDGE];

// ---------------- helpers ----------------
__device__ __forceinline__ float silu_f(float x) { return x / (1.0f + __expf(-x)); }

__device__ __forceinline__ uint32_t smem_u32(const void* p) {
    uint32_t a;
    asm("{ .reg .u64 t; cvta.to.shared.u64 t, %1; cvt.u32.u64 %0, t; }" : "=r"(a) : "l"(p));
    return a;
}

__device__ __forceinline__ void ldsm4(uint32_t* r, uint32_t addr) {
    asm volatile("ldmatrix.sync.aligned.m8n8.x4.shared.b16 {%0,%1,%2,%3}, [%4];"
                 : "=r"(r[0]), "=r"(r[1]), "=r"(r[2]), "=r"(r[3]) : "r"(addr));
}
__device__ __forceinline__ void ldsm2(uint32_t* r, uint32_t addr) {
    asm volatile("ldmatrix.sync.aligned.m8n8.x2.shared.b16 {%0,%1}, [%2];"
                 : "=r"(r[0]), "=r"(r[1]) : "r"(addr));
}

__device__ __forceinline__ void mma_bf16(float* d, const uint32_t* a, const uint32_t* b) {
    asm volatile(
        "mma.sync.aligned.m16n8k16.row.col.f32.bf16.bf16.f32 "
        "{%0,%1,%2,%3}, {%4,%5,%6,%7}, {%8,%9}, {%0,%1,%2,%3};"
        : "+f"(d[0]), "+f"(d[1]), "+f"(d[2]), "+f"(d[3])
        : "r"(a[0]), "r"(a[1]), "r"(a[2]), "r"(a[3]), "r"(b[0]), "r"(b[1]));
}

__device__ __forceinline__ uint32_t bfp(float a, float b) {
    __nv_bfloat162 t = __floats2bfloat162_rn(a, b);
    return *reinterpret_cast<uint32_t*>(&t);
}

// ---------------- zero scratch ----------------
__global__ void k_zero() {
    size_t i0 = (size_t)blockIdx.x * blockDim.x + threadIdx.x;
    size_t stride = (size_t)gridDim.x * blockDim.x;
    float4* r = reinterpret_cast<float4*>(g_reduced);
    size_t n4 = (size_t)NEDGE * EDIM / 4;
    for (size_t i = i0; i < n4; i += stride) r[i] = make_float4(0.f, 0.f, 0.f, 0.f);
    float4* m = reinterpret_cast<float4*>(g_msg);
    size_t m4 = (size_t)NLOC * NDIM / 4;
    for (size_t i = i0; i < m4; i += stride) m[i] = make_float4(0.f, 0.f, 0.f, 0.f);
    if (i0 < NLOC) g_ecnt[i0] = 0;
}

// ---------------- CSR build ----------------
__global__ void k_count(const int* __restrict__ n2e) {
    int e = blockIdx.x * blockDim.x + threadIdx.x;
    if (e < NEDGE) atomicAdd(&g_ecnt[n2e[e]], 1);
}

__global__ void k_scan() {
    __shared__ int sh[1024];
    int t = threadIdx.x;
    int c[4];
#pragma unroll
    for (int i = 0; i < 4; i++) c[i] = g_ecnt[t * 4 + i];
    int tot = c[0] + c[1] + c[2] + c[3];
    sh[t] = tot;
    __syncthreads();
    for (int st = 1; st < 1024; st <<= 1) {
        int add = (t >= st) ? sh[t - st] : 0;
        __syncthreads();
        sh[t] += add;
        __syncthreads();
    }
    int run = sh[t] - tot;
#pragma unroll
    for (int i = 0; i < 4; i++) {
        g_eoff[t * 4 + i] = run;
        g_ecur[t * 4 + i] = run;
        run += c[i];
    }
    if (t == 1023) g_eoff[NLOC] = run;
}

__global__ void k_scatter(const int* __restrict__ n2e) {
    int e = blockIdx.x * blockDim.x + threadIdx.x;
    if (e < NEDGE) {
        int n = n2e[e];
        int pos = atomicAdd(&g_ecur[n], 1);
        g_eids[pos] = e;
        g_enode[pos] = n;
    }
}

// ---------------- sym op: 4-way edge parallelism ----------------
__global__ __launch_bounds__(768) void k_sym(
    const float* __restrict__ edge_ebd, const float* __restrict__ node_ext,
    const float* __restrict__ h2, const float* __restrict__ sw,
    const int* __restrict__ n_ext2e) {
    __shared__ float P[4][3][192];
    __shared__ float S0[192], S1[192], S2[192];
    __shared__ float symv[768];
    int n = blockIdx.x;
    int t = threadIdx.x;
    int g = t / 192;
    int f = t - g * 192;
    int beg = g_eoff[n], end = g_eoff[n + 1];
    float a0 = 0.f, a1 = 0.f, a2 = 0.f;
    for (int i = beg + g; i < end; i += 4) {
        int e = g_eids[i];
        float swv = sw[e];
        float h0 = h2[e * 3 + 0] * swv;
        float h1 = h2[e * 3 + 1] * swv;
        float hh = h2[e * 3 + 2] * swv;
        float val = (f < 64) ? edge_ebd[(size_t)e * EDIM + f]
                             : node_ext[(size_t)n_ext2e[e] * NDIM + (f - 64)];
        a0 += h0 * val;
        a1 += h1 * val;
        a2 += hh * val;
    }
    P[g][0][f] = a0; P[g][1][f] = a1; P[g][2][f] = a2;
    __syncthreads();
    if (t < 192) {
        S0[t] = P[0][0][t] + P[1][0][t] + P[2][0][t] + P[3][0][t];
    } else if (t < 384) {
        int tt = t - 192;
        S1[tt] = P[0][1][tt] + P[1][1][tt] + P[2][1][tt] + P[3][1][tt];
    } else if (t < 576) {
        int tt = t - 384;
        S2[tt] = P[0][2][tt] + P[1][2][tt] + P[2][2][tt] + P[3][2][tt];
    }
    __syncthreads();
    if (t < 64) {
#pragma unroll
        for (int a = 0; a < 4; a++)
            symv[a * 64 + t] = SYM_SCALE * (S0[a] * S0[t] + S1[a] * S1[t] + S2[a] * S2[t]);
    } else if (t < 192) {
        int dn = t - 64;
#pragma unroll
        for (int a = 0; a < 4; a++)
            symv[256 + a * 128 + dn] =
                SYM_SCALE * (S0[64 + a] * S0[t] + S1[64 + a] * S1[t] + S2[64 + a] * S2[t]);
    }
    __syncthreads();
    g_sym[(size_t)n * 768 + t] = symv[t];
}

// ---------------- node_sym GEMM fused with node_self ----------------
__global__ __launch_bounds__(256) void k_symmm(
    const float* __restrict__ W_sym, const float* __restrict__ b_sym,
    const float* __restrict__ n_res1,
    const float* __restrict__ W_self, const float* __restrict__ b_self,
    const float* __restrict__ n_res0,
    const float* __restrict__ node_ext, float* __restrict__ out_node) {
    __shared__ float Wt[32 * 128];
    __shared__ float At[32 * 72];
    int tid = threadIdx.x;
    int jt = tid & 31, mt = tid >> 5;
    int n0 = blockIdx.x * 64;
    float acc0[8][4], acc1[8][4];
#pragma unroll
    for (int i = 0; i < 8; i++)
#pragma unroll
        for (int q = 0; q < 4; q++) { acc0[i][q] = 0.f; acc1[i][q] = 0.f; }

    for (int kt = 0; kt < 768; kt += 32) {
        for (int idx = tid; idx < 32 * 128; idx += 256)
            Wt[idx] = W_sym[(size_t)(kt + idx / 128) * 128 + (idx % 128)];
        for (int idx = tid; idx < 32 * 64; idx += 256) {
            int m = idx / 32, k = idx % 32;
            At[k * 72 + m] = g_sym[(size_t)(n0 + m) * 768 + kt + k];
        }
        __syncthreads();
#pragma unroll 4
        for (int k = 0; k < 32; k++) {
            float4 A0 = *reinterpret_cast<const float4*>(&At[k * 72 + mt * 8]);
            float4 A1 = *reinterpret_cast<const float4*>(&At[k * 72 + mt * 8 + 4]);
            float am[8] = {A0.x, A0.y, A0.z, A0.w, A1.x, A1.y, A1.z, A1.w};
            float4 wv = *reinterpret_cast<const float4*>(&Wt[k * 128 + jt * 4]);
            float wq[4] = {wv.x, wv.y, wv.z, wv.w};
#pragma unroll
            for (int i = 0; i < 8; i++)
#pragma unroll
                for (int q = 0; q < 4; q++) acc0[i][q] += am[i] * wq[q];
        }
        __syncthreads();
    }
    for (int kt = 0; kt < 128; kt += 32) {
        for (int idx = tid; idx < 32 * 128; idx += 256)
            Wt[idx] = W_self[(size_t)(kt + idx / 128) * 128 + (idx % 128)];
        for (int idx = tid; idx < 32 * 64; idx += 256) {
            int m = idx / 32, k = idx % 32;
            At[k * 72 + m] = node_ext[(size_t)(n0 + m) * NDIM + kt + k];
        }
        __syncthreads();
#pragma unroll 4
        for (int k = 0; k < 32; k++) {
            float4 A0 = *reinterpret_cast<const float4*>(&At[k * 72 + mt * 8]);
            float4 A1 = *reinterpret_cast<const float4*>(&At[k * 72 + mt * 8 + 4]);
            float am[8] = {A0.x, A0.y, A0.z, A0.w, A1.x, A1.y, A1.z, A1.w};
            float4 wv = *reinterpret_cast<const float4*>(&Wt[k * 128 + jt * 4]);
            float wq[4] = {wv.x, wv.y, wv.z, wv.w};
#pragma unroll
            for (int i = 0; i < 8; i++)
#pragma unroll
                for (int q = 0; q < 4; q++) acc1[i][q] += am[i] * wq[q];
        }
        __syncthreads();
    }
#pragma unroll
    for (int i = 0; i < 8; i++) {
        int n = n0 + mt * 8 + i;
#pragma unroll
        for (int q = 0; q < 4; q++) {
            int j = jt * 4 + q;
            float y1 = silu_f(acc0[i][q] + b_sym[j]);
            float y0 = silu_f(acc1[i][q] + b_self[j]);
            out_node[(size_t)n * 128 + j] =
                node_ext[(size_t)n * NDIM + j] + n_res0[j] * y0 + n_res1[j] * y1;
        }
    }
}

// ---------------- base precompute (edge kernel, 192 cols) ----------------
__global__ __launch_bounds__(256) void k_base(const float* __restrict__ node_ext,
                                              const float* __restrict__ W_ne,
                                              const float* __restrict__ W_es,
                                              const float* __restrict__ b_ne,
                                              const float* __restrict__ b_es) {
    __shared__ float Wt[32 * 192];
    __shared__ float At[32 * 72];
    int tid = threadIdx.x;
    int jt = tid & 31, mt = tid >> 5;
    int n0 = blockIdx.x * 64;
    float acc[8][6];
#pragma unroll
    for (int i = 0; i < 8; i++)
#pragma unroll
        for (int c = 0; c < 6; c++) acc[i][c] = 0.f;
    for (int kt = 0; kt < 128; kt += 32) {
        for (int idx = tid; idx < 32 * 192; idx += 256) {
            int k = idx / 192, j = idx % 192;
            int row = kt + k;
            Wt[idx] = (j < 128) ? W_ne[(size_t)row * 128 + j] : W_es[(size_t)row * 64 + (j - 128)];
        }
        for (int idx = tid; idx < 32 * 64; idx += 256) {
            int m = idx / 32, k = idx % 32;
            At[k * 72 + m] = node_ext[(size_t)(n0 + m) * NDIM + kt + k];
        }
        __syncthreads();
#pragma unroll 2
        for (int k = 0; k < 32; k++) {
            float4 A0 = *reinterpret_cast<const float4*>(&At[k * 72 + mt * 8]);
            float4 A1 = *reinterpret_cast<const float4*>(&At[k * 72 + mt * 8 + 4]);
            float am[8] = {A0.x, A0.y, A0.z, A0.w, A1.x, A1.y, A1.z, A1.w};
#pragma unroll
            for (int c = 0; c < 6; c++) {
                float w = Wt[k * 192 + jt + 32 * c];
#pragma unroll
                for (int i = 0; i < 8; i++) acc[i][c] += am[i] * w;
            }
        }
        __syncthreads();
    }
#pragma unroll
    for (int i = 0; i < 8; i++) {
        int n = n0 + mt * 8 + i;
#pragma unroll
        for (int c = 0; c < 6; c++) {
            int j = jt + 32 * c;
            float bb = (j < 128) ? b_ne[j] : b_es[j - 128];
            g_base[(size_t)n * 192 + j] = acc[i][c] + bb;
        }
    }
}

// ---------------- nbase precompute (angle kernel, 96 cols) ----------------
__global__ __launch_bounds__(256) void k_nbase(const float* __restrict__ node_ext,
                                               const float* __restrict__ W_ea1,
                                               const float* __restrict__ W_as,
                                               const float* __restrict__ b_ea1,
                                               const float* __restrict__ b_as) {
    __shared__ float Wt[32 * 96];
    __shared__ float At[32 * 72];
    int tid = threadIdx.x;
    int jt = tid & 31, mt = tid >> 5;
    int n0 = blockIdx.x * 64;
    float acc[8][3];
#pragma unroll
    for (int i = 0; i < 8; i++)
#pragma unroll
        for (int c = 0; c < 3; c++) acc[i][c] = 0.f;
    for (int kt = 0; kt < 128; kt += 32) {
        for (int idx = tid; idx < 32 * 96; idx += 256) {
            int k = idx / 96, j = idx % 96;
            int row = 32 + kt + k;
            Wt[idx] = (j < 64) ? W_ea1[(size_t)row * 64 + j] : W_as[(size_t)row * 32 + (j - 64)];
        }
        for (int idx = tid; idx < 32 * 64; idx += 256) {
            int m = idx / 32, k = idx % 32;
            At[k * 72 + m] = node_ext[(size_t)(n0 + m) * NDIM + kt + k];
        }
        __syncthreads();
#pragma unroll 2
        for (int k = 0; k < 32; k++) {
            float4 A0 = *reinterpret_cast<const float4*>(&At[k * 72 + mt * 8]);
            float4 A1 = *reinterpret_cast<const float4*>(&At[k * 72 + mt * 8 + 4]);
            float am[8] = {A0.x, A0.y, A0.z, A0.w, A1.x, A1.y, A1.z, A1.w};
#pragma unroll
            for (int c = 0; c < 3; c++) {
                float w = Wt[k * 96 + jt + 32 * c];
#pragma unroll
                for (int i = 0; i < 8; i++) acc[i][c] += am[i] * w;
            }
        }
        __syncthreads();
    }
#pragma unroll
    for (int i = 0; i < 8; i++) {
        int n = n0 + mt * 8 + i;
#pragma unroll
        for (int c = 0; c < 3; c++) {
            int j = jt + 32 * c;
            float bb = (j < 64) ? b_ea1[j] : b_as[j - 64];
            g_nbase[(size_t)n * 96 + j] = acc[i][c] + bb;
        }
    }
}

// ================= edge GEMM via mma.sync bf16 3-term split =================
#define ET_WH 0
#define ET_WL 76800
#define ET_AH 153600
#define ET_AL 179200
#define ET_IDX 204800
#define ET_SMEM 205568

__global__ __launch_bounds__(512, 1) void k_edge_tc(
    const float* __restrict__ node_ext, const float* __restrict__ edge_ebd,
    const float* __restrict__ sw, const int* __restrict__ n_ext2e,
    const float* __restrict__ W_ne, const float* __restrict__ W_es,
    const float* __restrict__ e_res0, float* __restrict__ out_edge) {
    extern __shared__ char smc[];
    uint32_t sb = smem_u32(smc);
    int tid = threadIdx.x;
    int wid = tid >> 5;
    int lane = tid & 31;
    int wm = wid >> 2;
    int wn = wid & 3;

    int* eidv = (int*)(smc + ET_IDX);
    int* nodev = eidv + 64;
    float* sws = (float*)(nodev + 64);

    for (int idx = tid; idx < 192 * 192; idx += 512) {
        int k = idx / 192, j = idx % 192;
        float w = (j < 128) ? W_ne[(size_t)(128 + k) * 128 + j]
                            : W_es[(size_t)(128 + k) * 64 + (j - 128)];
        __nv_bfloat16 h = __float2bfloat16(w);
        float l = w - __bfloat162float(h);
        *reinterpret_cast<__nv_bfloat16*>(smc + ET_WH + (j * 200 + k) * 2) = h;
        *reinterpret_cast<__nv_bfloat16*>(smc + ET_WL + (j * 200 + k) * 2) = __float2bfloat16(l);
    }

    uint32_t aRow = wm * 16 + (lane & 15);
    uint32_t aColH = (lane >> 4);
    uint32_t aAddrH = sb + ET_AH + (aRow * 200 + aColH * 8) * 2;
    uint32_t aAddrL = sb + ET_AL + (aRow * 200 + aColH * 8) * 2;
    int nrow = wn * 48 + (lane & 7) + ((lane & 16) ? 8 : 0);
    int khalf = (lane & 8) ? 8 : 0;
    uint32_t bAddrH = sb + ET_WH + (nrow * 200 + khalf) * 2;
    uint32_t bAddrL = sb + ET_WL + (nrow * 200 + khalf) * 2;

    int mfill = tid & 63;
    int seg = tid >> 6;

    for (int ch = blockIdx.x; ch < NEDGE / 64; ch += gridDim.x) {
        int c0 = ch * 64;
        __syncthreads();
        if (tid < 64) {
            int e = g_eids[c0 + tid];
            eidv[tid] = e;
            nodev[tid] = g_enode[c0 + tid];
            sws[tid] = sw[e];
        }
        {
            int e = __ldg(&g_eids[c0 + mfill]);
            int nd = __ldg(&n_ext2e[e]);
            const float4* nrowp = (const float4*)(node_ext + (size_t)nd * NDIM);
            const float4* erowp = (const float4*)(edge_ebd + (size_t)e * EDIM);
            uint32_t rowoff = (uint32_t)mfill * 200;
#pragma unroll
            for (int q = 0; q < 6; q++) {
                int kk = seg * 24 + q * 4;
                float4 v = (kk < 128) ? nrowp[kk >> 2] : erowp[(kk - 128) >> 2];
                __nv_bfloat16 h0 = __float2bfloat16(v.x);
                __nv_bfloat16 h1 = __float2bfloat16(v.y);
                __nv_bfloat16 h2 = __float2bfloat16(v.z);
                __nv_bfloat16 h3 = __float2bfloat16(v.w);
                uint32_t hi01, hi23;
                { __nv_bfloat162 t; t.x = h0; t.y = h1; hi01 = *reinterpret_cast<uint32_t*>(&t); }
                { __nv_bfloat162 t; t.x = h2; t.y = h3; hi23 = *reinterpret_cast<uint32_t*>(&t); }
                uint32_t lo01 = bfp(v.x - __bfloat162float(h0), v.y - __bfloat162float(h1));
                uint32_t lo23 = bfp(v.z - __bfloat162float(h2), v.w - __bfloat162float(h3));
                uint32_t boff = (rowoff + kk) * 2;
                *reinterpret_cast<uint32_t*>(smc + ET_AH + boff) = hi01;
                *reinterpret_cast<uint32_t*>(smc + ET_AH + boff + 4) = hi23;
                *reinterpret_cast<uint32_t*>(smc + ET_AL + boff) = lo01;
                *reinterpret_cast<uint32_t*>(smc + ET_AL + boff + 4) = lo23;
            }
        }
        __syncthreads();

        float d[6][4];
#pragma unroll
        for (int nt = 0; nt < 6; nt++)
#pragma unroll
            for (int q = 0; q < 4; q++) d[nt][q] = 0.f;

#pragma unroll
        for (int s = 0; s < 12; s++) {
            uint32_t ah[4], al[4];
            ldsm4(ah, aAddrH + s * 32);
            ldsm4(al, aAddrL + s * 32);
#pragma unroll
            for (int pr = 0; pr < 3; pr++) {
                uint32_t bh[4], bl[4];
                ldsm4(bh, bAddrH + pr * 16 * 400 + s * 32);
                ldsm4(bl, bAddrL + pr * 16 * 400 + s * 32);
                mma_bf16(d[pr * 2], ah, bh);
                mma_bf16(d[pr * 2], ah, bl);
                mma_bf16(d[pr * 2], al, bh);
                mma_bf16(d[pr * 2 + 1], ah, bh + 2);
                mma_bf16(d[pr * 2 + 1], ah, bl + 2);
                mma_bf16(d[pr * 2 + 1], al, bh + 2);
            }
        }

        int g = lane >> 2, qt = lane & 3;
        int r0 = wm * 16 + g, r1 = r0 + 8;
        int nd0 = nodev[r0], nd1 = nodev[r1];
        float sw0 = sws[r0], sw1 = sws[r1];
        int ee0 = eidv[r0], ee1 = eidv[r1];
        bool samend = (nd0 == nd1);
#pragma unroll
        for (int nt = 0; nt < 6; nt++) {
            int j0 = wn * 48 + nt * 8 + qt * 2;
            float2 b0v = *(const float2*)(g_base + (size_t)nd0 * 192 + j0);
            float2 b1v = *(const float2*)(g_base + (size_t)nd1 * 192 + j0);
            float y00 = silu_f(d[nt][0] + b0v.x);
            float y01 = silu_f(d[nt][1] + b0v.y);
            float y10 = silu_f(d[nt][2] + b1v.x);
            float y11 = silu_f(d[nt][3] + b1v.y);
            if (j0 < 128) {
                float v00 = y00 * sw0, v01 = y01 * sw0;
                float v10 = y10 * sw1, v11 = y11 * sw1;
                if (samend) {
                    atomicAdd(&g_msg[(size_t)nd0 * NDIM + j0], v00 + v10);
                    atomicAdd(&g_msg[(size_t)nd0 * NDIM + j0 + 1], v01 + v11);
                } else {
                    atomicAdd(&g_msg[(size_t)nd0 * NDIM + j0], v00);
                    atomicAdd(&g_msg[(size_t)nd0 * NDIM + j0 + 1], v01);
                    atomicAdd(&g_msg[(size_t)nd1 * NDIM + j0], v10);
                    atomicAdd(&g_msg[(size_t)nd1 * NDIM + j0 + 1], v11);
                }
            } else {
                int col = j0 - 128;
                float2 er = *(const float2*)(e_res0 + col);
                size_t o0 = (size_t)ee0 * EDIM + col;
                size_t o1 = (size_t)ee1 * EDIM + col;
                float2 eb0 = *(const float2*)(edge_ebd + o0);
                float2 eb1 = *(const float2*)(edge_ebd + o1);
                *(float2*)(out_edge + o0) = make_float2(eb0.x + er.x * y00, eb0.y + er.y * y01);
                *(float2*)(out_edge + o1) = make_float2(eb1.x + er.x * y10, eb1.y + er.y * y11);
            }
        }
    }
}

__global__ void k_node_finish(const float* __restrict__ n_res2, float* __restrict__ out_node) {
    int i = blockIdx.x * blockDim.x + threadIdx.x;
    if (i < NLOC * NDIM) {
        int j = i & (NDIM - 1);
        out_node[i] += n_res2[j] * g_msg[i] * INV_DYN_E;
    }
}

// ================= angle GEMM via mma.sync bf16 3-term split =================
#define AT_WH 0
#define AT_WL 32256
#define AT_AH 64512
#define AT_AL 86016
#define AT_IDX 107520
#define AT_SMEM 108288

__global__ __launch_bounds__(512, 2) void k_angle_tc(
    const float* __restrict__ angle_ebd, const float* __restrict__ edge_ebd,
    const int* __restrict__ ai, const float* __restrict__ a_sw,
    const float* __restrict__ W_ea1, const float* __restrict__ W_as,
    const float* __restrict__ a_res0, float* __restrict__ out_angle) {
    extern __shared__ char smc[];
    uint32_t sb = smem_u32(smc);
    int tid = threadIdx.x;
    int wid = tid >> 5;
    int lane = tid & 31;
    int wm = wid >> 2;
    int wn = wid & 3;

    int* nav = (int*)(smc + AT_IDX);
    int* ijav = nav + 64;
    float* aswv = (float*)(ijav + 64);

    const int* n2a = ai;
    const int* eij = ai + NANGLE;
    const int* eik = ai + 2 * NANGLE;

    for (int idx = tid; idx < 96 * 160; idx += 512) {
        int j = idx / 160, k = idx % 160;
        int srck = (k < 32) ? k : ((k < 96) ? 160 + (k - 32) : 224 + (k - 96));
        float w = (j < 64) ? W_ea1[(size_t)srck * 64 + j] : W_as[(size_t)srck * 32 + (j - 64)];
        __nv_bfloat16 h = __float2bfloat16(w);
        float l = w - __bfloat162float(h);
        *reinterpret_cast<__nv_bfloat16*>(smc + AT_WH + (j * 168 + k) * 2) = h;
        *reinterpret_cast<__nv_bfloat16*>(smc + AT_WL + (j * 168 + k) * 2) = __float2bfloat16(l);
    }

    uint32_t aRow = wm * 16 + (lane & 15);
    uint32_t aColH = (lane >> 4);
    uint32_t aAddrH = sb + AT_AH + (aRow * 168 + aColH * 8) * 2;
    uint32_t aAddrL = sb + AT_AL + (aRow * 168 + aColH * 8) * 2;
    int nrow = wn * 24 + (lane & 7) + ((lane & 16) ? 8 : 0);
    int khalf = (lane & 8) ? 8 : 0;
    uint32_t bAddrH = sb + AT_WH + (nrow * 168 + khalf) * 2;
    uint32_t bAddrL = sb + AT_WL + (nrow * 168 + khalf) * 2;
    int nrow2 = wn * 24 + 16 + (lane & 7);
    int khalf2 = (lane & 8) ? 8 : 0;
    uint32_t b2AddrH = sb + AT_WH + (nrow2 * 168 + khalf2) * 2;
    uint32_t b2AddrL = sb + AT_WL + (nrow2 * 168 + khalf2) * 2;

    int mfill = tid & 63;
    int seg = tid >> 6;

    for (int t = blockIdx.x; t < NANGLE / 64; t += gridDim.x) {
        int a0 = t * 64;
        __syncthreads();
        if (tid < 64) {
            nav[tid] = n2a[a0 + tid];
            ijav[tid] = eij[a0 + tid];
            aswv[tid] = a_sw[a0 + tid];
        }
        {
            int a = a0 + mfill;
            int ek = __ldg(&eik[a]);
            int ej = __ldg(&eij[a]);
            const float4* arow = (const float4*)(angle_ebd + (size_t)a * ADIM);
            const float4* krow = (const float4*)(edge_ebd + (size_t)ek * EDIM);
            const float4* jrow = (const float4*)(edge_ebd + (size_t)ej * EDIM);
            uint32_t rowoff = (uint32_t)mfill * 168;
#pragma unroll
            for (int q = 0; q < 5; q++) {
                int kk = seg * 20 + q * 4;
                float4 v = (kk < 32) ? arow[kk >> 2]
                         : (kk < 96) ? krow[(kk - 32) >> 2]
                                     : jrow[(kk - 96) >> 2];
                __nv_bfloat16 h0 = __float2bfloat16(v.x);
                __nv_bfloat16 h1 = __float2bfloat16(v.y);
                __nv_bfloat16 h2 = __float2bfloat16(v.z);
                __nv_bfloat16 h3 = __float2bfloat16(v.w);
                uint32_t hi01, hi23;
                { __nv_bfloat162 tt; tt.x = h0; tt.y = h1; hi01 = *reinterpret_cast<uint32_t*>(&tt); }
                { __nv_bfloat162 tt; tt.x = h2; tt.y = h3; hi23 = *reinterpret_cast<uint32_t*>(&tt); }
                uint32_t lo01 = bfp(v.x - __bfloat162float(h0), v.y - __bfloat162float(h1));
                uint32_t lo23 = bfp(v.z - __bfloat162float(h2), v.w - __bfloat162float(h3));
                uint32_t boff = (rowoff + kk) * 2;
                *reinterpret_cast<uint32_t*>(smc + AT_AH + boff) = hi01;
                *reinterpret_cast<uint32_t*>(smc + AT_AH + boff + 4) = hi23;
                *reinterpret_cast<uint32_t*>(smc + AT_AL + boff) = lo01;
                *reinterpret_cast<uint32_t*>(smc + AT_AL + boff + 4) = lo23;
            }
        }
        __syncthreads();

        float d[3][4];
#pragma unroll
        for (int nt = 0; nt < 3; nt++)
#pragma unroll
            for (int q = 0; q < 4; q++) d[nt][q] = 0.f;

#pragma unroll
        for (int s = 0; s < 10; s++) {
            uint32_t ah[4], al[4];
            ldsm4(ah, aAddrH + s * 32);
            ldsm4(al, aAddrL + s * 32);
            uint32_t bh[4], bl[4], b2h[2], b2l[2];
            ldsm4(bh, bAddrH + s * 32);
            ldsm4(bl, bAddrL + s * 32);
            ldsm2(b2h, b2AddrH + s * 32);
            ldsm2(b2l, b2AddrL + s * 32);
            mma_bf16(d[0], ah, bh);
            mma_bf16(d[0], ah, bl);
            mma_bf16(d[0], al, bh);
            mma_bf16(d[1], ah, bh + 2);
            mma_bf16(d[1], ah, bl + 2);
            mma_bf16(d[1], al, bh + 2);
            mma_bf16(d[2], ah, b2h);
            mma_bf16(d[2], ah, b2l);
            mma_bf16(d[2], al, b2h);
        }

        int g = lane >> 2, qt = lane & 3;
        int r0 = wm * 16 + g, r1 = r0 + 8;
        int nd0 = nav[r0], nd1 = nav[r1];
        float sw0 = aswv[r0], sw1 = aswv[r1];
        int ij0 = ijav[r0], ij1 = ijav[r1];
#pragma unroll
        for (int nt = 0; nt < 3; nt++) {
            int j0 = wn * 24 + nt * 8 + qt * 2;
            float2 nb0 = *(const float2*)(g_nbase + (size_t)nd0 * 96 + j0);
            float2 nb1 = *(const float2*)(g_nbase + (size_t)nd1 * 96 + j0);
            float y00 = silu_f(d[nt][0] + nb0.x);
            float y01 = silu_f(d[nt][1] + nb0.y);
            float y10 = silu_f(d[nt][2] + nb1.x);
            float y11 = silu_f(d[nt][3] + nb1.y);
            if (j0 < 64) {
                atomicAdd(&g_reduced[(size_t)ij0 * EDIM + j0], y00 * sw0);
                atomicAdd(&g_reduced[(size_t)ij0 * EDIM + j0 + 1], y01 * sw0);
                atomicAdd(&g_reduced[(size_t)ij1 * EDIM + j0], y10 * sw1);
                atomicAdd(&g_reduced[(size_t)ij1 * EDIM + j0 + 1], y11 * sw1);
            } else {
                int col = j0 - 64;
                float2 arr = *(const float2*)(a_res0 + col);
                size_t o0 = (size_t)(a0 + r0) * ADIM + col;
                size_t o1 = (size_t)(a0 + r1) * ADIM + col;
                float2 ae0 = *(const float2*)(angle_ebd + o0);
                float2 ae1 = *(const float2*)(angle_ebd + o1);
                *(float2*)(out_angle + o0) = make_float2(ae0.x + arr.x * y00, ae0.y + arr.y * y01);
                *(float2*)(out_angle + o1) = make_float2(ae1.x + arr.x * y10, ae1.y + arr.y * y11);
            }
        }
    }
}

// ================= edge angle message GEMM via mma.sync bf16 =================
__global__ __launch_bounds__(256) void k_edge_msg(const float* __restrict__ W2,
                                                  const float* __restrict__ b2,
                                                  const float* __restrict__ e_res1,
                                                  float* __restrict__ out_edge) {
    __shared__ __align__(16) __nv_bfloat16 Wh[64 * 72];
    __shared__ __align__(16) __nv_bfloat16 Wl[64 * 72];
    __shared__ __align__(16) __nv_bfloat16 Ah[64 * 72];
    __shared__ __align__(16) __nv_bfloat16 Al[64 * 72];
    int tid = threadIdx.x;
    int wid = tid >> 5;
    int lane = tid & 31;
    int wm = wid >> 1;
    int wn = wid & 1;
    int e0 = blockIdx.x * 64;

    for (int idx = tid; idx < 64 * 64; idx += 256) {
        int j = idx >> 6, k = idx & 63;
        float w = W2[k * 64 + j];
        __nv_bfloat16 h = __float2bfloat16(w);
        Wh[j * 72 + k] = h;
        Wl[j * 72 + k] = __float2bfloat16(w - __bfloat162float(h));
    }
    {
        int m = tid & 63, seg = tid >> 6;
        const float4* src = (const float4*)(g_reduced + (size_t)(e0 + m) * EDIM + seg * 16);
#pragma unroll
        for (int q = 0; q < 4; q++) {
            float4 v = src[q];
            int kk = seg * 16 + q * 4;
            __nv_bfloat16 h0 = __float2bfloat16(v.x);
            __nv_bfloat16 h1 = __float2bfloat16(v.y);
            __nv_bfloat16 h2 = __float2bfloat16(v.z);
            __nv_bfloat16 h3 = __float2bfloat16(v.w);
            Ah[m * 72 + kk + 0] = h0;
            Ah[m * 72 + kk + 1] = h1;
            Ah[m * 72 + kk + 2] = h2;
            Ah[m * 72 + kk + 3] = h3;
            Al[m * 72 + kk + 0] = __float2bfloat16(v.x - __bfloat162float(h0));
            Al[m * 72 + kk + 1] = __float2bfloat16(v.y - __bfloat162float(h1));
            Al[m * 72 + kk + 2] = __float2bfloat16(v.z - __bfloat162float(h2));
            Al[m * 72 + kk + 3] = __float2bfloat16(v.w - __bfloat162float(h3));
        }
    }
    __syncthreads();

    uint32_t aRow = wm * 16 + (lane & 15);
    uint32_t aColH = (lane >> 4);
    uint32_t aAddrH = smem_u32(Ah) + (aRow * 72 + aColH * 8) * 2;
    uint32_t aAddrL = smem_u32(Al) + (aRow * 72 + aColH * 8) * 2;
    int nrow = wn * 32 + (lane & 7) + ((lane & 16) ? 8 : 0);
    int khalf = (lane & 8) ? 8 : 0;
    uint32_t bAddrH = smem_u32(Wh) + (nrow * 72 + khalf) * 2;
    uint32_t bAddrL = smem_u32(Wl) + (nrow * 72 + khalf) * 2;
    uint32_t b2AddrH = bAddrH + 16 * 144;
    uint32_t b2AddrL = bAddrL + 16 * 144;

    float d[4][4];
#pragma unroll
    for (int nt = 0; nt < 4; nt++)
#pragma unroll
        for (int q = 0; q < 4; q++) d[nt][q] = 0.f;

#pragma unroll
    for (int s = 0; s < 4; s++) {
        uint32_t ah[4], al[4];
        ldsm4(ah, aAddrH + s * 32);
        ldsm4(al, aAddrL + s * 32);
        uint32_t bh[4], bl[4], ch[4], cl[4];
        ldsm4(bh, bAddrH + s * 32);
        ldsm4(bl, bAddrL + s * 32);
        ldsm4(ch, b2AddrH + s * 32);
        ldsm4(cl, b2AddrL + s * 32);
        mma_bf16(d[0], ah, bh);
        mma_bf16(d[0], ah, bl);
        mma_bf16(d[0], al, bh);
        mma_bf16(d[1], ah, bh + 2);
        mma_bf16(d[1], ah, bl + 2);
        mma_bf16(d[1], al, bh + 2);
        mma_bf16(d[2], ah, ch);
        mma_bf16(d[2], ah, cl);
        mma_bf16(d[2], al, ch);
        mma_bf16(d[3], ah, ch + 2);
        mma_bf16(d[3], ah, cl + 2);
        mma_bf16(d[3], al, ch + 2);
    }

    int g = lane >> 2, qt = lane & 3;
    int r0 = wm * 16 + g, r1 = r0 + 8;
#pragma unroll
    for (int nt = 0; nt < 4; nt++) {
        int j0 = wn * 32 + nt * 8 + qt * 2;
        float2 bb = *(const float2*)(b2 + j0);
        float2 er = *(const float2*)(e_res1 + j0);
        size_t o0 = (size_t)(e0 + r0) * EDIM + j0;
        size_t o1 = (size_t)(e0 + r1) * EDIM + j0;
        float2 v0 = *(float2*)(out_edge + o0);
        float2 v1 = *(float2*)(out_edge + o1);
        v0.x += er.x * silu_f(d[nt][0] + bb.x);
        v0.y += er.y * silu_f(d[nt][1] + bb.y);
        v1.x += er.x * silu_f(d[nt][2] + bb.x);
        v1.y += er.y * silu_f(d[nt][3] + bb.y);
        *(float2*)(out_edge + o0) = v0;
        *(float2*)(out_edge + o1) = v1;
    }
}

// ---------------- launch ----------------
extern "C" void kernel_launch(void* const* d_in, const int* in_sizes, int n_in,
                              void* d_out, int out_size) {
    const float* node_ext   = (const float*)d_in[0];
    const float* edge_ebd   = (const float*)d_in[1];
    const float* h2         = (const float*)d_in[2];
    const float* angle_ebd  = (const float*)d_in[3];
    const float* sw         = (const float*)d_in[6];
    const float* a_sw       = (const float*)d_in[9];
    const int*   edge_index = (const int*)d_in[10];
    const int*   angle_index= (const int*)d_in[11];
    const float* W_node_self = (const float*)d_in[12];
    const float* b_node_self = (const float*)d_in[13];
    const float* W_node_sym  = (const float*)d_in[14];
    const float* b_node_sym  = (const float*)d_in[15];
    const float* W_node_edge = (const float*)d_in[16];
    const float* b_node_edge = (const float*)d_in[17];
    const float* W_edge_self = (const float*)d_in[18];
    const float* b_edge_self = (const float*)d_in[19];
    const float* W_edge_angle1 = (const float*)d_in[20];
    const float* b_edge_angle1 = (const float*)d_in[21];
    const float* W_edge_angle2 = (const float*)d_in[22];
    const float* b_edge_angle2 = (const float*)d_in[23];
    const float* W_angle_self  = (const float*)d_in[24];
    const float* b_angle_self  = (const float*)d_in[25];
    const float* n_res0 = (const float*)d_in[26];
    const float* n_res1 = (const float*)d_in[27];
    const float* n_res2 = (const float*)d_in[28];
    const float* e_res0 = (const float*)d_in[29];
    const float* e_res1 = (const float*)d_in[30];
    const float* a_res0 = (const float*)d_in[31];

    float* out = (float*)d_out;
    float* out_node  = out;
    float* out_edge  = out + (size_t)NLOC * NDIM;
    float* out_angle = out_edge + (size_t)NEDGE * EDIM;

    const int* n2e = edge_index;
    const int* n_ext2e = edge_index + NEDGE;

    cudaFuncSetAttribute((const void*)k_edge_tc,
                         cudaFuncAttributeMaxDynamicSharedMemorySize, ET_SMEM);
    cudaFuncSetAttribute((const void*)k_angle_tc,
                         cudaFuncAttributeMaxDynamicSharedMemorySize, AT_SMEM);

    k_zero<<<4096, 256>>>();
    k_count<<<NEDGE / 256, 256>>>(n2e);
    k_scan<<<1, 1024>>>();
    k_scatter<<<NEDGE / 256, 256>>>(n2e);
    k_sym<<<NLOC, 768>>>(edge_ebd, node_ext, h2, sw, n_ext2e);
    k_symmm<<<NLOC / 64, 256>>>(W_node_sym, b_node_sym, n_res1,
                                W_node_self, b_node_self, n_res0, node_ext, out_node);
    k_base<<<NLOC / 64, 256>>>(node_ext, W_node_edge, W_edge_self, b_node_edge, b_edge_self);
    k_nbase<<<NLOC / 64, 256>>>(node_ext, W_edge_angle1, W_angle_self,
                                b_edge_angle1, b_angle_self);
    k_edge_tc<<<148, 512, ET_SMEM>>>(node_ext, edge_ebd, sw, n_ext2e,
                                     W_node_edge, W_edge_self, e_res0, out_edge);
    k_node_finish<<<NLOC * NDIM / 256, 256>>>(n_res2, out_node);
    k_angle_tc<<<296, 512, AT_SMEM>>>(angle_ebd, edge_ebd, angle_index, a_sw,
                                      W_edge_angle1, W_angle_self, a_res0, out_angle);
    k_edge_msg<<<NEDGE / 64, 256>>>(W_edge_angle2, b_edge_angle2, e_res1, out_edge);
}

// round 12
// speedup vs baseline: 4.3418x; 1.1592x over previous
#include <cuda_runtime.h>
#include <cuda_bf16.h>
#include <cstdint>
#include <cstddef>

#define NLOC   4096
#define NALL   6144
#define NDIM   128
#define EDIM   64
#define ADIM   32
#define NEDGE  262144
#define NANGLE 409600
#define INV_DYN_E 0.15625f            // 1/6.4
#define SYM_SCALE 0.0520833333333f    // (1/6.4)/3

// ---------------- device scratch ----------------
__device__ float g_sym[(size_t)NLOC * 768];
__device__ float g_base[(size_t)NLOC * 192];
__device__ float g_base2[(size_t)NALL * 192];
__device__ float g_nbase[(size_t)NLOC * 96];
__device__ float g_reduced[(size_t)NEDGE * EDIM];
__device__ float g_msg[(size_t)NLOC * NDIM];
__device__ int   g_ecnt[NLOC];
__device__ int   g_eoff[NLOC + 1];
__device__ int   g_ecur[NLOC];
__device__ int   g_eids[NEDGE];
__device__ int   g_enode[NEDGE];

// ---------------- helpers ----------------
__device__ __forceinline__ float silu_f(float x) { return x / (1.0f + __expf(-x)); }

__device__ __forceinline__ uint32_t smem_u32(const void* p) {
    uint32_t a;
    asm("{ .reg .u64 t; cvta.to.shared.u64 t, %1; cvt.u32.u64 %0, t; }" : "=r"(a) : "l"(p));
    return a;
}

__device__ __forceinline__ void ldsm4(uint32_t* r, uint32_t addr) {
    asm volatile("ldmatrix.sync.aligned.m8n8.x4.shared.b16 {%0,%1,%2,%3}, [%4];"
                 : "=r"(r[0]), "=r"(r[1]), "=r"(r[2]), "=r"(r[3]) : "r"(addr));
}
__device__ __forceinline__ void ldsm2(uint32_t* r, uint32_t addr) {
    asm volatile("ldmatrix.sync.aligned.m8n8.x2.shared.b16 {%0,%1}, [%2];"
                 : "=r"(r[0]), "=r"(r[1]) : "r"(addr));
}

__device__ __forceinline__ void mma_bf16(float* d, const uint32_t* a, const uint32_t* b) {
    asm volatile(
        "mma.sync.aligned.m16n8k16.row.col.f32.bf16.bf16.f32 "
        "{%0,%1,%2,%3}, {%4,%5,%6,%7}, {%8,%9}, {%0,%1,%2,%3};"
        : "+f"(d[0]), "+f"(d[1]), "+f"(d[2]), "+f"(d[3])
        : "r"(a[0]), "r"(a[1]), "r"(a[2]), "r"(a[3]), "r"(b[0]), "r"(b[1]));
}

__device__ __forceinline__ uint32_t bfp(float a, float b) {
    __nv_bfloat162 t = __floats2bfloat162_rn(a, b);
    return *reinterpret_cast<uint32_t*>(&t);
}

// ---------------- zero scratch ----------------
__global__ void k_zero() {
    size_t i0 = (size_t)blockIdx.x * blockDim.x + threadIdx.x;
    size_t stride = (size_t)gridDim.x * blockDim.x;
    float4* r = reinterpret_cast<float4*>(g_reduced);
    size_t n4 = (size_t)NEDGE * EDIM / 4;
    for (size_t i = i0; i < n4; i += stride) r[i] = make_float4(0.f, 0.f, 0.f, 0.f);
    float4* m = reinterpret_cast<float4*>(g_msg);
    size_t m4 = (size_t)NLOC * NDIM / 4;
    for (size_t i = i0; i < m4; i += stride) m[i] = make_float4(0.f, 0.f, 0.f, 0.f);
    if (i0 < NLOC) g_ecnt[i0] = 0;
}

// ---------------- CSR build ----------------
__global__ void k_count(const int* __restrict__ n2e) {
    int e = blockIdx.x * blockDim.x + threadIdx.x;
    if (e < NEDGE) atomicAdd(&g_ecnt[n2e[e]], 1);
}

__global__ void k_scan() {
    __shared__ int sh[1024];
    int t = threadIdx.x;
    int c[4];
#pragma unroll
    for (int i = 0; i < 4; i++) c[i] = g_ecnt[t * 4 + i];
    int tot = c[0] + c[1] + c[2] + c[3];
    sh[t] = tot;
    __syncthreads();
    for (int st = 1; st < 1024; st <<= 1) {
        int add = (t >= st) ? sh[t - st] : 0;
        __syncthreads();
        sh[t] += add;
        __syncthreads();
    }
    int run = sh[t] - tot;
#pragma unroll
    for (int i = 0; i < 4; i++) {
        g_eoff[t * 4 + i] = run;
        g_ecur[t * 4 + i] = run;
        run += c[i];
    }
    if (t == 1023) g_eoff[NLOC] = run;
}

__global__ void k_scatter(const int* __restrict__ n2e) {
    int e = blockIdx.x * blockDim.x + threadIdx.x;
    if (e < NEDGE) {
        int n = n2e[e];
        int pos = atomicAdd(&g_ecur[n], 1);
        g_eids[pos] = e;
        g_enode[pos] = n;
    }
}

// ---------------- sym op: 4-way edge parallelism ----------------
__global__ __launch_bounds__(768) void k_sym(
    const float* __restrict__ edge_ebd, const float* __restrict__ node_ext,
    const float* __restrict__ h2, const float* __restrict__ sw,
    const int* __restrict__ n_ext2e) {
    __shared__ float P[4][3][192];
    __shared__ float S0[192], S1[192], S2[192];
    __shared__ float symv[768];
    int n = blockIdx.x;
    int t = threadIdx.x;
    int g = t / 192;
    int f = t - g * 192;
    int beg = g_eoff[n], end = g_eoff[n + 1];
    float a0 = 0.f, a1 = 0.f, a2 = 0.f;
    for (int i = beg + g; i < end; i += 4) {
        int e = g_eids[i];
        float swv = sw[e];
        float h0 = h2[e * 3 + 0] * swv;
        float h1 = h2[e * 3 + 1] * swv;
        float hh = h2[e * 3 + 2] * swv;
        float val = (f < 64) ? edge_ebd[(size_t)e * EDIM + f]
                             : node_ext[(size_t)n_ext2e[e] * NDIM + (f - 64)];
        a0 += h0 * val;
        a1 += h1 * val;
        a2 += hh * val;
    }
    P[g][0][f] = a0; P[g][1][f] = a1; P[g][2][f] = a2;
    __syncthreads();
    if (t < 192) {
        S0[t] = P[0][0][t] + P[1][0][t] + P[2][0][t] + P[3][0][t];
    } else if (t < 384) {
        int tt = t - 192;
        S1[tt] = P[0][1][tt] + P[1][1][tt] + P[2][1][tt] + P[3][1][tt];
    } else if (t < 576) {
        int tt = t - 384;
        S2[tt] = P[0][2][tt] + P[1][2][tt] + P[2][2][tt] + P[3][2][tt];
    }
    __syncthreads();
    if (t < 64) {
#pragma unroll
        for (int a = 0; a < 4; a++)
            symv[a * 64 + t] = SYM_SCALE * (S0[a] * S0[t] + S1[a] * S1[t] + S2[a] * S2[t]);
    } else if (t < 192) {
        int dn = t - 64;
#pragma unroll
        for (int a = 0; a < 4; a++)
            symv[256 + a * 128 + dn] =
                SYM_SCALE * (S0[64 + a] * S0[t] + S1[64 + a] * S1[t] + S2[64 + a] * S2[t]);
    }
    __syncthreads();
    g_sym[(size_t)n * 768 + t] = symv[t];
}

// ---------------- node_sym GEMM fused with node_self ----------------
__global__ __launch_bounds__(256) void k_symmm(
    const float* __restrict__ W_sym, const float* __restrict__ b_sym,
    const float* __restrict__ n_res1,
    const float* __restrict__ W_self, const float* __restrict__ b_self,
    const float* __restrict__ n_res0,
    const float* __restrict__ node_ext, float* __restrict__ out_node) {
    __shared__ float Wt[32 * 128];
    __shared__ float At[32 * 72];
    int tid = threadIdx.x;
    int jt = tid & 31, mt = tid >> 5;
    int n0 = blockIdx.x * 64;
    float acc0[8][4], acc1[8][4];
#pragma unroll
    for (int i = 0; i < 8; i++)
#pragma unroll
        for (int q = 0; q < 4; q++) { acc0[i][q] = 0.f; acc1[i][q] = 0.f; }

    for (int kt = 0; kt < 768; kt += 32) {
        for (int idx = tid; idx < 32 * 128; idx += 256)
            Wt[idx] = W_sym[(size_t)(kt + idx / 128) * 128 + (idx % 128)];
        for (int idx = tid; idx < 32 * 64; idx += 256) {
            int m = idx / 32, k = idx % 32;
            At[k * 72 + m] = g_sym[(size_t)(n0 + m) * 768 + kt + k];
        }
        __syncthreads();
#pragma unroll 4
        for (int k = 0; k < 32; k++) {
            float4 A0 = *reinterpret_cast<const float4*>(&At[k * 72 + mt * 8]);
            float4 A1 = *reinterpret_cast<const float4*>(&At[k * 72 + mt * 8 + 4]);
            float am[8] = {A0.x, A0.y, A0.z, A0.w, A1.x, A1.y, A1.z, A1.w};
            float4 wv = *reinterpret_cast<const float4*>(&Wt[k * 128 + jt * 4]);
            float wq[4] = {wv.x, wv.y, wv.z, wv.w};
#pragma unroll
            for (int i = 0; i < 8; i++)
#pragma unroll
                for (int q = 0; q < 4; q++) acc0[i][q] += am[i] * wq[q];
        }
        __syncthreads();
    }
    for (int kt = 0; kt < 128; kt += 32) {
        for (int idx = tid; idx < 32 * 128; idx += 256)
            Wt[idx] = W_self[(size_t)(kt + idx / 128) * 128 + (idx % 128)];
        for (int idx = tid; idx < 32 * 64; idx += 256) {
            int m = idx / 32, k = idx % 32;
            At[k * 72 + m] = node_ext[(size_t)(n0 + m) * NDIM + kt + k];
        }
        __syncthreads();
#pragma unroll 4
        for (int k = 0; k < 32; k++) {
            float4 A0 = *reinterpret_cast<const float4*>(&At[k * 72 + mt * 8]);
            float4 A1 = *reinterpret_cast<const float4*>(&At[k * 72 + mt * 8 + 4]);
            float am[8] = {A0.x, A0.y, A0.z, A0.w, A1.x, A1.y, A1.z, A1.w};
            float4 wv = *reinterpret_cast<const float4*>(&Wt[k * 128 + jt * 4]);
            float wq[4] = {wv.x, wv.y, wv.z, wv.w};
#pragma unroll
            for (int i = 0; i < 8; i++)
#pragma unroll
                for (int q = 0; q < 4; q++) acc1[i][q] += am[i] * wq[q];
        }
        __syncthreads();
    }
#pragma unroll
    for (int i = 0; i < 8; i++) {
        int n = n0 + mt * 8 + i;
#pragma unroll
        for (int q = 0; q < 4; q++) {
            int j = jt * 4 + q;
            float y1 = silu_f(acc0[i][q] + b_sym[j]);
            float y0 = silu_f(acc1[i][q] + b_self[j]);
            out_node[(size_t)n * 128 + j] =
                node_ext[(size_t)n * NDIM + j] + n_res0[j] * y0 + n_res1[j] * y1;
        }
    }
}

// ---------------- base precompute (dest part, 192 cols, W rows 0..127) ----------------
__global__ __launch_bounds__(256) void k_base(const float* __restrict__ node_ext,
                                              const float* __restrict__ W_ne,
                                              const float* __restrict__ W_es,
                                              const float* __restrict__ b_ne,
                                              const float* __restrict__ b_es) {
    __shared__ float Wt[32 * 192];
    __shared__ float At[32 * 72];
    int tid = threadIdx.x;
    int jt = tid & 31, mt = tid >> 5;
    int n0 = blockIdx.x * 64;
    float acc[8][6];
#pragma unroll
    for (int i = 0; i < 8; i++)
#pragma unroll
        for (int c = 0; c < 6; c++) acc[i][c] = 0.f;
    for (int kt = 0; kt < 128; kt += 32) {
        for (int idx = tid; idx < 32 * 192; idx += 256) {
            int k = idx / 192, j = idx % 192;
            int row = kt + k;
            Wt[idx] = (j < 128) ? W_ne[(size_t)row * 128 + j] : W_es[(size_t)row * 64 + (j - 128)];
        }
        for (int idx = tid; idx < 32 * 64; idx += 256) {
            int m = idx / 32, k = idx % 32;
            At[k * 72 + m] = node_ext[(size_t)(n0 + m) * NDIM + kt + k];
        }
        __syncthreads();
#pragma unroll 2
        for (int k = 0; k < 32; k++) {
            float4 A0 = *reinterpret_cast<const float4*>(&At[k * 72 + mt * 8]);
            float4 A1 = *reinterpret_cast<const float4*>(&At[k * 72 + mt * 8 + 4]);
            float am[8] = {A0.x, A0.y, A0.z, A0.w, A1.x, A1.y, A1.z, A1.w};
#pragma unroll
            for (int c = 0; c < 6; c++) {
                float w = Wt[k * 192 + jt + 32 * c];
#pragma unroll
                for (int i = 0; i < 8; i++) acc[i][c] += am[i] * w;
            }
        }
        __syncthreads();
    }
#pragma unroll
    for (int i = 0; i < 8; i++) {
        int n = n0 + mt * 8 + i;
#pragma unroll
        for (int c = 0; c < 6; c++) {
            int j = jt + 32 * c;
            float bb = (j < 128) ? b_ne[j] : b_es[j - 128];
            g_base[(size_t)n * 192 + j] = acc[i][c] + bb;
        }
    }
}

// ---------------- base2 precompute (nei part, all NALL nodes, W rows 128..255) ----------------
__global__ __launch_bounds__(256) void k_base2(const float* __restrict__ node_ext,
                                               const float* __restrict__ W_ne,
                                               const float* __restrict__ W_es) {
    __shared__ float Wt[32 * 192];
    __shared__ float At[32 * 72];
    int tid = threadIdx.x;
    int jt = tid & 31, mt = tid >> 5;
    int n0 = blockIdx.x * 64;
    float acc[8][6];
#pragma unroll
    for (int i = 0; i < 8; i++)
#pragma unroll
        for (int c = 0; c < 6; c++) acc[i][c] = 0.f;
    for (int kt = 0; kt < 128; kt += 32) {
        for (int idx = tid; idx < 32 * 192; idx += 256) {
            int k = idx / 192, j = idx % 192;
            int row = 128 + kt + k;
            Wt[idx] = (j < 128) ? W_ne[(size_t)row * 128 + j] : W_es[(size_t)row * 64 + (j - 128)];
        }
        for (int idx = tid; idx < 32 * 64; idx += 256) {
            int m = idx / 32, k = idx % 32;
            At[k * 72 + m] = node_ext[(size_t)(n0 + m) * NDIM + kt + k];
        }
        __syncthreads();
#pragma unroll 2
        for (int k = 0; k < 32; k++) {
            float4 A0 = *reinterpret_cast<const float4*>(&At[k * 72 + mt * 8]);
            float4 A1 = *reinterpret_cast<const float4*>(&At[k * 72 + mt * 8 + 4]);
            float am[8] = {A0.x, A0.y, A0.z, A0.w, A1.x, A1.y, A1.z, A1.w};
#pragma unroll
            for (int c = 0; c < 6; c++) {
                float w = Wt[k * 192 + jt + 32 * c];
#pragma unroll
                for (int i = 0; i < 8; i++) acc[i][c] += am[i] * w;
            }
        }
        __syncthreads();
    }
#pragma unroll
    for (int i = 0; i < 8; i++) {
        int n = n0 + mt * 8 + i;
#pragma unroll
        for (int c = 0; c < 6; c++) {
            int j = jt + 32 * c;
            g_base2[(size_t)n * 192 + j] = acc[i][c];
        }
    }
}

// ---------------- nbase precompute (angle kernel, 96 cols) ----------------
__global__ __launch_bounds__(256) void k_nbase(const float* __restrict__ node_ext,
                                               const float* __restrict__ W_ea1,
                                               const float* __restrict__ W_as,
                                               const float* __restrict__ b_ea1,
                                               const float* __restrict__ b_as) {
    __shared__ float Wt[32 * 96];
    __shared__ float At[32 * 72];
    int tid = threadIdx.x;
    int jt = tid & 31, mt = tid >> 5;
    int n0 = blockIdx.x * 64;
    float acc[8][3];
#pragma unroll
    for (int i = 0; i < 8; i++)
#pragma unroll
        for (int c = 0; c < 3; c++) acc[i][c] = 0.f;
    for (int kt = 0; kt < 128; kt += 32) {
        for (int idx = tid; idx < 32 * 96; idx += 256) {
            int k = idx / 96, j = idx % 96;
            int row = 32 + kt + k;
            Wt[idx] = (j < 64) ? W_ea1[(size_t)row * 64 + j] : W_as[(size_t)row * 32 + (j - 64)];
        }
        for (int idx = tid; idx < 32 * 64; idx += 256) {
            int m = idx / 32, k = idx % 32;
            At[k * 72 + m] = node_ext[(size_t)(n0 + m) * NDIM + kt + k];
        }
        __syncthreads();
#pragma unroll 2
        for (int k = 0; k < 32; k++) {
            float4 A0 = *reinterpret_cast<const float4*>(&At[k * 72 + mt * 8]);
            float4 A1 = *reinterpret_cast<const float4*>(&At[k * 72 + mt * 8 + 4]);
            float am[8] = {A0.x, A0.y, A0.z, A0.w, A1.x, A1.y, A1.z, A1.w};
#pragma unroll
            for (int c = 0; c < 3; c++) {
                float w = Wt[k * 96 + jt + 32 * c];
#pragma unroll
                for (int i = 0; i < 8; i++) acc[i][c] += am[i] * w;
            }
        }
        __syncthreads();
    }
#pragma unroll
    for (int i = 0; i < 8; i++) {
        int n = n0 + mt * 8 + i;
#pragma unroll
        for (int c = 0; c < 3; c++) {
            int j = jt + 32 * c;
            float bb = (j < 64) ? b_ea1[j] : b_as[j - 64];
            g_nbase[(size_t)n * 96 + j] = acc[i][c] + bb;
        }
    }
}

// ================= edge GEMM via mma.sync bf16, K=64 (nei part hoisted) =================
// M=64 edges, N=192, K=64. smem halves stride 72 (144B rows, conflict-free).
#define ET_WH 0
#define ET_WL 27648
#define ET_AH 55296
#define ET_AL 64512
#define ET_IDX 73728
#define ET_SMEM 74752

__global__ __launch_bounds__(512, 2) void k_edge_tc(
    const float* __restrict__ edge_ebd,
    const float* __restrict__ sw, const int* __restrict__ n_ext2e,
    const float* __restrict__ W_ne, const float* __restrict__ W_es,
    const float* __restrict__ e_res0, float* __restrict__ out_edge) {
    extern __shared__ char smc[];
    uint32_t sb = smem_u32(smc);
    int tid = threadIdx.x;
    int wid = tid >> 5;
    int lane = tid & 31;
    int wm = wid >> 2;
    int wn = wid & 3;

    int* eidv = (int*)(smc + ET_IDX);
    int* nodev = eidv + 64;
    int* neiv = nodev + 64;
    float* sws = (float*)(neiv + 64);

    // weights rows 256..319 (edge part), [n=192][k=64], bf16 hi/lo
    for (int idx = tid; idx < 192 * 64; idx += 512) {
        int j = idx / 64, k = idx % 64;
        int row = 256 + k;
        float w = (j < 128) ? W_ne[(size_t)row * 128 + j] : W_es[(size_t)row * 64 + (j - 128)];
        __nv_bfloat16 h = __float2bfloat16(w);
        float l = w - __bfloat162float(h);
        *reinterpret_cast<__nv_bfloat16*>(smc + ET_WH + (j * 72 + k) * 2) = h;
        *reinterpret_cast<__nv_bfloat16*>(smc + ET_WL + (j * 72 + k) * 2) = __float2bfloat16(l);
    }

    uint32_t aRow = wm * 16 + (lane & 15);
    uint32_t aColH = (lane >> 4);
    uint32_t aAddrH = sb + ET_AH + (aRow * 72 + aColH * 8) * 2;
    uint32_t aAddrL = sb + ET_AL + (aRow * 72 + aColH * 8) * 2;
    int nrow = wn * 48 + (lane & 7) + ((lane & 16) ? 8 : 0);
    int khalf = (lane & 8) ? 8 : 0;
    uint32_t bAddrH = sb + ET_WH + (nrow * 72 + khalf) * 2;
    uint32_t bAddrL = sb + ET_WL + (nrow * 72 + khalf) * 2;

    int mfill = tid & 63;
    int seg = tid >> 6;   // 0..7, 8 floats each

    for (int ch = blockIdx.x; ch < NEDGE / 64; ch += gridDim.x) {
        int c0 = ch * 64;
        __syncthreads();
        if (tid < 64) {
            int e = g_eids[c0 + tid];
            eidv[tid] = e;
            nodev[tid] = g_enode[c0 + tid];
            neiv[tid] = n_ext2e[e];
            sws[tid] = sw[e];
        }
        {
            int e = __ldg(&g_eids[c0 + mfill]);
            const float4* erowp = (const float4*)(edge_ebd + (size_t)e * EDIM);
            uint32_t rowoff = (uint32_t)mfill * 72;
#pragma unroll
            for (int q = 0; q < 2; q++) {
                int kk = seg * 8 + q * 4;
                float4 v = erowp[kk >> 2];
                __nv_bfloat16 h0 = __float2bfloat16(v.x);
                __nv_bfloat16 h1 = __float2bfloat16(v.y);
                __nv_bfloat16 h2 = __float2bfloat16(v.z);
                __nv_bfloat16 h3 = __float2bfloat16(v.w);
                uint32_t hi01, hi23;
                { __nv_bfloat162 t; t.x = h0; t.y = h1; hi01 = *reinterpret_cast<uint32_t*>(&t); }
                { __nv_bfloat162 t; t.x = h2; t.y = h3; hi23 = *reinterpret_cast<uint32_t*>(&t); }
                uint32_t lo01 = bfp(v.x - __bfloat162float(h0), v.y - __bfloat162float(h1));
                uint32_t lo23 = bfp(v.z - __bfloat162float(h2), v.w - __bfloat162float(h3));
                uint32_t boff = (rowoff + kk) * 2;
                *reinterpret_cast<uint32_t*>(smc + ET_AH + boff) = hi01;
                *reinterpret_cast<uint32_t*>(smc + ET_AH + boff + 4) = hi23;
                *reinterpret_cast<uint32_t*>(smc + ET_AL + boff) = lo01;
                *reinterpret_cast<uint32_t*>(smc + ET_AL + boff + 4) = lo23;
            }
        }
        __syncthreads();

        float d[6][4];
#pragma unroll
        for (int nt = 0; nt < 6; nt++)
#pragma unroll
            for (int q = 0; q < 4; q++) d[nt][q] = 0.f;

#pragma unroll
        for (int s = 0; s < 4; s++) {
            uint32_t ah[4], al[4];
            ldsm4(ah, aAddrH + s * 32);
            ldsm4(al, aAddrL + s * 32);
#pragma unroll
            for (int pr = 0; pr < 3; pr++) {
                uint32_t bh[4], bl[4];
                ldsm4(bh, bAddrH + pr * 16 * 144 + s * 32);
                ldsm4(bl, bAddrL + pr * 16 * 144 + s * 32);
                mma_bf16(d[pr * 2], ah, bh);
                mma_bf16(d[pr * 2], ah, bl);
                mma_bf16(d[pr * 2], al, bh);
                mma_bf16(d[pr * 2 + 1], ah, bh + 2);
                mma_bf16(d[pr * 2 + 1], ah, bl + 2);
                mma_bf16(d[pr * 2 + 1], al, bh + 2);
            }
        }

        int g = lane >> 2, qt = lane & 3;
        int r0 = wm * 16 + g, r1 = r0 + 8;
        int nd0 = nodev[r0], nd1 = nodev[r1];
        int ne0 = neiv[r0], ne1 = neiv[r1];
        float sw0 = sws[r0], sw1 = sws[r1];
        int ee0 = eidv[r0], ee1 = eidv[r1];
        bool samend = (nd0 == nd1);
#pragma unroll
        for (int nt = 0; nt < 6; nt++) {
            int j0 = wn * 48 + nt * 8 + qt * 2;
            float2 b0v = *(const float2*)(g_base + (size_t)nd0 * 192 + j0);
            float2 b1v = *(const float2*)(g_base + (size_t)nd1 * 192 + j0);
            float2 c0v = *(const float2*)(g_base2 + (size_t)ne0 * 192 + j0);
            float2 c1v = *(const float2*)(g_base2 + (size_t)ne1 * 192 + j0);
            float y00 = silu_f(d[nt][0] + b0v.x + c0v.x);
            float y01 = silu_f(d[nt][1] + b0v.y + c0v.y);
            float y10 = silu_f(d[nt][2] + b1v.x + c1v.x);
            float y11 = silu_f(d[nt][3] + b1v.y + c1v.y);
            if (j0 < 128) {
                float v00 = y00 * sw0, v01 = y01 * sw0;
                float v10 = y10 * sw1, v11 = y11 * sw1;
                if (samend) {
                    atomicAdd(&g_msg[(size_t)nd0 * NDIM + j0], v00 + v10);
                    atomicAdd(&g_msg[(size_t)nd0 * NDIM + j0 + 1], v01 + v11);
                } else {
                    atomicAdd(&g_msg[(size_t)nd0 * NDIM + j0], v00);
                    atomicAdd(&g_msg[(size_t)nd0 * NDIM + j0 + 1], v01);
                    atomicAdd(&g_msg[(size_t)nd1 * NDIM + j0], v10);
                    atomicAdd(&g_msg[(size_t)nd1 * NDIM + j0 + 1], v11);
                }
            } else {
                int col = j0 - 128;
                float2 er = *(const float2*)(e_res0 + col);
                size_t o0 = (size_t)ee0 * EDIM + col;
                size_t o1 = (size_t)ee1 * EDIM + col;
                float2 eb0 = *(const float2*)(edge_ebd + o0);
                float2 eb1 = *(const float2*)(edge_ebd + o1);
                *(float2*)(out_edge + o0) = make_float2(eb0.x + er.x * y00, eb0.y + er.y * y01);
                *(float2*)(out_edge + o1) = make_float2(eb1.x + er.x * y10, eb1.y + er.y * y11);
            }
        }
    }
}

__global__ void k_node_finish(const float* __restrict__ n_res2, float* __restrict__ out_node) {
    int i = blockIdx.x * blockDim.x + threadIdx.x;
    if (i < NLOC * NDIM) {
        int j = i & (NDIM - 1);
        out_node[i] += n_res2[j] * g_msg[i] * INV_DYN_E;
    }
}

// ================= angle GEMM via mma.sync bf16 3-term split =================
#define AT_WH 0
#define AT_WL 32256
#define AT_AH 64512
#define AT_AL 86016
#define AT_IDX 107520
#define AT_SMEM 108288

__global__ __launch_bounds__(512, 2) void k_angle_tc(
    const float* __restrict__ angle_ebd, const float* __restrict__ edge_ebd,
    const int* __restrict__ ai, const float* __restrict__ a_sw,
    const float* __restrict__ W_ea1, const float* __restrict__ W_as,
    const float* __restrict__ a_res0, float* __restrict__ out_angle) {
    extern __shared__ char smc[];
    uint32_t sb = smem_u32(smc);
    int tid = threadIdx.x;
    int wid = tid >> 5;
    int lane = tid & 31;
    int wm = wid >> 2;
    int wn = wid & 3;

    int* nav = (int*)(smc + AT_IDX);
    int* ijav = nav + 64;
    float* aswv = (float*)(ijav + 64);

    const int* n2a = ai;
    const int* eij = ai + NANGLE;
    const int* eik = ai + 2 * NANGLE;

    for (int idx = tid; idx < 96 * 160; idx += 512) {
        int j = idx / 160, k = idx % 160;
        int srck = (k < 32) ? k : ((k < 96) ? 160 + (k - 32) : 224 + (k - 96));
        float w = (j < 64) ? W_ea1[(size_t)srck * 64 + j] : W_as[(size_t)srck * 32 + (j - 64)];
        __nv_bfloat16 h = __float2bfloat16(w);
        float l = w - __bfloat162float(h);
        *reinterpret_cast<__nv_bfloat16*>(smc + AT_WH + (j * 168 + k) * 2) = h;
        *reinterpret_cast<__nv_bfloat16*>(smc + AT_WL + (j * 168 + k) * 2) = __float2bfloat16(l);
    }

    uint32_t aRow = wm * 16 + (lane & 15);
    uint32_t aColH = (lane >> 4);
    uint32_t aAddrH = sb + AT_AH + (aRow * 168 + aColH * 8) * 2;
    uint32_t aAddrL = sb + AT_AL + (aRow * 168 + aColH * 8) * 2;
    int nrow = wn * 24 + (lane & 7) + ((lane & 16) ? 8 : 0);
    int khalf = (lane & 8) ? 8 : 0;
    uint32_t bAddrH = sb + AT_WH + (nrow * 168 + khalf) * 2;
    uint32_t bAddrL = sb + AT_WL + (nrow * 168 + khalf) * 2;
    int nrow2 = wn * 24 + 16 + (lane & 7);
    int khalf2 = (lane & 8) ? 8 : 0;
    uint32_t b2AddrH = sb + AT_WH + (nrow2 * 168 + khalf2) * 2;
    uint32_t b2AddrL = sb + AT_WL + (nrow2 * 168 + khalf2) * 2;

    int mfill = tid & 63;
    int seg = tid >> 6;

    for (int t = blockIdx.x; t < NANGLE / 64; t += gridDim.x) {
        int a0 = t * 64;
        __syncthreads();
        if (tid < 64) {
            nav[tid] = n2a[a0 + tid];
            ijav[tid] = eij[a0 + tid];
            aswv[tid] = a_sw[a0 + tid];
        }
        {
            int a = a0 + mfill;
            int ek = __ldg(&eik[a]);
            int ej = __ldg(&eij[a]);
            const float4* arow = (const float4*)(angle_ebd + (size_t)a * ADIM);
            const float4* krow = (const float4*)(edge_ebd + (size_t)ek * EDIM);
            const float4* jrow = (const float4*)(edge_ebd + (size_t)ej * EDIM);
            uint32_t rowoff = (uint32_t)mfill * 168;
#pragma unroll
            for (int q = 0; q < 5; q++) {
                int kk = seg * 20 + q * 4;
                float4 v = (kk < 32) ? arow[kk >> 2]
                         : (kk < 96) ? krow[(kk - 32) >> 2]
                                     : jrow[(kk - 96) >> 2];
                __nv_bfloat16 h0 = __float2bfloat16(v.x);
                __nv_bfloat16 h1 = __float2bfloat16(v.y);
                __nv_bfloat16 h2 = __float2bfloat16(v.z);
                __nv_bfloat16 h3 = __float2bfloat16(v.w);
                uint32_t hi01, hi23;
                { __nv_bfloat162 tt; tt.x = h0; tt.y = h1; hi01 = *reinterpret_cast<uint32_t*>(&tt); }
                { __nv_bfloat162 tt; tt.x = h2; tt.y = h3; hi23 = *reinterpret_cast<uint32_t*>(&tt); }
                uint32_t lo01 = bfp(v.x - __bfloat162float(h0), v.y - __bfloat162float(h1));
                uint32_t lo23 = bfp(v.z - __bfloat162float(h2), v.w - __bfloat162float(h3));
                uint32_t boff = (rowoff + kk) * 2;
                *reinterpret_cast<uint32_t*>(smc + AT_AH + boff) = hi01;
                *reinterpret_cast<uint32_t*>(smc + AT_AH + boff + 4) = hi23;
                *reinterpret_cast<uint32_t*>(smc + AT_AL + boff) = lo01;
                *reinterpret_cast<uint32_t*>(smc + AT_AL + boff + 4) = lo23;
            }
        }
        __syncthreads();

        float d[3][4];
#pragma unroll
        for (int nt = 0; nt < 3; nt++)
#pragma unroll
            for (int q = 0; q < 4; q++) d[nt][q] = 0.f;

#pragma unroll
        for (int s = 0; s < 10; s++) {
            uint32_t ah[4], al[4];
            ldsm4(ah, aAddrH + s * 32);
            ldsm4(al, aAddrL + s * 32);
            uint32_t bh[4], bl[4], b2h[2], b2l[2];
            ldsm4(bh, bAddrH + s * 32);
            ldsm4(bl, bAddrL + s * 32);
            ldsm2(b2h, b2AddrH + s * 32);
            ldsm2(b2l, b2AddrL + s * 32);
            mma_bf16(d[0], ah, bh);
            mma_bf16(d[0], ah, bl);
            mma_bf16(d[0], al, bh);
            mma_bf16(d[1], ah, bh + 2);
            mma_bf16(d[1], ah, bl + 2);
            mma_bf16(d[1], al, bh + 2);
            mma_bf16(d[2], ah, b2h);
            mma_bf16(d[2], ah, b2l);
            mma_bf16(d[2], al, b2h);
        }

        int g = lane >> 2, qt = lane & 3;
        int r0 = wm * 16 + g, r1 = r0 + 8;
        int nd0 = nav[r0], nd1 = nav[r1];
        float sw0 = aswv[r0], sw1 = aswv[r1];
        int ij0 = ijav[r0], ij1 = ijav[r1];
#pragma unroll
        for (int nt = 0; nt < 3; nt++) {
            int j0 = wn * 24 + nt * 8 + qt * 2;
            float2 nb0 = *(const float2*)(g_nbase + (size_t)nd0 * 96 + j0);
            float2 nb1 = *(const float2*)(g_nbase + (size_t)nd1 * 96 + j0);
            float y00 = silu_f(d[nt][0] + nb0.x);
            float y01 = silu_f(d[nt][1] + nb0.y);
            float y10 = silu_f(d[nt][2] + nb1.x);
            float y11 = silu_f(d[nt][3] + nb1.y);
            if (j0 < 64) {
                atomicAdd(&g_reduced[(size_t)ij0 * EDIM + j0], y00 * sw0);
                atomicAdd(&g_reduced[(size_t)ij0 * EDIM + j0 + 1], y01 * sw0);
                atomicAdd(&g_reduced[(size_t)ij1 * EDIM + j0], y10 * sw1);
                atomicAdd(&g_reduced[(size_t)ij1 * EDIM + j0 + 1], y11 * sw1);
            } else {
                int col = j0 - 64;
                float2 arr = *(const float2*)(a_res0 + col);
                size_t o0 = (size_t)(a0 + r0) * ADIM + col;
                size_t o1 = (size_t)(a0 + r1) * ADIM + col;
                float2 ae0 = *(const float2*)(angle_ebd + o0);
                float2 ae1 = *(const float2*)(angle_ebd + o1);
                *(float2*)(out_angle + o0) = make_float2(ae0.x + arr.x * y00, ae0.y + arr.y * y01);
                *(float2*)(out_angle + o1) = make_float2(ae1.x + arr.x * y10, ae1.y + arr.y * y11);
            }
        }
    }
}

// ================= edge angle message GEMM via mma.sync bf16 =================
__global__ __launch_bounds__(256) void k_edge_msg(const float* __restrict__ W2,
                                                  const float* __restrict__ b2,
                                                  const float* __restrict__ e_res1,
                                                  float* __restrict__ out_edge) {
    __shared__ __align__(16) __nv_bfloat16 Wh[64 * 72];
    __shared__ __align__(16) __nv_bfloat16 Wl[64 * 72];
    __shared__ __align__(16) __nv_bfloat16 Ah[64 * 72];
    __shared__ __align__(16) __nv_bfloat16 Al[64 * 72];
    int tid = threadIdx.x;
    int wid = tid >> 5;
    int lane = tid & 31;
    int wm = wid >> 1;
    int wn = wid & 1;
    int e0 = blockIdx.x * 64;

    for (int idx = tid; idx < 64 * 64; idx += 256) {
        int j = idx >> 6, k = idx & 63;
        float w = W2[k * 64 + j];
        __nv_bfloat16 h = __float2bfloat16(w);
        Wh[j * 72 + k] = h;
        Wl[j * 72 + k] = __float2bfloat16(w - __bfloat162float(h));
    }
    {
        int m = tid & 63, seg = tid >> 6;
        const float4* src = (const float4*)(g_reduced + (size_t)(e0 + m) * EDIM + seg * 16);
#pragma unroll
        for (int q = 0; q < 4; q++) {
            float4 v = src[q];
            int kk = seg * 16 + q * 4;
            __nv_bfloat16 h0 = __float2bfloat16(v.x);
            __nv_bfloat16 h1 = __float2bfloat16(v.y);
            __nv_bfloat16 h2 = __float2bfloat16(v.z);
            __nv_bfloat16 h3 = __float2bfloat16(v.w);
            Ah[m * 72 + kk + 0] = h0;
            Ah[m * 72 + kk + 1] = h1;
            Ah[m * 72 + kk + 2] = h2;
            Ah[m * 72 + kk + 3] = h3;
            Al[m * 72 + kk + 0] = __float2bfloat16(v.x - __bfloat162float(h0));
            Al[m * 72 + kk + 1] = __float2bfloat16(v.y - __bfloat162float(h1));
            Al[m * 72 + kk + 2] = __float2bfloat16(v.z - __bfloat162float(h2));
            Al[m * 72 + kk + 3] = __float2bfloat16(v.w - __bfloat162float(h3));
        }
    }
    __syncthreads();

    uint32_t aRow = wm * 16 + (lane & 15);
    uint32_t aColH = (lane >> 4);
    uint32_t aAddrH = smem_u32(Ah) + (aRow * 72 + aColH * 8) * 2;
    uint32_t aAddrL = smem_u32(Al) + (aRow * 72 + aColH * 8) * 2;
    int nrow = wn * 32 + (lane & 7) + ((lane & 16) ? 8 : 0);
    int khalf = (lane & 8) ? 8 : 0;
    uint32_t bAddrH = smem_u32(Wh) + (nrow * 72 + khalf) * 2;
    uint32_t bAddrL = smem_u32(Wl) + (nrow * 72 + khalf) * 2;
    uint32_t b2AddrH = bAddrH + 16 * 144;
    uint32_t b2AddrL = bAddrL + 16 * 144;

    float d[4][4];
#pragma unroll
    for (int nt = 0; nt < 4; nt++)
#pragma unroll
        for (int q = 0; q < 4; q++) d[nt][q] = 0.f;

#pragma unroll
    for (int s = 0; s < 4; s++) {
        uint32_t ah[4], al[4];
        ldsm4(ah, aAddrH + s * 32);
        ldsm4(al, aAddrL + s * 32);
        uint32_t bh[4], bl[4], ch[4], cl[4];
        ldsm4(bh, bAddrH + s * 32);
        ldsm4(bl, bAddrL + s * 32);
        ldsm4(ch, b2AddrH + s * 32);
        ldsm4(cl, b2AddrL + s * 32);
        mma_bf16(d[0], ah, bh);
        mma_bf16(d[0], ah, bl);
        mma_bf16(d[0], al, bh);
        mma_bf16(d[1], ah, bh + 2);
        mma_bf16(d[1], ah, bl + 2);
        mma_bf16(d[1], al, bh + 2);
        mma_bf16(d[2], ah, ch);
        mma_bf16(d[2], ah, cl);
        mma_bf16(d[2], al, ch);
        mma_bf16(d[3], ah, ch + 2);
        mma_bf16(d[3], ah, cl + 2);
        mma_bf16(d[3], al, ch + 2);
    }

    int g = lane >> 2, qt = lane & 3;
    int r0 = wm * 16 + g, r1 = r0 + 8;
#pragma unroll
    for (int nt = 0; nt < 4; nt++) {
        int j0 = wn * 32 + nt * 8 + qt * 2;
        float2 bb = *(const float2*)(b2 + j0);
        float2 er = *(const float2*)(e_res1 + j0);
        size_t o0 = (size_t)(e0 + r0) * EDIM + j0;
        size_t o1 = (size_t)(e0 + r1) * EDIM + j0;
        float2 v0 = *(float2*)(out_edge + o0);
        float2 v1 = *(float2*)(out_edge + o1);
        v0.x += er.x * silu_f(d[nt][0] + bb.x);
        v0.y += er.y * silu_f(d[nt][1] + bb.y);
        v1.x += er.x * silu_f(d[nt][2] + bb.x);
        v1.y += er.y * silu_f(d[nt][3] + bb.y);
        *(float2*)(out_edge + o0) = v0;
        *(float2*)(out_edge + o1) = v1;
    }
}

// ---------------- launch ----------------
extern "C" void kernel_launch(void* const* d_in, const int* in_sizes, int n_in,
                              void* d_out, int out_size) {
    const float* node_ext   = (const float*)d_in[0];
    const float* edge_ebd   = (const float*)d_in[1];
    const float* h2         = (const float*)d_in[2];
    const float* angle_ebd  = (const float*)d_in[3];
    const float* sw         = (const float*)d_in[6];
    const float* a_sw       = (const float*)d_in[9];
    const int*   edge_index = (const int*)d_in[10];
    const int*   angle_index= (const int*)d_in[11];
    const float* W_node_self = (const float*)d_in[12];
    const float* b_node_self = (const float*)d_in[13];
    const float* W_node_sym  = (const float*)d_in[14];
    const float* b_node_sym  = (const float*)d_in[15];
    const float* W_node_edge = (const float*)d_in[16];
    const float* b_node_edge = (const float*)d_in[17];
    const float* W_edge_self = (const float*)d_in[18];
    const float* b_edge_self = (const float*)d_in[19];
    const float* W_edge_angle1 = (const float*)d_in[20];
    const float* b_edge_angle1 = (const float*)d_in[21];
    const float* W_edge_angle2 = (const float*)d_in[22];
    const float* b_edge_angle2 = (const float*)d_in[23];
    const float* W_angle_self  = (const float*)d_in[24];
    const float* b_angle_self  = (const float*)d_in[25];
    const float* n_res0 = (const float*)d_in[26];
    const float* n_res1 = (const float*)d_in[27];
    const float* n_res2 = (const float*)d_in[28];
    const float* e_res0 = (const float*)d_in[29];
    const float* e_res1 = (const float*)d_in[30];
    const float* a_res0 = (const float*)d_in[31];

    float* out = (float*)d_out;
    float* out_node  = out;
    float* out_edge  = out + (size_t)NLOC * NDIM;
    float* out_angle = out_edge + (size_t)NEDGE * EDIM;

    const int* n2e = edge_index;
    const int* n_ext2e = edge_index + NEDGE;

    cudaFuncSetAttribute((const void*)k_edge_tc,
                         cudaFuncAttributeMaxDynamicSharedMemorySize, ET_SMEM);
    cudaFuncSetAttribute((const void*)k_angle_tc,
                         cudaFuncAttributeMaxDynamicSharedMemorySize, AT_SMEM);

    k_zero<<<4096, 256>>>();
    k_count<<<NEDGE / 256, 256>>>(n2e);
    k_scan<<<1, 1024>>>();
    k_scatter<<<NEDGE / 256, 256>>>(n2e);
    k_sym<<<NLOC, 768>>>(edge_ebd, node_ext, h2, sw, n_ext2e);
    k_symmm<<<NLOC / 64, 256>>>(W_node_sym, b_node_sym, n_res1,
                                W_node_self, b_node_self, n_res0, node_ext, out_node);
    k_base<<<NLOC / 64, 256>>>(node_ext, W_node_edge, W_edge_self, b_node_edge, b_edge_self);
    k_base2<<<NALL / 64, 256>>>(node_ext, W_node_edge, W_edge_self);
    k_nbase<<<NLOC / 64, 256>>>(node_ext, W_edge_angle1, W_angle_self,
                                b_edge_angle1, b_angle_self);
    k_edge_tc<<<296, 512, ET_SMEM>>>(edge_ebd, sw, n_ext2e,
                                     W_node_edge, W_edge_self, e_res0, out_edge);
    k_node_finish<<<NLOC * NDIM / 256, 256>>>(n_res2, out_node);
    k_angle_tc<<<296, 512, AT_SMEM>>>(angle_ebd, edge_ebd, angle_index, a_sw,
                                      W_edge_angle1, W_angle_self, a_res0, out_angle);
    k_edge_msg<<<NEDGE / 64, 256>>>(W_edge_angle2, b_edge_angle2, e_res1, out_edge);
}

// round 14
// speedup vs baseline: 4.8557x; 1.1184x over previous
#include <cuda_runtime.h>
#include <cuda_bf16.h>
#include <cstdint>
#include <cstddef>

#define NLOC   4096
#define NALL   6144
#define NDIM   128
#define EDIM   64
#define ADIM   32
#define NEDGE  262144
#define NANGLE 409600
#define INV_DYN_E 0.15625f            // 1/6.4
#define SYM_SCALE 0.0520833333333f    // (1/6.4)/3

// ---------------- device scratch ----------------
__device__ float g_sym[(size_t)NLOC * 768];
__device__ float g_base[(size_t)NLOC * 192];
__device__ float g_base2[(size_t)NALL * 192];
__device__ float g_nbase[(size_t)NLOC * 96];
__device__ float g_reduced[(size_t)NEDGE * EDIM];
__device__ float g_msg[(size_t)NLOC * NDIM];
__device__ int   g_ecnt[NLOC];
__device__ int   g_eoff[NLOC + 1];
__device__ int   g_ecur[NLOC];
__device__ int   g_eids[NEDGE];
__device__ int   g_enode[NEDGE];

// ---------------- helpers ----------------
__device__ __forceinline__ float silu_f(float x) { return x / (1.0f + __expf(-x)); }

__device__ __forceinline__ uint32_t smem_u32(const void* p) {
    uint32_t a;
    asm("{ .reg .u64 t; cvta.to.shared.u64 t, %1; cvt.u32.u64 %0, t; }" : "=r"(a) : "l"(p));
    return a;
}

__device__ __forceinline__ void ldsm4(uint32_t* r, uint32_t addr) {
    asm volatile("ldmatrix.sync.aligned.m8n8.x4.shared.b16 {%0,%1,%2,%3}, [%4];"
                 : "=r"(r[0]), "=r"(r[1]), "=r"(r[2]), "=r"(r[3]) : "r"(addr));
}
__device__ __forceinline__ void ldsm2(uint32_t* r, uint32_t addr) {
    asm volatile("ldmatrix.sync.aligned.m8n8.x2.shared.b16 {%0,%1}, [%2];"
                 : "=r"(r[0]), "=r"(r[1]) : "r"(addr));
}

__device__ __forceinline__ void mma_bf16(float* d, const uint32_t* a, const uint32_t* b) {
    asm volatile(
        "mma.sync.aligned.m16n8k16.row.col.f32.bf16.bf16.f32 "
        "{%0,%1,%2,%3}, {%4,%5,%6,%7}, {%8,%9}, {%0,%1,%2,%3};"
        : "+f"(d[0]), "+f"(d[1]), "+f"(d[2]), "+f"(d[3])
        : "r"(a[0]), "r"(a[1]), "r"(a[2]), "r"(a[3]), "r"(b[0]), "r"(b[1]));
}

__device__ __forceinline__ uint32_t bfp(float a, float b) {
    __nv_bfloat162 t = __floats2bfloat162_rn(a, b);
    return *reinterpret_cast<uint32_t*>(&t);
}

// ---------------- zero scratch ----------------
__global__ void k_zero() {
    size_t i0 = (size_t)blockIdx.x * blockDim.x + threadIdx.x;
    size_t stride = (size_t)gridDim.x * blockDim.x;
    float4* r = reinterpret_cast<float4*>(g_reduced);
    size_t n4 = (size_t)NEDGE * EDIM / 4;
    for (size_t i = i0; i < n4; i += stride) r[i] = make_float4(0.f, 0.f, 0.f, 0.f);
    float4* m = reinterpret_cast<float4*>(g_msg);
    size_t m4 = (size_t)NLOC * NDIM / 4;
    for (size_t i = i0; i < m4; i += stride) m[i] = make_float4(0.f, 0.f, 0.f, 0.f);
    if (i0 < NLOC) g_ecnt[i0] = 0;
}

// ---------------- CSR build ----------------
__global__ void k_count(const int* __restrict__ n2e) {
    int e = blockIdx.x * blockDim.x + threadIdx.x;
    if (e < NEDGE) atomicAdd(&g_ecnt[n2e[e]], 1);
}

__global__ void k_scan() {
    __shared__ int sh[1024];
    int t = threadIdx.x;
    int c[4];
#pragma unroll
    for (int i = 0; i < 4; i++) c[i] = g_ecnt[t * 4 + i];
    int tot = c[0] + c[1] + c[2] + c[3];
    sh[t] = tot;
    __syncthreads();
    for (int st = 1; st < 1024; st <<= 1) {
        int add = (t >= st) ? sh[t - st] : 0;
        __syncthreads();
        sh[t] += add;
        __syncthreads();
    }
    int run = sh[t] - tot;
#pragma unroll
    for (int i = 0; i < 4; i++) {
        g_eoff[t * 4 + i] = run;
        g_ecur[t * 4 + i] = run;
        run += c[i];
    }
    if (t == 1023) g_eoff[NLOC] = run;
}

__global__ void k_scatter(const int* __restrict__ n2e) {
    int e = blockIdx.x * blockDim.x + threadIdx.x;
    if (e < NEDGE) {
        int n = n2e[e];
        int pos = atomicAdd(&g_ecur[n], 1);
        g_eids[pos] = e;
        g_enode[pos] = n;
    }
}

// ---------------- sym op: 4-way edge parallelism ----------------
__global__ __launch_bounds__(768) void k_sym(
    const float* __restrict__ edge_ebd, const float* __restrict__ node_ext,
    const float* __restrict__ h2, const float* __restrict__ sw,
    const int* __restrict__ n_ext2e) {
    __shared__ float P[4][3][192];
    __shared__ float S0[192], S1[192], S2[192];
    __shared__ float symv[768];
    int n = blockIdx.x;
    int t = threadIdx.x;
    int g = t / 192;
    int f = t - g * 192;
    int beg = g_eoff[n], end = g_eoff[n + 1];
    float a0 = 0.f, a1 = 0.f, a2 = 0.f;
    for (int i = beg + g; i < end; i += 4) {
        int e = g_eids[i];
        float swv = sw[e];
        float h0 = h2[e * 3 + 0] * swv;
        float h1 = h2[e * 3 + 1] * swv;
        float hh = h2[e * 3 + 2] * swv;
        float val = (f < 64) ? edge_ebd[(size_t)e * EDIM + f]
                             : node_ext[(size_t)n_ext2e[e] * NDIM + (f - 64)];
        a0 += h0 * val;
        a1 += h1 * val;
        a2 += hh * val;
    }
    P[g][0][f] = a0; P[g][1][f] = a1; P[g][2][f] = a2;
    __syncthreads();
    if (t < 192) {
        S0[t] = P[0][0][t] + P[1][0][t] + P[2][0][t] + P[3][0][t];
    } else if (t < 384) {
        int tt = t - 192;
        S1[tt] = P[0][1][tt] + P[1][1][tt] + P[2][1][tt] + P[3][1][tt];
    } else if (t < 576) {
        int tt = t - 384;
        S2[tt] = P[0][2][tt] + P[1][2][tt] + P[2][2][tt] + P[3][2][tt];
    }
    __syncthreads();
    if (t < 64) {
#pragma unroll
        for (int a = 0; a < 4; a++)
            symv[a * 64 + t] = SYM_SCALE * (S0[a] * S0[t] + S1[a] * S1[t] + S2[a] * S2[t]);
    } else if (t < 192) {
        int dn = t - 64;
#pragma unroll
        for (int a = 0; a < 4; a++)
            symv[256 + a * 128 + dn] =
                SYM_SCALE * (S0[64 + a] * S0[t] + S1[64 + a] * S1[t] + S2[64 + a] * S2[t]);
    }
    __syncthreads();
    g_sym[(size_t)n * 768 + t] = symv[t];
}

// ---------------- node_sym GEMM fused with node_self ----------------
__global__ __launch_bounds__(256) void k_symmm(
    const float* __restrict__ W_sym, const float* __restrict__ b_sym,
    const float* __restrict__ n_res1,
    const float* __restrict__ W_self, const float* __restrict__ b_self,
    const float* __restrict__ n_res0,
    const float* __restrict__ node_ext, float* __restrict__ out_node) {
    __shared__ float Wt[32 * 128];
    __shared__ float At[32 * 72];
    int tid = threadIdx.x;
    int jt = tid & 31, mt = tid >> 5;
    int n0 = blockIdx.x * 64;
    float acc0[8][4], acc1[8][4];
#pragma unroll
    for (int i = 0; i < 8; i++)
#pragma unroll
        for (int q = 0; q < 4; q++) { acc0[i][q] = 0.f; acc1[i][q] = 0.f; }

    for (int kt = 0; kt < 768; kt += 32) {
        for (int idx = tid; idx < 32 * 128; idx += 256)
            Wt[idx] = W_sym[(size_t)(kt + idx / 128) * 128 + (idx % 128)];
        for (int idx = tid; idx < 32 * 64; idx += 256) {
            int m = idx / 32, k = idx % 32;
            At[k * 72 + m] = g_sym[(size_t)(n0 + m) * 768 + kt + k];
        }
        __syncthreads();
#pragma unroll 4
        for (int k = 0; k < 32; k++) {
            float4 A0 = *reinterpret_cast<const float4*>(&At[k * 72 + mt * 8]);
            float4 A1 = *reinterpret_cast<const float4*>(&At[k * 72 + mt * 8 + 4]);
            float am[8] = {A0.x, A0.y, A0.z, A0.w, A1.x, A1.y, A1.z, A1.w};
            float4 wv = *reinterpret_cast<const float4*>(&Wt[k * 128 + jt * 4]);
            float wq[4] = {wv.x, wv.y, wv.z, wv.w};
#pragma unroll
            for (int i = 0; i < 8; i++)
#pragma unroll
                for (int q = 0; q < 4; q++) acc0[i][q] += am[i] * wq[q];
        }
        __syncthreads();
    }
    for (int kt = 0; kt < 128; kt += 32) {
        for (int idx = tid; idx < 32 * 128; idx += 256)
            Wt[idx] = W_self[(size_t)(kt + idx / 128) * 128 + (idx % 128)];
        for (int idx = tid; idx < 32 * 64; idx += 256) {
            int m = idx / 32, k = idx % 32;
            At[k * 72 + m] = node_ext[(size_t)(n0 + m) * NDIM + kt + k];
        }
        __syncthreads();
#pragma unroll 4
        for (int k = 0; k < 32; k++) {
            float4 A0 = *reinterpret_cast<const float4*>(&At[k * 72 + mt * 8]);
            float4 A1 = *reinterpret_cast<const float4*>(&At[k * 72 + mt * 8 + 4]);
            float am[8] = {A0.x, A0.y, A0.z, A0.w, A1.x, A1.y, A1.z, A1.w};
            float4 wv = *reinterpret_cast<const float4*>(&Wt[k * 128 + jt * 4]);
            float wq[4] = {wv.x, wv.y, wv.z, wv.w};
#pragma unroll
            for (int i = 0; i < 8; i++)
#pragma unroll
                for (int q = 0; q < 4; q++) acc1[i][q] += am[i] * wq[q];
        }
        __syncthreads();
    }
#pragma unroll
    for (int i = 0; i < 8; i++) {
        int n = n0 + mt * 8 + i;
#pragma unroll
        for (int q = 0; q < 4; q++) {
            int j = jt * 4 + q;
            float y1 = silu_f(acc0[i][q] + b_sym[j]);
            float y0 = silu_f(acc1[i][q] + b_self[j]);
            out_node[(size_t)n * 128 + j] =
                node_ext[(size_t)n * NDIM + j] + n_res0[j] * y0 + n_res1[j] * y1;
        }
    }
}

// ---------------- base precompute (dest part, 192 cols, W rows 0..127) ----------------
__global__ __launch_bounds__(256) void k_base(const float* __restrict__ node_ext,
                                              const float* __restrict__ W_ne,
                                              const float* __restrict__ W_es,
                                              const float* __restrict__ b_ne,
                                              const float* __restrict__ b_es) {
    __shared__ float Wt[32 * 192];
    __shared__ float At[32 * 72];
    int tid = threadIdx.x;
    int jt = tid & 31, mt = tid >> 5;
    int n0 = blockIdx.x * 64;
    float acc[8][6];
#pragma unroll
    for (int i = 0; i < 8; i++)
#pragma unroll
        for (int c = 0; c < 6; c++) acc[i][c] = 0.f;
    for (int kt = 0; kt < 128; kt += 32) {
        for (int idx = tid; idx < 32 * 192; idx += 256) {
            int k = idx / 192, j = idx % 192;
            int row = kt + k;
            Wt[idx] = (j < 128) ? W_ne[(size_t)row * 128 + j] : W_es[(size_t)row * 64 + (j - 128)];
        }
        for (int idx = tid; idx < 32 * 64; idx += 256) {
            int m = idx / 32, k = idx % 32;
            At[k * 72 + m] = node_ext[(size_t)(n0 + m) * NDIM + kt + k];
        }
        __syncthreads();
#pragma unroll 2
        for (int k = 0; k < 32; k++) {
            float4 A0 = *reinterpret_cast<const float4*>(&At[k * 72 + mt * 8]);
            float4 A1 = *reinterpret_cast<const float4*>(&At[k * 72 + mt * 8 + 4]);
            float am[8] = {A0.x, A0.y, A0.z, A0.w, A1.x, A1.y, A1.z, A1.w};
#pragma unroll
            for (int c = 0; c < 6; c++) {
                float w = Wt[k * 192 + jt + 32 * c];
#pragma unroll
                for (int i = 0; i < 8; i++) acc[i][c] += am[i] * w;
            }
        }
        __syncthreads();
    }
#pragma unroll
    for (int i = 0; i < 8; i++) {
        int n = n0 + mt * 8 + i;
#pragma unroll
        for (int c = 0; c < 6; c++) {
            int j = jt + 32 * c;
            float bb = (j < 128) ? b_ne[j] : b_es[j - 128];
            g_base[(size_t)n * 192 + j] = acc[i][c] + bb;
        }
    }
}

// ---------------- base2 precompute (nei part, all NALL nodes, W rows 128..255) ----------------
__global__ __launch_bounds__(256) void k_base2(const float* __restrict__ node_ext,
                                               const float* __restrict__ W_ne,
                                               const float* __restrict__ W_es) {
    __shared__ float Wt[32 * 192];
    __shared__ float At[32 * 72];
    int tid = threadIdx.x;
    int jt = tid & 31, mt = tid >> 5;
    int n0 = blockIdx.x * 64;
    float acc[8][6];
#pragma unroll
    for (int i = 0; i < 8; i++)
#pragma unroll
        for (int c = 0; c < 6; c++) acc[i][c] = 0.f;
    for (int kt = 0; kt < 128; kt += 32) {
        for (int idx = tid; idx < 32 * 192; idx += 256) {
            int k = idx / 192, j = idx % 192;
            int row = 128 + kt + k;
            Wt[idx] = (j < 128) ? W_ne[(size_t)row * 128 + j] : W_es[(size_t)row * 64 + (j - 128)];
        }
        for (int idx = tid; idx < 32 * 64; idx += 256) {
            int m = idx / 32, k = idx % 32;
            At[k * 72 + m] = node_ext[(size_t)(n0 + m) * NDIM + kt + k];
        }
        __syncthreads();
#pragma unroll 2
        for (int k = 0; k < 32; k++) {
            float4 A0 = *reinterpret_cast<const float4*>(&At[k * 72 + mt * 8]);
            float4 A1 = *reinterpret_cast<const float4*>(&At[k * 72 + mt * 8 + 4]);
            float am[8] = {A0.x, A0.y, A0.z, A0.w, A1.x, A1.y, A1.z, A1.w};
#pragma unroll
            for (int c = 0; c < 6; c++) {
                float w = Wt[k * 192 + jt + 32 * c];
#pragma unroll
                for (int i = 0; i < 8; i++) acc[i][c] += am[i] * w;
            }
        }
        __syncthreads();
    }
#pragma unroll
    for (int i = 0; i < 8; i++) {
        int n = n0 + mt * 8 + i;
#pragma unroll
        for (int c = 0; c < 6; c++) {
            int j = jt + 32 * c;
            g_base2[(size_t)n * 192 + j] = acc[i][c];
        }
    }
}

// ---------------- nbase precompute (angle kernel, 96 cols) ----------------
__global__ __launch_bounds__(256) void k_nbase(const float* __restrict__ node_ext,
                                               const float* __restrict__ W_ea1,
                                               const float* __restrict__ W_as,
                                               const float* __restrict__ b_ea1,
                                               const float* __restrict__ b_as) {
    __shared__ float Wt[32 * 96];
    __shared__ float At[32 * 72];
    int tid = threadIdx.x;
    int jt = tid & 31, mt = tid >> 5;
    int n0 = blockIdx.x * 64;
    float acc[8][3];
#pragma unroll
    for (int i = 0; i < 8; i++)
#pragma unroll
        for (int c = 0; c < 3; c++) acc[i][c] = 0.f;
    for (int kt = 0; kt < 128; kt += 32) {
        for (int idx = tid; idx < 32 * 96; idx += 256) {
            int k = idx / 96, j = idx % 96;
            int row = 32 + kt + k;
            Wt[idx] = (j < 64) ? W_ea1[(size_t)row * 64 + j] : W_as[(size_t)row * 32 + (j - 64)];
        }
        for (int idx = tid; idx < 32 * 64; idx += 256) {
            int m = idx / 32, k = idx % 32;
            At[k * 72 + m] = node_ext[(size_t)(n0 + m) * NDIM + kt + k];
        }
        __syncthreads();
#pragma unroll 2
        for (int k = 0; k < 32; k++) {
            float4 A0 = *reinterpret_cast<const float4*>(&At[k * 72 + mt * 8]);
            float4 A1 = *reinterpret_cast<const float4*>(&At[k * 72 + mt * 8 + 4]);
            float am[8] = {A0.x, A0.y, A0.z, A0.w, A1.x, A1.y, A1.z, A1.w};
#pragma unroll
            for (int c = 0; c < 3; c++) {
                float w = Wt[k * 96 + jt + 32 * c];
#pragma unroll
                for (int i = 0; i < 8; i++) acc[i][c] += am[i] * w;
            }
        }
        __syncthreads();
    }
#pragma unroll
    for (int i = 0; i < 8; i++) {
        int n = n0 + mt * 8 + i;
#pragma unroll
        for (int c = 0; c < 3; c++) {
            int j = jt + 32 * c;
            float bb = (j < 64) ? b_ea1[j] : b_as[j - 64];
            g_nbase[(size_t)n * 96 + j] = acc[i][c] + bb;
        }
    }
}

// ================= edge GEMM via mma.sync bf16 2-term split (AhBh+AlBh) =================
// M=64 edges, N=192, K=64. smem halves stride 72.
#define ET_WH 0
#define ET_AH 27648
#define ET_AL 36864
#define ET_IDX 46080
#define ET_SMEM 47104

__global__ __launch_bounds__(512, 2) void k_edge_tc(
    const float* __restrict__ edge_ebd,
    const float* __restrict__ sw, const int* __restrict__ n_ext2e,
    const float* __restrict__ W_ne, const float* __restrict__ W_es,
    const float* __restrict__ e_res0, float* __restrict__ out_edge) {
    extern __shared__ char smc[];
    uint32_t sb = smem_u32(smc);
    int tid = threadIdx.x;
    int wid = tid >> 5;
    int lane = tid & 31;
    int wm = wid >> 2;
    int wn = wid & 3;

    int* eidv = (int*)(smc + ET_IDX);
    int* nodev = eidv + 64;
    int* neiv = nodev + 64;
    float* sws = (float*)(neiv + 64);

    for (int idx = tid; idx < 192 * 64; idx += 512) {
        int j = idx / 64, k = idx % 64;
        int row = 256 + k;
        float w = (j < 128) ? W_ne[(size_t)row * 128 + j] : W_es[(size_t)row * 64 + (j - 128)];
        *reinterpret_cast<__nv_bfloat16*>(smc + ET_WH + (j * 72 + k) * 2) = __float2bfloat16(w);
    }

    uint32_t aRow = wm * 16 + (lane & 15);
    uint32_t aColH = (lane >> 4);
    uint32_t aAddrH = sb + ET_AH + (aRow * 72 + aColH * 8) * 2;
    uint32_t aAddrL = sb + ET_AL + (aRow * 72 + aColH * 8) * 2;
    int nrow = wn * 48 + (lane & 7) + ((lane & 16) ? 8 : 0);
    int khalf = (lane & 8) ? 8 : 0;
    uint32_t bAddrH = sb + ET_WH + (nrow * 72 + khalf) * 2;

    int mfill = tid & 63;
    int seg = tid >> 6;

    for (int ch = blockIdx.x; ch < NEDGE / 64; ch += gridDim.x) {
        int c0 = ch * 64;
        __syncthreads();
        if (tid < 64) {
            int e = g_eids[c0 + tid];
            eidv[tid] = e;
            nodev[tid] = g_enode[c0 + tid];
            neiv[tid] = n_ext2e[e];
            sws[tid] = sw[e];
        }
        {
            int e = __ldg(&g_eids[c0 + mfill]);
            const float4* erowp = (const float4*)(edge_ebd + (size_t)e * EDIM);
            uint32_t rowoff = (uint32_t)mfill * 72;
#pragma unroll
            for (int q = 0; q < 2; q++) {
                int kk = seg * 8 + q * 4;
                float4 v = erowp[kk >> 2];
                __nv_bfloat16 h0 = __float2bfloat16(v.x);
                __nv_bfloat16 h1 = __float2bfloat16(v.y);
                __nv_bfloat16 h2 = __float2bfloat16(v.z);
                __nv_bfloat16 h3 = __float2bfloat16(v.w);
                uint32_t hi01, hi23;
                { __nv_bfloat162 t; t.x = h0; t.y = h1; hi01 = *reinterpret_cast<uint32_t*>(&t); }
                { __nv_bfloat162 t; t.x = h2; t.y = h3; hi23 = *reinterpret_cast<uint32_t*>(&t); }
                uint32_t lo01 = bfp(v.x - __bfloat162float(h0), v.y - __bfloat162float(h1));
                uint32_t lo23 = bfp(v.z - __bfloat162float(h2), v.w - __bfloat162float(h3));
                uint32_t boff = (rowoff + kk) * 2;
                *reinterpret_cast<uint32_t*>(smc + ET_AH + boff) = hi01;
                *reinterpret_cast<uint32_t*>(smc + ET_AH + boff + 4) = hi23;
                *reinterpret_cast<uint32_t*>(smc + ET_AL + boff) = lo01;
                *reinterpret_cast<uint32_t*>(smc + ET_AL + boff + 4) = lo23;
            }
        }
        __syncthreads();

        float d[6][4];
#pragma unroll
        for (int nt = 0; nt < 6; nt++)
#pragma unroll
            for (int q = 0; q < 4; q++) d[nt][q] = 0.f;

#pragma unroll
        for (int s = 0; s < 4; s++) {
            uint32_t ah[4], al[4];
            ldsm4(ah, aAddrH + s * 32);
            ldsm4(al, aAddrL + s * 32);
#pragma unroll
            for (int pr = 0; pr < 3; pr++) {
                uint32_t bh[4];
                ldsm4(bh, bAddrH + pr * 16 * 144 + s * 32);
                mma_bf16(d[pr * 2], ah, bh);
                mma_bf16(d[pr * 2], al, bh);
                mma_bf16(d[pr * 2 + 1], ah, bh + 2);
                mma_bf16(d[pr * 2 + 1], al, bh + 2);
            }
        }

        int g = lane >> 2, qt = lane & 3;
        int r0 = wm * 16 + g, r1 = r0 + 8;
        int nd0 = nodev[r0], nd1 = nodev[r1];
        int ne0 = neiv[r0], ne1 = neiv[r1];
        float sw0 = sws[r0], sw1 = sws[r1];
        int ee0 = eidv[r0], ee1 = eidv[r1];
        bool samend = (nd0 == nd1);
#pragma unroll
        for (int nt = 0; nt < 6; nt++) {
            int j0 = wn * 48 + nt * 8 + qt * 2;
            float2 b0v = *(const float2*)(g_base + (size_t)nd0 * 192 + j0);
            float2 b1v = *(const float2*)(g_base + (size_t)nd1 * 192 + j0);
            float2 c0v = *(const float2*)(g_base2 + (size_t)ne0 * 192 + j0);
            float2 c1v = *(const float2*)(g_base2 + (size_t)ne1 * 192 + j0);
            float y00 = silu_f(d[nt][0] + b0v.x + c0v.x);
            float y01 = silu_f(d[nt][1] + b0v.y + c0v.y);
            float y10 = silu_f(d[nt][2] + b1v.x + c1v.x);
            float y11 = silu_f(d[nt][3] + b1v.y + c1v.y);
            if (j0 < 128) {
                float v00 = y00 * sw0, v01 = y01 * sw0;
                float v10 = y10 * sw1, v11 = y11 * sw1;
                if (samend) {
                    atomicAdd(&g_msg[(size_t)nd0 * NDIM + j0], v00 + v10);
                    atomicAdd(&g_msg[(size_t)nd0 * NDIM + j0 + 1], v01 + v11);
                } else {
                    atomicAdd(&g_msg[(size_t)nd0 * NDIM + j0], v00);
                    atomicAdd(&g_msg[(size_t)nd0 * NDIM + j0 + 1], v01);
                    atomicAdd(&g_msg[(size_t)nd1 * NDIM + j0], v10);
                    atomicAdd(&g_msg[(size_t)nd1 * NDIM + j0 + 1], v11);
                }
            } else {
                int col = j0 - 128;
                float2 er = *(const float2*)(e_res0 + col);
                size_t o0 = (size_t)ee0 * EDIM + col;
                size_t o1 = (size_t)ee1 * EDIM + col;
                float2 eb0 = *(const float2*)(edge_ebd + o0);
                float2 eb1 = *(const float2*)(edge_ebd + o1);
                *(float2*)(out_edge + o0) = make_float2(eb0.x + er.x * y00, eb0.y + er.y * y01);
                *(float2*)(out_edge + o1) = make_float2(eb1.x + er.x * y10, eb1.y + er.y * y11);
            }
        }
    }
}

__global__ void k_node_finish(const float* __restrict__ n_res2, float* __restrict__ out_node) {
    int i = blockIdx.x * blockDim.x + threadIdx.x;
    if (i < NLOC * NDIM) {
        int j = i & (NDIM - 1);
        out_node[i] += n_res2[j] * g_msg[i] * INV_DYN_E;
    }
}

// ================= angle GEMM via mma.sync bf16 2-term split =================
#define AT_WH 0
#define AT_AH 32256
#define AT_AL 53760
#define AT_IDX 75264
#define AT_SMEM 76032

__global__ __launch_bounds__(512, 2) void k_angle_tc(
    const float* __restrict__ angle_ebd, const float* __restrict__ edge_ebd,
    const int* __restrict__ ai, const float* __restrict__ a_sw,
    const float* __restrict__ W_ea1, const float* __restrict__ W_as,
    const float* __restrict__ a_res0, float* __restrict__ out_angle) {
    extern __shared__ char smc[];
    uint32_t sb = smem_u32(smc);
    int tid = threadIdx.x;
    int wid = tid >> 5;
    int lane = tid & 31;
    int wm = wid >> 2;
    int wn = wid & 3;

    int* nav = (int*)(smc + AT_IDX);
    int* ijav = nav + 64;
    float* aswv = (float*)(ijav + 64);

    const int* n2a = ai;
    const int* eij = ai + NANGLE;
    const int* eik = ai + 2 * NANGLE;

    for (int idx = tid; idx < 96 * 160; idx += 512) {
        int j = idx / 160, k = idx % 160;
        int srck = (k < 32) ? k : ((k < 96) ? 160 + (k - 32) : 224 + (k - 96));
        float w = (j < 64) ? W_ea1[(size_t)srck * 64 + j] : W_as[(size_t)srck * 32 + (j - 64)];
        *reinterpret_cast<__nv_bfloat16*>(smc + AT_WH + (j * 168 + k) * 2) = __float2bfloat16(w);
    }

    uint32_t aRow = wm * 16 + (lane & 15);
    uint32_t aColH = (lane >> 4);
    uint32_t aAddrH = sb + AT_AH + (aRow * 168 + aColH * 8) * 2;
    uint32_t aAddrL = sb + AT_AL + (aRow * 168 + aColH * 8) * 2;
    int nrow = wn * 24 + (lane & 7) + ((lane & 16) ? 8 : 0);
    int khalf = (lane & 8) ? 8 : 0;
    uint32_t bAddrH = sb + AT_WH + (nrow * 168 + khalf) * 2;
    int nrow2 = wn * 24 + 16 + (lane & 7);
    int khalf2 = (lane & 8) ? 8 : 0;
    uint32_t b2AddrH = sb + AT_WH + (nrow2 * 168 + khalf2) * 2;

    int mfill = tid & 63;
    int seg = tid >> 6;

    for (int t = blockIdx.x; t < NANGLE / 64; t += gridDim.x) {
        int a0 = t * 64;
        __syncthreads();
        if (tid < 64) {
            nav[tid] = n2a[a0 + tid];
            ijav[tid] = eij[a0 + tid];
            aswv[tid] = a_sw[a0 + tid];
        }
        {
            int a = a0 + mfill;
            int ek = __ldg(&eik[a]);
            int ej = __ldg(&eij[a]);
            const float4* arow = (const float4*)(angle_ebd + (size_t)a * ADIM);
            const float4* krow = (const float4*)(edge_ebd + (size_t)ek * EDIM);
            const float4* jrow = (const float4*)(edge_ebd + (size_t)ej * EDIM);
            uint32_t rowoff = (uint32_t)mfill * 168;
#pragma unroll
            for (int q = 0; q < 5; q++) {
                int kk = seg * 20 + q * 4;
                float4 v = (kk < 32) ? arow[kk >> 2]
                         : (kk < 96) ? krow[(kk - 32) >> 2]
                                     : jrow[(kk - 96) >> 2];
                __nv_bfloat16 h0 = __float2bfloat16(v.x);
                __nv_bfloat16 h1 = __float2bfloat16(v.y);
                __nv_bfloat16 h2 = __float2bfloat16(v.z);
                __nv_bfloat16 h3 = __float2bfloat16(v.w);
                uint32_t hi01, hi23;
                { __nv_bfloat162 tt; tt.x = h0; tt.y = h1; hi01 = *reinterpret_cast<uint32_t*>(&tt); }
                { __nv_bfloat162 tt; tt.x = h2; tt.y = h3; hi23 = *reinterpret_cast<uint32_t*>(&tt); }
                uint32_t lo01 = bfp(v.x - __bfloat162float(h0), v.y - __bfloat162float(h1));
                uint32_t lo23 = bfp(v.z - __bfloat162float(h2), v.w - __bfloat162float(h3));
                uint32_t boff = (rowoff + kk) * 2;
                *reinterpret_cast<uint32_t*>(smc + AT_AH + boff) = hi01;
                *reinterpret_cast<uint32_t*>(smc + AT_AH + boff + 4) = hi23;
                *reinterpret_cast<uint32_t*>(smc + AT_AL + boff) = lo01;
                *reinterpret_cast<uint32_t*>(smc + AT_AL + boff + 4) = lo23;
            }
        }
        __syncthreads();

        float d[3][4];
#pragma unroll
        for (int nt = 0; nt < 3; nt++)
#pragma unroll
            for (int q = 0; q < 4; q++) d[nt][q] = 0.f;

#pragma unroll
        for (int s = 0; s < 10; s++) {
            uint32_t ah[4], al[4];
            ldsm4(ah, aAddrH + s * 32);
            ldsm4(al, aAddrL + s * 32);
            uint32_t bh[4], b2h[2];
            ldsm4(bh, bAddrH + s * 32);
            ldsm2(b2h, b2AddrH + s * 32);
            mma_bf16(d[0], ah, bh);
            mma_bf16(d[0], al, bh);
            mma_bf16(d[1], ah, bh + 2);
            mma_bf16(d[1], al, bh + 2);
            mma_bf16(d[2], ah, b2h);
            mma_bf16(d[2], al, b2h);
        }

        int g = lane >> 2, qt = lane & 3;
        int r0 = wm * 16 + g, r1 = r0 + 8;
        int nd0 = nav[r0], nd1 = nav[r1];
        float sw0 = aswv[r0], sw1 = aswv[r1];
        int ij0 = ijav[r0], ij1 = ijav[r1];
#pragma unroll
        for (int nt = 0; nt < 3; nt++) {
            int j0 = wn * 24 + nt * 8 + qt * 2;
            float2 nb0 = *(const float2*)(g_nbase + (size_t)nd0 * 96 + j0);
            float2 nb1 = *(const float2*)(g_nbase + (size_t)nd1 * 96 + j0);
            float y00 = silu_f(d[nt][0] + nb0.x);
            float y01 = silu_f(d[nt][1] + nb0.y);
            float y10 = silu_f(d[nt][2] + nb1.x);
            float y11 = silu_f(d[nt][3] + nb1.y);
            if (j0 < 64) {
                atomicAdd(&g_reduced[(size_t)ij0 * EDIM + j0], y00 * sw0);
                atomicAdd(&g_reduced[(size_t)ij0 * EDIM + j0 + 1], y01 * sw0);
                atomicAdd(&g_reduced[(size_t)ij1 * EDIM + j0], y10 * sw1);
                atomicAdd(&g_reduced[(size_t)ij1 * EDIM + j0 + 1], y11 * sw1);
            } else {
                int col = j0 - 64;
                float2 arr = *(const float2*)(a_res0 + col);
                size_t o0 = (size_t)(a0 + r0) * ADIM + col;
                size_t o1 = (size_t)(a0 + r1) * ADIM + col;
                float2 ae0 = *(const float2*)(angle_ebd + o0);
                float2 ae1 = *(const float2*)(angle_ebd + o1);
                *(float2*)(out_angle + o0) = make_float2(ae0.x + arr.x * y00, ae0.y + arr.y * y01);
                *(float2*)(out_angle + o1) = make_float2(ae1.x + arr.x * y10, ae1.y + arr.y * y11);
            }
        }
    }
}

// ================= edge angle message GEMM via mma.sync bf16 2-term =================
__global__ __launch_bounds__(256) void k_edge_msg(const float* __restrict__ W2,
                                                  const float* __restrict__ b2,
                                                  const float* __restrict__ e_res1,
                                                  float* __restrict__ out_edge) {
    __shared__ __align__(16) __nv_bfloat16 Wh[64 * 72];
    __shared__ __align__(16) __nv_bfloat16 Ah[64 * 72];
    __shared__ __align__(16) __nv_bfloat16 Al[64 * 72];
    int tid = threadIdx.x;
    int wid = tid >> 5;
    int lane = tid & 31;
    int wm = wid >> 1;
    int wn = wid & 1;
    int e0 = blockIdx.x * 64;

    for (int idx = tid; idx < 64 * 64; idx += 256) {
        int j = idx >> 6, k = idx & 63;
        Wh[j * 72 + k] = __float2bfloat16(W2[k * 64 + j]);
    }
    {
        int m = tid & 63, seg = tid >> 6;
        const float4* src = (const float4*)(g_reduced + (size_t)(e0 + m) * EDIM + seg * 16);
#pragma unroll
        for (int q = 0; q < 4; q++) {
            float4 v = src[q];
            int kk = seg * 16 + q * 4;
            __nv_bfloat16 h0 = __float2bfloat16(v.x);
            __nv_bfloat16 h1 = __float2bfloat16(v.y);
            __nv_bfloat16 h2 = __float2bfloat16(v.z);
            __nv_bfloat16 h3 = __float2bfloat16(v.w);
            Ah[m * 72 + kk + 0] = h0;
            Ah[m * 72 + kk + 1] = h1;
            Ah[m * 72 + kk + 2] = h2;
            Ah[m * 72 + kk + 3] = h3;
            Al[m * 72 + kk + 0] = __float2bfloat16(v.x - __bfloat162float(h0));
            Al[m * 72 + kk + 1] = __float2bfloat16(v.y - __bfloat162float(h1));
            Al[m * 72 + kk + 2] = __float2bfloat16(v.z - __bfloat162float(h2));
            Al[m * 72 + kk + 3] = __float2bfloat16(v.w - __bfloat162float(h3));
        }
    }
    __syncthreads();

    uint32_t aRow = wm * 16 + (lane & 15);
    uint32_t aColH = (lane >> 4);
    uint32_t aAddrH = smem_u32(Ah) + (aRow * 72 + aColH * 8) * 2;
    uint32_t aAddrL = smem_u32(Al) + (aRow * 72 + aColH * 8) * 2;
    int nrow = wn * 32 + (lane & 7) + ((lane & 16) ? 8 : 0);
    int khalf = (lane & 8) ? 8 : 0;
    uint32_t bAddrH = smem_u32(Wh) + (nrow * 72 + khalf) * 2;
    uint32_t b2AddrH = bAddrH + 16 * 144;

    float d[4][4];
#pragma unroll
    for (int nt = 0; nt < 4; nt++)
#pragma unroll
        for (int q = 0; q < 4; q++) d[nt][q] = 0.f;

#pragma unroll
    for (int s = 0; s < 4; s++) {
        uint32_t ah[4], al[4];
        ldsm4(ah, aAddrH + s * 32);
        ldsm4(al, aAddrL + s * 32);
        uint32_t bh[4], ch[4];
        ldsm4(bh, bAddrH + s * 32);
        ldsm4(ch, b2AddrH + s * 32);
        mma_bf16(d[0], ah, bh);
        mma_bf16(d[0], al, bh);
        mma_bf16(d[1], ah, bh + 2);
        mma_bf16(d[1], al, bh + 2);
        mma_bf16(d[2], ah, ch);
        mma_bf16(d[2], al, ch);
        mma_bf16(d[3], ah, ch + 2);
        mma_bf16(d[3], al, ch + 2);
    }

    int g = lane >> 2, qt = lane & 3;
    int r0 = wm * 16 + g, r1 = r0 + 8;
#pragma unroll
    for (int nt = 0; nt < 4; nt++) {
        int j0 = wn * 32 + nt * 8 + qt * 2;
        float2 bb = *(const float2*)(b2 + j0);
        float2 er = *(const float2*)(e_res1 + j0);
        size_t o0 = (size_t)(e0 + r0) * EDIM + j0;
        size_t o1 = (size_t)(e0 + r1) * EDIM + j0;
        float2 v0 = *(float2*)(out_edge + o0);
        float2 v1 = *(float2*)(out_edge + o1);
        v0.x += er.x * silu_f(d[nt][0] + bb.x);
        v0.y += er.y * silu_f(d[nt][1] + bb.y);
        v1.x += er.x * silu_f(d[nt][2] + bb.x);
        v1.y += er.y * silu_f(d[nt][3] + bb.y);
        *(float2*)(out_edge + o0) = v0;
        *(float2*)(out_edge + o1) = v1;
    }
}

// ---------------- launch ----------------
extern "C" void kernel_launch(void* const* d_in, const int* in_sizes, int n_in,
                              void* d_out, int out_size) {
    const float* node_ext   = (const float*)d_in[0];
    const float* edge_ebd   = (const float*)d_in[1];
    const float* h2         = (const float*)d_in[2];
    const float* angle_ebd  = (const float*)d_in[3];
    const float* sw         = (const float*)d_in[6];
    const float* a_sw       = (const float*)d_in[9];
    const int*   edge_index = (const int*)d_in[10];
    const int*   angle_index= (const int*)d_in[11];
    const float* W_node_self = (const float*)d_in[12];
    const float* b_node_self = (const float*)d_in[13];
    const float* W_node_sym  = (const float*)d_in[14];
    const float* b_node_sym  = (const float*)d_in[15];
    const float* W_node_edge = (const float*)d_in[16];
    const float* b_node_edge = (const float*)d_in[17];
    const float* W_edge_self = (const float*)d_in[18];
    const float* b_edge_self = (const float*)d_in[19];
    const float* W_edge_angle1 = (const float*)d_in[20];
    const float* b_edge_angle1 = (const float*)d_in[21];
    const float* W_edge_angle2 = (const float*)d_in[22];
    const float* b_edge_angle2 = (const float*)d_in[23];
    const float* W_angle_self  = (const float*)d_in[24];
    const float* b_angle_self  = (const float*)d_in[25];
    const float* n_res0 = (const float*)d_in[26];
    const float* n_res1 = (const float*)d_in[27];
    const float* n_res2 = (const float*)d_in[28];
    const float* e_res0 = (const float*)d_in[29];
    const float* e_res1 = (const float*)d_in[30];
    const float* a_res0 = (const float*)d_in[31];

    float* out = (float*)d_out;
    float* out_node  = out;
    float* out_edge  = out + (size_t)NLOC * NDIM;
    float* out_angle = out_edge + (size_t)NEDGE * EDIM;

    const int* n2e = edge_index;
    const int* n_ext2e = edge_index + NEDGE;

    cudaFuncSetAttribute((const void*)k_edge_tc,
                         cudaFuncAttributeMaxDynamicSharedMemorySize, ET_SMEM);
    cudaFuncSetAttribute((const void*)k_angle_tc,
                         cudaFuncAttributeMaxDynamicSharedMemorySize, AT_SMEM);

    k_zero<<<4096, 256>>>();
    k_count<<<NEDGE / 256, 256>>>(n2e);
    k_scan<<<1, 1024>>>();
    k_scatter<<<NEDGE / 256, 256>>>(n2e);
    k_sym<<<NLOC, 768>>>(edge_ebd, node_ext, h2, sw, n_ext2e);
    k_symmm<<<NLOC / 64, 256>>>(W_node_sym, b_node_sym, n_res1,
                                W_node_self, b_node_self, n_res0, node_ext, out_node);
    k_base<<<NLOC / 64, 256>>>(node_ext, W_node_edge, W_edge_self, b_node_edge, b_edge_self);
    k_base2<<<NALL / 64, 256>>>(node_ext, W_node_edge, W_edge_self);
    k_nbase<<<NLOC / 64, 256>>>(node_ext, W_edge_angle1, W_angle_self,
                                b_edge_angle1, b_angle_self);
    k_edge_tc<<<296, 512, ET_SMEM>>>(edge_ebd, sw, n_ext2e,
                                     W_node_edge, W_edge_self, e_res0, out_edge);
    k_node_finish<<<NLOC * NDIM / 256, 256>>>(n_res2, out_node);
    k_angle_tc<<<296, 512, AT_SMEM>>>(angle_ebd, edge_ebd, angle_index, a_sw,
                                      W_edge_angle1, W_angle_self, a_res0, out_angle);
    k_edge_msg<<<NEDGE / 64, 256>>>(W_edge_angle2, b_edge_angle2, e_res1, out_edge);
}

// round 15
// speedup vs baseline: 5.1017x; 1.0507x over previous
#include <cuda_runtime.h>
#include <cuda_bf16.h>
#include <cstdint>
#include <cstddef>

#define NLOC   4096
#define NALL   6144
#define NDIM   128
#define EDIM   64
#define ADIM   32
#define NEDGE  262144
#define NANGLE 409600
#define INV_DYN_E 0.15625f            // 1/6.4
#define SYM_SCALE 0.0520833333333f    // (1/6.4)/3

// ---------------- device scratch ----------------
__device__ float g_sym[(size_t)NLOC * 768];
__device__ float g_base[(size_t)NLOC * 192];
__device__ float g_base2[(size_t)NALL * 192];
__device__ float g_nbase[(size_t)NLOC * 96];
__device__ float g_reduced[(size_t)NEDGE * EDIM];
__device__ float g_msg[(size_t)NLOC * NDIM];
__device__ int   g_ecnt[NLOC];
__device__ int   g_eoff[NLOC + 1];
__device__ int   g_ecur[NLOC];
__device__ int   g_eids[NEDGE];
__device__ int   g_enode[NEDGE];

// ---------------- helpers ----------------
__device__ __forceinline__ float silu_f(float x) { return x / (1.0f + __expf(-x)); }

__device__ __forceinline__ uint32_t smem_u32(const void* p) {
    uint32_t a;
    asm("{ .reg .u64 t; cvta.to.shared.u64 t, %1; cvt.u32.u64 %0, t; }" : "=r"(a) : "l"(p));
    return a;
}

__device__ __forceinline__ void ldsm4(uint32_t* r, uint32_t addr) {
    asm volatile("ldmatrix.sync.aligned.m8n8.x4.shared.b16 {%0,%1,%2,%3}, [%4];"
                 : "=r"(r[0]), "=r"(r[1]), "=r"(r[2]), "=r"(r[3]) : "r"(addr));
}
__device__ __forceinline__ void ldsm2(uint32_t* r, uint32_t addr) {
    asm volatile("ldmatrix.sync.aligned.m8n8.x2.shared.b16 {%0,%1}, [%2];"
                 : "=r"(r[0]), "=r"(r[1]) : "r"(addr));
}

__device__ __forceinline__ void mma_bf16(float* d, const uint32_t* a, const uint32_t* b) {
    asm volatile(
        "mma.sync.aligned.m16n8k16.row.col.f32.bf16.bf16.f32 "
        "{%0,%1,%2,%3}, {%4,%5,%6,%7}, {%8,%9}, {%0,%1,%2,%3};"
        : "+f"(d[0]), "+f"(d[1]), "+f"(d[2]), "+f"(d[3])
        : "r"(a[0]), "r"(a[1]), "r"(a[2]), "r"(a[3]), "r"(b[0]), "r"(b[1]));
}

__device__ __forceinline__ uint32_t bfp(float a, float b) {
    __nv_bfloat162 t = __floats2bfloat162_rn(a, b);
    return *reinterpret_cast<uint32_t*>(&t);
}

// ---------------- zero scratch ----------------
__global__ void k_zero() {
    size_t i0 = (size_t)blockIdx.x * blockDim.x + threadIdx.x;
    size_t stride = (size_t)gridDim.x * blockDim.x;
    float4* r = reinterpret_cast<float4*>(g_reduced);
    size_t n4 = (size_t)NEDGE * EDIM / 4;
    for (size_t i = i0; i < n4; i += stride) r[i] = make_float4(0.f, 0.f, 0.f, 0.f);
    float4* m = reinterpret_cast<float4*>(g_msg);
    size_t m4 = (size_t)NLOC * NDIM / 4;
    for (size_t i = i0; i < m4; i += stride) m[i] = make_float4(0.f, 0.f, 0.f, 0.f);
    if (i0 < NLOC) g_ecnt[i0] = 0;
}

// ---------------- CSR build ----------------
__global__ void k_count(const int* __restrict__ n2e) {
    int e = blockIdx.x * blockDim.x + threadIdx.x;
    if (e < NEDGE) atomicAdd(&g_ecnt[n2e[e]], 1);
}

__global__ void k_scan() {
    __shared__ int sh[1024];
    int t = threadIdx.x;
    int c[4];
#pragma unroll
    for (int i = 0; i < 4; i++) c[i] = g_ecnt[t * 4 + i];
    int tot = c[0] + c[1] + c[2] + c[3];
    sh[t] = tot;
    __syncthreads();
    for (int st = 1; st < 1024; st <<= 1) {
        int add = (t >= st) ? sh[t - st] : 0;
        __syncthreads();
        sh[t] += add;
        __syncthreads();
    }
    int run = sh[t] - tot;
#pragma unroll
    for (int i = 0; i < 4; i++) {
        g_eoff[t * 4 + i] = run;
        g_ecur[t * 4 + i] = run;
        run += c[i];
    }
    if (t == 1023) g_eoff[NLOC] = run;
}

__global__ void k_scatter(const int* __restrict__ n2e) {
    int e = blockIdx.x * blockDim.x + threadIdx.x;
    if (e < NEDGE) {
        int n = n2e[e];
        int pos = atomicAdd(&g_ecur[n], 1);
        g_eids[pos] = e;
        g_enode[pos] = n;
    }
}

// ---------------- sym op: 4-way edge parallelism ----------------
__global__ __launch_bounds__(768) void k_sym(
    const float* __restrict__ edge_ebd, const float* __restrict__ node_ext,
    const float* __restrict__ h2, const float* __restrict__ sw,
    const int* __restrict__ n_ext2e) {
    __shared__ float P[4][3][192];
    __shared__ float S0[192], S1[192], S2[192];
    __shared__ float symv[768];
    int n = blockIdx.x;
    int t = threadIdx.x;
    int g = t / 192;
    int f = t - g * 192;
    int beg = g_eoff[n], end = g_eoff[n + 1];
    float a0 = 0.f, a1 = 0.f, a2 = 0.f;
    for (int i = beg + g; i < end; i += 4) {
        int e = g_eids[i];
        float swv = sw[e];
        float h0 = h2[e * 3 + 0] * swv;
        float h1 = h2[e * 3 + 1] * swv;
        float hh = h2[e * 3 + 2] * swv;
        float val = (f < 64) ? edge_ebd[(size_t)e * EDIM + f]
                             : node_ext[(size_t)n_ext2e[e] * NDIM + (f - 64)];
        a0 += h0 * val;
        a1 += h1 * val;
        a2 += hh * val;
    }
    P[g][0][f] = a0; P[g][1][f] = a1; P[g][2][f] = a2;
    __syncthreads();
    if (t < 192) {
        S0[t] = P[0][0][t] + P[1][0][t] + P[2][0][t] + P[3][0][t];
    } else if (t < 384) {
        int tt = t - 192;
        S1[tt] = P[0][1][tt] + P[1][1][tt] + P[2][1][tt] + P[3][1][tt];
    } else if (t < 576) {
        int tt = t - 384;
        S2[tt] = P[0][2][tt] + P[1][2][tt] + P[2][2][tt] + P[3][2][tt];
    }
    __syncthreads();
    if (t < 64) {
#pragma unroll
        for (int a = 0; a < 4; a++)
            symv[a * 64 + t] = SYM_SCALE * (S0[a] * S0[t] + S1[a] * S1[t] + S2[a] * S2[t]);
    } else if (t < 192) {
        int dn = t - 64;
#pragma unroll
        for (int a = 0; a < 4; a++)
            symv[256 + a * 128 + dn] =
                SYM_SCALE * (S0[64 + a] * S0[t] + S1[64 + a] * S1[t] + S2[64 + a] * S2[t]);
    }
    __syncthreads();
    g_sym[(size_t)n * 768 + t] = symv[t];
}

// ---------------- node_sym GEMM fused with node_self (M=32 tiles) ----------------
__global__ __launch_bounds__(256) void k_symmm(
    const float* __restrict__ W_sym, const float* __restrict__ b_sym,
    const float* __restrict__ n_res1,
    const float* __restrict__ W_self, const float* __restrict__ b_self,
    const float* __restrict__ n_res0,
    const float* __restrict__ node_ext, float* __restrict__ out_node) {
    __shared__ float Wt[32 * 128];
    __shared__ float At[32 * 36];
    int tid = threadIdx.x;
    int jt = tid & 31, mt = tid >> 5;   // rows mt*4..+4
    int n0 = blockIdx.x * 32;
    float acc0[4][4], acc1[4][4];
#pragma unroll
    for (int i = 0; i < 4; i++)
#pragma unroll
        for (int q = 0; q < 4; q++) { acc0[i][q] = 0.f; acc1[i][q] = 0.f; }

    for (int kt = 0; kt < 768; kt += 32) {
        for (int idx = tid; idx < 32 * 128; idx += 256)
            Wt[idx] = W_sym[(size_t)(kt + idx / 128) * 128 + (idx % 128)];
        for (int idx = tid; idx < 32 * 32; idx += 256) {
            int m = idx / 32, k = idx % 32;
            At[k * 36 + m] = g_sym[(size_t)(n0 + m) * 768 + kt + k];
        }
        __syncthreads();
#pragma unroll 4
        for (int k = 0; k < 32; k++) {
            float4 A0 = *reinterpret_cast<const float4*>(&At[k * 36 + mt * 4]);
            float am[4] = {A0.x, A0.y, A0.z, A0.w};
            float4 wv = *reinterpret_cast<const float4*>(&Wt[k * 128 + jt * 4]);
            float wq[4] = {wv.x, wv.y, wv.z, wv.w};
#pragma unroll
            for (int i = 0; i < 4; i++)
#pragma unroll
                for (int q = 0; q < 4; q++) acc0[i][q] += am[i] * wq[q];
        }
        __syncthreads();
    }
    for (int kt = 0; kt < 128; kt += 32) {
        for (int idx = tid; idx < 32 * 128; idx += 256)
            Wt[idx] = W_self[(size_t)(kt + idx / 128) * 128 + (idx % 128)];
        for (int idx = tid; idx < 32 * 32; idx += 256) {
            int m = idx / 32, k = idx % 32;
            At[k * 36 + m] = node_ext[(size_t)(n0 + m) * NDIM + kt + k];
        }
        __syncthreads();
#pragma unroll 4
        for (int k = 0; k < 32; k++) {
            float4 A0 = *reinterpret_cast<const float4*>(&At[k * 36 + mt * 4]);
            float am[4] = {A0.x, A0.y, A0.z, A0.w};
            float4 wv = *reinterpret_cast<const float4*>(&Wt[k * 128 + jt * 4]);
            float wq[4] = {wv.x, wv.y, wv.z, wv.w};
#pragma unroll
            for (int i = 0; i < 4; i++)
#pragma unroll
                for (int q = 0; q < 4; q++) acc1[i][q] += am[i] * wq[q];
        }
        __syncthreads();
    }
#pragma unroll
    for (int i = 0; i < 4; i++) {
        int n = n0 + mt * 4 + i;
#pragma unroll
        for (int q = 0; q < 4; q++) {
            int j = jt * 4 + q;
            float y1 = silu_f(acc0[i][q] + b_sym[j]);
            float y0 = silu_f(acc1[i][q] + b_self[j]);
            out_node[(size_t)n * 128 + j] =
                node_ext[(size_t)n * NDIM + j] + n_res0[j] * y0 + n_res1[j] * y1;
        }
    }
}

// ---------------- base precompute (dest part, 192 cols, W rows 0..127) ----------------
__global__ __launch_bounds__(256) void k_base(const float* __restrict__ node_ext,
                                              const float* __restrict__ W_ne,
                                              const float* __restrict__ W_es,
                                              const float* __restrict__ b_ne,
                                              const float* __restrict__ b_es) {
    __shared__ float Wt[32 * 192];
    __shared__ float At[32 * 72];
    int tid = threadIdx.x;
    int jt = tid & 31, mt = tid >> 5;
    int n0 = blockIdx.x * 64;
    float acc[8][6];
#pragma unroll
    for (int i = 0; i < 8; i++)
#pragma unroll
        for (int c = 0; c < 6; c++) acc[i][c] = 0.f;
    for (int kt = 0; kt < 128; kt += 32) {
        for (int idx = tid; idx < 32 * 192; idx += 256) {
            int k = idx / 192, j = idx % 192;
            int row = kt + k;
            Wt[idx] = (j < 128) ? W_ne[(size_t)row * 128 + j] : W_es[(size_t)row * 64 + (j - 128)];
        }
        for (int idx = tid; idx < 32 * 64; idx += 256) {
            int m = idx / 32, k = idx % 32;
            At[k * 72 + m] = node_ext[(size_t)(n0 + m) * NDIM + kt + k];
        }
        __syncthreads();
#pragma unroll 2
        for (int k = 0; k < 32; k++) {
            float4 A0 = *reinterpret_cast<const float4*>(&At[k * 72 + mt * 8]);
            float4 A1 = *reinterpret_cast<const float4*>(&At[k * 72 + mt * 8 + 4]);
            float am[8] = {A0.x, A0.y, A0.z, A0.w, A1.x, A1.y, A1.z, A1.w};
#pragma unroll
            for (int c = 0; c < 6; c++) {
                float w = Wt[k * 192 + jt + 32 * c];
#pragma unroll
                for (int i = 0; i < 8; i++) acc[i][c] += am[i] * w;
            }
        }
        __syncthreads();
    }
#pragma unroll
    for (int i = 0; i < 8; i++) {
        int n = n0 + mt * 8 + i;
#pragma unroll
        for (int c = 0; c < 6; c++) {
            int j = jt + 32 * c;
            float bb = (j < 128) ? b_ne[j] : b_es[j - 128];
            g_base[(size_t)n * 192 + j] = acc[i][c] + bb;
        }
    }
}

// ---------------- base2 precompute (nei part, all NALL nodes, W rows 128..255) ----------------
__global__ __launch_bounds__(256) void k_base2(const float* __restrict__ node_ext,
                                               const float* __restrict__ W_ne,
                                               const float* __restrict__ W_es) {
    __shared__ float Wt[32 * 192];
    __shared__ float At[32 * 72];
    int tid = threadIdx.x;
    int jt = tid & 31, mt = tid >> 5;
    int n0 = blockIdx.x * 64;
    float acc[8][6];
#pragma unroll
    for (int i = 0; i < 8; i++)
#pragma unroll
        for (int c = 0; c < 6; c++) acc[i][c] = 0.f;
    for (int kt = 0; kt < 128; kt += 32) {
        for (int idx = tid; idx < 32 * 192; idx += 256) {
            int k = idx / 192, j = idx % 192;
            int row = 128 + kt + k;
            Wt[idx] = (j < 128) ? W_ne[(size_t)row * 128 + j] : W_es[(size_t)row * 64 + (j - 128)];
        }
        for (int idx = tid; idx < 32 * 64; idx += 256) {
            int m = idx / 32, k = idx % 32;
            At[k * 72 + m] = node_ext[(size_t)(n0 + m) * NDIM + kt + k];
        }
        __syncthreads();
#pragma unroll 2
        for (int k = 0; k < 32; k++) {
            float4 A0 = *reinterpret_cast<const float4*>(&At[k * 72 + mt * 8]);
            float4 A1 = *reinterpret_cast<const float4*>(&At[k * 72 + mt * 8 + 4]);
            float am[8] = {A0.x, A0.y, A0.z, A0.w, A1.x, A1.y, A1.z, A1.w};
#pragma unroll
            for (int c = 0; c < 6; c++) {
                float w = Wt[k * 192 + jt + 32 * c];
#pragma unroll
                for (int i = 0; i < 8; i++) acc[i][c] += am[i] * w;
            }
        }
        __syncthreads();
    }
#pragma unroll
    for (int i = 0; i < 8; i++) {
        int n = n0 + mt * 8 + i;
#pragma unroll
        for (int c = 0; c < 6; c++) {
            int j = jt + 32 * c;
            g_base2[(size_t)n * 192 + j] = acc[i][c];
        }
    }
}

// ---------------- nbase precompute (angle kernel, 96 cols) ----------------
__global__ __launch_bounds__(256) void k_nbase(const float* __restrict__ node_ext,
                                               const float* __restrict__ W_ea1,
                                               const float* __restrict__ W_as,
                                               const float* __restrict__ b_ea1,
                                               const float* __restrict__ b_as) {
    __shared__ float Wt[32 * 96];
    __shared__ float At[32 * 72];
    int tid = threadIdx.x;
    int jt = tid & 31, mt = tid >> 5;
    int n0 = blockIdx.x * 64;
    float acc[8][3];
#pragma unroll
    for (int i = 0; i < 8; i++)
#pragma unroll
        for (int c = 0; c < 3; c++) acc[i][c] = 0.f;
    for (int kt = 0; kt < 128; kt += 32) {
        for (int idx = tid; idx < 32 * 96; idx += 256) {
            int k = idx / 96, j = idx % 96;
            int row = 32 + kt + k;
            Wt[idx] = (j < 64) ? W_ea1[(size_t)row * 64 + j] : W_as[(size_t)row * 32 + (j - 64)];
        }
        for (int idx = tid; idx < 32 * 64; idx += 256) {
            int m = idx / 32, k = idx % 32;
            At[k * 72 + m] = node_ext[(size_t)(n0 + m) * NDIM + kt + k];
        }
        __syncthreads();
#pragma unroll 2
        for (int k = 0; k < 32; k++) {
            float4 A0 = *reinterpret_cast<const float4*>(&At[k * 72 + mt * 8]);
            float4 A1 = *reinterpret_cast<const float4*>(&At[k * 72 + mt * 8 + 4]);
            float am[8] = {A0.x, A0.y, A0.z, A0.w, A1.x, A1.y, A1.z, A1.w};
#pragma unroll
            for (int c = 0; c < 3; c++) {
                float w = Wt[k * 96 + jt + 32 * c];
#pragma unroll
                for (int i = 0; i < 8; i++) acc[i][c] += am[i] * w;
            }
        }
        __syncthreads();
    }
#pragma unroll
    for (int i = 0; i < 8; i++) {
        int n = n0 + mt * 8 + i;
#pragma unroll
        for (int c = 0; c < 3; c++) {
            int j = jt + 32 * c;
            float bb = (j < 64) ? b_ea1[j] : b_as[j - 64];
            g_nbase[(size_t)n * 96 + j] = acc[i][c] + bb;
        }
    }
}

// ================= edge GEMM via mma.sync bf16 1-term =================
// M=64 edges, N=192, K=64. smem stride 72.
#define ET_WH 0
#define ET_AH 27648
#define ET_IDX 36864
#define ET_SMEM 37888

__global__ __launch_bounds__(512, 2) void k_edge_tc(
    const float* __restrict__ edge_ebd,
    const float* __restrict__ sw, const int* __restrict__ n_ext2e,
    const float* __restrict__ W_ne, const float* __restrict__ W_es,
    const float* __restrict__ e_res0, float* __restrict__ out_edge) {
    extern __shared__ char smc[];
    uint32_t sb = smem_u32(smc);
    int tid = threadIdx.x;
    int wid = tid >> 5;
    int lane = tid & 31;
    int wm = wid >> 2;
    int wn = wid & 3;

    int* eidv = (int*)(smc + ET_IDX);
    int* nodev = eidv + 64;
    int* neiv = nodev + 64;
    float* sws = (float*)(neiv + 64);

    for (int idx = tid; idx < 192 * 64; idx += 512) {
        int j = idx / 64, k = idx % 64;
        int row = 256 + k;
        float w = (j < 128) ? W_ne[(size_t)row * 128 + j] : W_es[(size_t)row * 64 + (j - 128)];
        *reinterpret_cast<__nv_bfloat16*>(smc + ET_WH + (j * 72 + k) * 2) = __float2bfloat16(w);
    }

    uint32_t aRow = wm * 16 + (lane & 15);
    uint32_t aColH = (lane >> 4);
    uint32_t aAddrH = sb + ET_AH + (aRow * 72 + aColH * 8) * 2;
    int nrow = wn * 48 + (lane & 7) + ((lane & 16) ? 8 : 0);
    int khalf = (lane & 8) ? 8 : 0;
    uint32_t bAddrH = sb + ET_WH + (nrow * 72 + khalf) * 2;

    int mfill = tid & 63;
    int seg = tid >> 6;

    for (int ch = blockIdx.x; ch < NEDGE / 64; ch += gridDim.x) {
        int c0 = ch * 64;
        __syncthreads();
        if (tid < 64) {
            int e = g_eids[c0 + tid];
            eidv[tid] = e;
            nodev[tid] = g_enode[c0 + tid];
            neiv[tid] = n_ext2e[e];
            sws[tid] = sw[e];
        }
        {
            int e = __ldg(&g_eids[c0 + mfill]);
            const float4* erowp = (const float4*)(edge_ebd + (size_t)e * EDIM);
            uint32_t rowoff = (uint32_t)mfill * 72;
#pragma unroll
            for (int q = 0; q < 2; q++) {
                int kk = seg * 8 + q * 4;
                float4 v = erowp[kk >> 2];
                uint32_t hi01 = bfp(v.x, v.y);
                uint32_t hi23 = bfp(v.z, v.w);
                uint32_t boff = (rowoff + kk) * 2;
                *reinterpret_cast<uint32_t*>(smc + ET_AH + boff) = hi01;
                *reinterpret_cast<uint32_t*>(smc + ET_AH + boff + 4) = hi23;
            }
        }
        __syncthreads();

        float d[6][4];
#pragma unroll
        for (int nt = 0; nt < 6; nt++)
#pragma unroll
            for (int q = 0; q < 4; q++) d[nt][q] = 0.f;

#pragma unroll
        for (int s = 0; s < 4; s++) {
            uint32_t ah[4];
            ldsm4(ah, aAddrH + s * 32);
#pragma unroll
            for (int pr = 0; pr < 3; pr++) {
                uint32_t bh[4];
                ldsm4(bh, bAddrH + pr * 16 * 144 + s * 32);
                mma_bf16(d[pr * 2], ah, bh);
                mma_bf16(d[pr * 2 + 1], ah, bh + 2);
            }
        }

        int g = lane >> 2, qt = lane & 3;
        int r0 = wm * 16 + g, r1 = r0 + 8;
        int nd0 = nodev[r0], nd1 = nodev[r1];
        int ne0 = neiv[r0], ne1 = neiv[r1];
        float sw0 = sws[r0], sw1 = sws[r1];
        int ee0 = eidv[r0], ee1 = eidv[r1];
        bool samend = (nd0 == nd1);
#pragma unroll
        for (int nt = 0; nt < 6; nt++) {
            int j0 = wn * 48 + nt * 8 + qt * 2;
            float2 b0v = *(const float2*)(g_base + (size_t)nd0 * 192 + j0);
            float2 b1v = *(const float2*)(g_base + (size_t)nd1 * 192 + j0);
            float2 c0v = *(const float2*)(g_base2 + (size_t)ne0 * 192 + j0);
            float2 c1v = *(const float2*)(g_base2 + (size_t)ne1 * 192 + j0);
            float y00 = silu_f(d[nt][0] + b0v.x + c0v.x);
            float y01 = silu_f(d[nt][1] + b0v.y + c0v.y);
            float y10 = silu_f(d[nt][2] + b1v.x + c1v.x);
            float y11 = silu_f(d[nt][3] + b1v.y + c1v.y);
            if (j0 < 128) {
                float v00 = y00 * sw0, v01 = y01 * sw0;
                float v10 = y10 * sw1, v11 = y11 * sw1;
                if (samend) {
                    atomicAdd(&g_msg[(size_t)nd0 * NDIM + j0], v00 + v10);
                    atomicAdd(&g_msg[(size_t)nd0 * NDIM + j0 + 1], v01 + v11);
                } else {
                    atomicAdd(&g_msg[(size_t)nd0 * NDIM + j0], v00);
                    atomicAdd(&g_msg[(size_t)nd0 * NDIM + j0 + 1], v01);
                    atomicAdd(&g_msg[(size_t)nd1 * NDIM + j0], v10);
                    atomicAdd(&g_msg[(size_t)nd1 * NDIM + j0 + 1], v11);
                }
            } else {
                int col = j0 - 128;
                float2 er = *(const float2*)(e_res0 + col);
                size_t o0 = (size_t)ee0 * EDIM + col;
                size_t o1 = (size_t)ee1 * EDIM + col;
                float2 eb0 = *(const float2*)(edge_ebd + o0);
                float2 eb1 = *(const float2*)(edge_ebd + o1);
                *(float2*)(out_edge + o0) = make_float2(eb0.x + er.x * y00, eb0.y + er.y * y01);
                *(float2*)(out_edge + o1) = make_float2(eb1.x + er.x * y10, eb1.y + er.y * y11);
            }
        }
    }
}

__global__ void k_node_finish(const float* __restrict__ n_res2, float* __restrict__ out_node) {
    int i = blockIdx.x * blockDim.x + threadIdx.x;
    if (i < NLOC * NDIM) {
        int j = i & (NDIM - 1);
        out_node[i] += n_res2[j] * g_msg[i] * INV_DYN_E;
    }
}

// ================= angle GEMM via mma.sync bf16 1-term =================
#define AT_WH 0
#define AT_AH 32256
#define AT_IDX 53760
#define AT_SMEM 54528

__global__ __launch_bounds__(512, 2) void k_angle_tc(
    const float* __restrict__ angle_ebd, const float* __restrict__ edge_ebd,
    const int* __restrict__ ai, const float* __restrict__ a_sw,
    const float* __restrict__ W_ea1, const float* __restrict__ W_as,
    const float* __restrict__ a_res0, float* __restrict__ out_angle) {
    extern __shared__ char smc[];
    uint32_t sb = smem_u32(smc);
    int tid = threadIdx.x;
    int wid = tid >> 5;
    int lane = tid & 31;
    int wm = wid >> 2;
    int wn = wid & 3;

    int* nav = (int*)(smc + AT_IDX);
    int* ijav = nav + 64;
    float* aswv = (float*)(ijav + 64);

    const int* n2a = ai;
    const int* eij = ai + NANGLE;
    const int* eik = ai + 2 * NANGLE;

    for (int idx = tid; idx < 96 * 160; idx += 512) {
        int j = idx / 160, k = idx % 160;
        int srck = (k < 32) ? k : ((k < 96) ? 160 + (k - 32) : 224 + (k - 96));
        float w = (j < 64) ? W_ea1[(size_t)srck * 64 + j] : W_as[(size_t)srck * 32 + (j - 64)];
        *reinterpret_cast<__nv_bfloat16*>(smc + AT_WH + (j * 168 + k) * 2) = __float2bfloat16(w);
    }

    uint32_t aRow = wm * 16 + (lane & 15);
    uint32_t aColH = (lane >> 4);
    uint32_t aAddrH = sb + AT_AH + (aRow * 168 + aColH * 8) * 2;
    int nrow = wn * 24 + (lane & 7) + ((lane & 16) ? 8 : 0);
    int khalf = (lane & 8) ? 8 : 0;
    uint32_t bAddrH = sb + AT_WH + (nrow * 168 + khalf) * 2;
    int nrow2 = wn * 24 + 16 + (lane & 7);
    int khalf2 = (lane & 8) ? 8 : 0;
    uint32_t b2AddrH = sb + AT_WH + (nrow2 * 168 + khalf2) * 2;

    int mfill = tid & 63;
    int seg = tid >> 6;

    for (int t = blockIdx.x; t < NANGLE / 64; t += gridDim.x) {
        int a0 = t * 64;
        __syncthreads();
        if (tid < 64) {
            nav[tid] = n2a[a0 + tid];
            ijav[tid] = eij[a0 + tid];
            aswv[tid] = a_sw[a0 + tid];
        }
        {
            int a = a0 + mfill;
            int ek = __ldg(&eik[a]);
            int ej = __ldg(&eij[a]);
            const float4* arow = (const float4*)(angle_ebd + (size_t)a * ADIM);
            const float4* krow = (const float4*)(edge_ebd + (size_t)ek * EDIM);
            const float4* jrow = (const float4*)(edge_ebd + (size_t)ej * EDIM);
            uint32_t rowoff = (uint32_t)mfill * 168;
#pragma unroll
            for (int q = 0; q < 5; q++) {
                int kk = seg * 20 + q * 4;
                float4 v = (kk < 32) ? arow[kk >> 2]
                         : (kk < 96) ? krow[(kk - 32) >> 2]
                                     : jrow[(kk - 96) >> 2];
                uint32_t hi01 = bfp(v.x, v.y);
                uint32_t hi23 = bfp(v.z, v.w);
                uint32_t boff = (rowoff + kk) * 2;
                *reinterpret_cast<uint32_t*>(smc + AT_AH + boff) = hi01;
                *reinterpret_cast<uint32_t*>(smc + AT_AH + boff + 4) = hi23;
            }
        }
        __syncthreads();

        float d[3][4];
#pragma unroll
        for (int nt = 0; nt < 3; nt++)
#pragma unroll
            for (int q = 0; q < 4; q++) d[nt][q] = 0.f;

#pragma unroll
        for (int s = 0; s < 10; s++) {
            uint32_t ah[4];
            ldsm4(ah, aAddrH + s * 32);
            uint32_t bh[4], b2h[2];
            ldsm4(bh, bAddrH + s * 32);
            ldsm2(b2h, b2AddrH + s * 32);
            mma_bf16(d[0], ah, bh);
            mma_bf16(d[1], ah, bh + 2);
            mma_bf16(d[2], ah, b2h);
        }

        int g = lane >> 2, qt = lane & 3;
        int r0 = wm * 16 + g, r1 = r0 + 8;
        int nd0 = nav[r0], nd1 = nav[r1];
        float sw0 = aswv[r0], sw1 = aswv[r1];
        int ij0 = ijav[r0], ij1 = ijav[r1];
#pragma unroll
        for (int nt = 0; nt < 3; nt++) {
            int j0 = wn * 24 + nt * 8 + qt * 2;
            float2 nb0 = *(const float2*)(g_nbase + (size_t)nd0 * 96 + j0);
            float2 nb1 = *(const float2*)(g_nbase + (size_t)nd1 * 96 + j0);
            float y00 = silu_f(d[nt][0] + nb0.x);
            float y01 = silu_f(d[nt][1] + nb0.y);
            float y10 = silu_f(d[nt][2] + nb1.x);
            float y11 = silu_f(d[nt][3] + nb1.y);
            if (j0 < 64) {
                atomicAdd(&g_reduced[(size_t)ij0 * EDIM + j0], y00 * sw0);
                atomicAdd(&g_reduced[(size_t)ij0 * EDIM + j0 + 1], y01 * sw0);
                atomicAdd(&g_reduced[(size_t)ij1 * EDIM + j0], y10 * sw1);
                atomicAdd(&g_reduced[(size_t)ij1 * EDIM + j0 + 1], y11 * sw1);
            } else {
                int col = j0 - 64;
                float2 arr = *(const float2*)(a_res0 + col);
                size_t o0 = (size_t)(a0 + r0) * ADIM + col;
                size_t o1 = (size_t)(a0 + r1) * ADIM + col;
                float2 ae0 = *(const float2*)(angle_ebd + o0);
                float2 ae1 = *(const float2*)(angle_ebd + o1);
                *(float2*)(out_angle + o0) = make_float2(ae0.x + arr.x * y00, ae0.y + arr.y * y01);
                *(float2*)(out_angle + o1) = make_float2(ae1.x + arr.x * y10, ae1.y + arr.y * y11);
            }
        }
    }
}

// ================= edge angle message GEMM via mma.sync bf16 1-term =================
__global__ __launch_bounds__(256) void k_edge_msg(const float* __restrict__ W2,
                                                  const float* __restrict__ b2,
                                                  const float* __restrict__ e_res1,
                                                  float* __restrict__ out_edge) {
    __shared__ __align__(16) __nv_bfloat16 Wh[64 * 72];
    __shared__ __align__(16) __nv_bfloat16 Ah[64 * 72];
    int tid = threadIdx.x;
    int wid = tid >> 5;
    int lane = tid & 31;
    int wm = wid >> 1;
    int wn = wid & 1;
    int e0 = blockIdx.x * 64;

    for (int idx = tid; idx < 64 * 64; idx += 256) {
        int j = idx >> 6, k = idx & 63;
        Wh[j * 72 + k] = __float2bfloat16(W2[k * 64 + j]);
    }
    {
        int m = tid & 63, seg = tid >> 6;
        const float4* src = (const float4*)(g_reduced + (size_t)(e0 + m) * EDIM + seg * 16);
#pragma unroll
        for (int q = 0; q < 4; q++) {
            float4 v = src[q];
            int kk = seg * 16 + q * 4;
            Ah[m * 72 + kk + 0] = __float2bfloat16(v.x);
            Ah[m * 72 + kk + 1] = __float2bfloat16(v.y);
            Ah[m * 72 + kk + 2] = __float2bfloat16(v.z);
            Ah[m * 72 + kk + 3] = __float2bfloat16(v.w);
        }
    }
    __syncthreads();

    uint32_t aRow = wm * 16 + (lane & 15);
    uint32_t aColH = (lane >> 4);
    uint32_t aAddrH = smem_u32(Ah) + (aRow * 72 + aColH * 8) * 2;
    int nrow = wn * 32 + (lane & 7) + ((lane & 16) ? 8 : 0);
    int khalf = (lane & 8) ? 8 : 0;
    uint32_t bAddrH = smem_u32(Wh) + (nrow * 72 + khalf) * 2;
    uint32_t b2AddrH = bAddrH + 16 * 144;

    float d[4][4];
#pragma unroll
    for (int nt = 0; nt < 4; nt++)
#pragma unroll
        for (int q = 0; q < 4; q++) d[nt][q] = 0.f;

#pragma unroll
    for (int s = 0; s < 4; s++) {
        uint32_t ah[4];
        ldsm4(ah, aAddrH + s * 32);
        uint32_t bh[4], ch[4];
        ldsm4(bh, bAddrH + s * 32);
        ldsm4(ch, b2AddrH + s * 32);
        mma_bf16(d[0], ah, bh);
        mma_bf16(d[1], ah, bh + 2);
        mma_bf16(d[2], ah, ch);
        mma_bf16(d[3], ah, ch + 2);
    }

    int g = lane >> 2, qt = lane & 3;
    int r0 = wm * 16 + g, r1 = r0 + 8;
#pragma unroll
    for (int nt = 0; nt < 4; nt++) {
        int j0 = wn * 32 + nt * 8 + qt * 2;
        float2 bb = *(const float2*)(b2 + j0);
        float2 er = *(const float2*)(e_res1 + j0);
        size_t o0 = (size_t)(e0 + r0) * EDIM + j0;
        size_t o1 = (size_t)(e0 + r1) * EDIM + j0;
        float2 v0 = *(float2*)(out_edge + o0);
        float2 v1 = *(float2*)(out_edge + o1);
        v0.x += er.x * silu_f(d[nt][0] + bb.x);
        v0.y += er.y * silu_f(d[nt][1] + bb.y);
        v1.x += er.x * silu_f(d[nt][2] + bb.x);
        v1.y += er.y * silu_f(d[nt][3] + bb.y);
        *(float2*)(out_edge + o0) = v0;
        *(float2*)(out_edge + o1) = v1;
    }
}

// ---------------- launch ----------------
extern "C" void kernel_launch(void* const* d_in, const int* in_sizes, int n_in,
                              void* d_out, int out_size) {
    const float* node_ext   = (const float*)d_in[0];
    const float* edge_ebd   = (const float*)d_in[1];
    const float* h2         = (const float*)d_in[2];
    const float* angle_ebd  = (const float*)d_in[3];
    const float* sw         = (const float*)d_in[6];
    const float* a_sw       = (const float*)d_in[9];
    const int*   edge_index = (const int*)d_in[10];
    const int*   angle_index= (const int*)d_in[11];
    const float* W_node_self = (const float*)d_in[12];
    const float* b_node_self = (const float*)d_in[13];
    const float* W_node_sym  = (const float*)d_in[14];
    const float* b_node_sym  = (const float*)d_in[15];
    const float* W_node_edge = (const float*)d_in[16];
    const float* b_node_edge = (const float*)d_in[17];
    const float* W_edge_self = (const float*)d_in[18];
    const float* b_edge_self = (const float*)d_in[19];
    const float* W_edge_angle1 = (const float*)d_in[20];
    const float* b_edge_angle1 = (const float*)d_in[21];
    const float* W_edge_angle2 = (const float*)d_in[22];
    const float* b_edge_angle2 = (const float*)d_in[23];
    const float* W_angle_self  = (const float*)d_in[24];
    const float* b_angle_self  = (const float*)d_in[25];
    const float* n_res0 = (const float*)d_in[26];
    const float* n_res1 = (const float*)d_in[27];
    const float* n_res2 = (const float*)d_in[28];
    const float* e_res0 = (const float*)d_in[29];
    const float* e_res1 = (const float*)d_in[30];
    const float* a_res0 = (const float*)d_in[31];

    float* out = (float*)d_out;
    float* out_node  = out;
    float* out_edge  = out + (size_t)NLOC * NDIM;
    float* out_angle = out_edge + (size_t)NEDGE * EDIM;

    const int* n2e = edge_index;
    const int* n_ext2e = edge_index + NEDGE;

    cudaFuncSetAttribute((const void*)k_edge_tc,
                         cudaFuncAttributeMaxDynamicSharedMemorySize, ET_SMEM);
    cudaFuncSetAttribute((const void*)k_angle_tc,
                         cudaFuncAttributeMaxDynamicSharedMemorySize, AT_SMEM);

    k_zero<<<4096, 256>>>();
    k_count<<<NEDGE / 256, 256>>>(n2e);
    k_scan<<<1, 1024>>>();
    k_scatter<<<NEDGE / 256, 256>>>(n2e);
    k_sym<<<NLOC, 768>>>(edge_ebd, node_ext, h2, sw, n_ext2e);
    k_symmm<<<NLOC / 32, 256>>>(W_node_sym, b_node_sym, n_res1,
                                W_node_self, b_node_self, n_res0, node_ext, out_node);
    k_base<<<NLOC / 64, 256>>>(node_ext, W_node_edge, W_edge_self, b_node_edge, b_edge_self);
    k_base2<<<NALL / 64, 256>>>(node_ext, W_node_edge, W_edge_self);
    k_nbase<<<NLOC / 64, 256>>>(node_ext, W_edge_angle1, W_angle_self,
                                b_edge_angle1, b_angle_self);
    k_edge_tc<<<296, 512, ET_SMEM>>>(edge_ebd, sw, n_ext2e,
                                     W_node_edge, W_edge_self, e_res0, out_edge);
    k_node_finish<<<NLOC * NDIM / 256, 256>>>(n_res2, out_node);
    k_angle_tc<<<296, 512, AT_SMEM>>>(angle_ebd, edge_ebd, angle_index, a_sw,
                                      W_edge_angle1, W_angle_self, a_res0, out_angle);
    k_edge_msg<<<NEDGE / 64, 256>>>(W_edge_angle2, b_edge_angle2, e_res1, out_edge);
}